// round 7
// baseline (speedup 1.0000x reference)
#include <cuda_runtime.h>
#include <cuda_bf16.h>
#include <cstdint>

#define N_NODES 50000
#define N_EDGES 800000
#define F_IN 256
#define HID 64
#define NCLS 16
#define NB_SCAN 196   // ceil(50000/256)
#define MG 391        // ceil(50000/128)

// ---------------- scratch ----------------
__device__ int   g_cnt[N_NODES];
__device__ int   g_rowptr[N_NODES + 1];
__device__ int   g_cursor[N_NODES];
__device__ int   g_bsum[256];
__device__ int   g_boff[256];
__device__ int   g_es[N_EDGES];
__device__ float g_ep[N_EDGES];
__device__ float g_rdeg[N_NODES];

__device__ __align__(16) float g_h[(size_t)N_NODES * HID];     // fp32 ODE state
__device__ __align__(16) float g_acc[(size_t)N_NODES * HID];   // fp32 RK accumulator
__device__ __align__(16) __nv_bfloat16 g_hb[(size_t)N_NODES * HID];
__device__ __align__(16) __nv_bfloat16 g_midb[(size_t)N_NODES * HID];
__device__ __align__(16) __nv_bfloat16 g_curb[(size_t)N_NODES * HID];
__device__ __align__(16) __nv_bfloat16 g_c1[(size_t)N_NODES * 128]; // interleaved y0/y1, conv1
__device__ __align__(16) float g_xr1[(size_t)N_NODES * HID];
__device__ __align__(16) __nv_bfloat16 g_c2[(size_t)N_NODES * 32];  // interleaved y0/y1, conv2
__device__ __align__(16) float g_xr2[(size_t)N_NODES * NCLS];
// concatenated weights
__device__ __align__(16) float g_B1[256 * 192];    // cols [W1_0 | W1_1 | R1]
__device__ __align__(16) float g_Bh1[192 * 64];    // rows [Ra; Wa0; Wa1]
__device__ __align__(16) float g_Bh2[192 * 64];    // rows [Rb; Wb0; Wb1]
__device__ __align__(16) float g_B2[64 * 48];      // cols [W2_0 | W2_1 | R2]

// ---------------- tf32 mma helpers ----------------
__device__ __forceinline__ unsigned f2tf(float f) {
    unsigned r; asm("cvt.rna.tf32.f32 %0, %1;" : "=r"(r) : "f"(f)); return r;
}
__device__ __forceinline__ void mma_tf32(float* d, const unsigned* a, const unsigned* b) {
    asm volatile("mma.sync.aligned.m16n8k8.row.col.f32.tf32.tf32.f32 "
        "{%0,%1,%2,%3}, {%4,%5,%6,%7}, {%8,%9}, {%0,%1,%2,%3};"
        : "+f"(d[0]), "+f"(d[1]), "+f"(d[2]), "+f"(d[3])
        : "r"(a[0]), "r"(a[1]), "r"(a[2]), "r"(a[3]), "r"(b[0]), "r"(b[1]));
}

// ---------------- init: zero counts + concatenate weights (one kernel) ----------------
__global__ void k_init(const float* __restrict__ W1, const float* __restrict__ R1,
                       const float* __restrict__ Wa, const float* __restrict__ Ra,
                       const float* __restrict__ Wb, const float* __restrict__ Rb,
                       const float* __restrict__ W2, const float* __restrict__ R2) {
    int bx = blockIdx.x, t = threadIdx.x;
    if (bx < NB_SCAN) {
        int i = bx * 256 + t;
        if (i < N_NODES) g_cnt[i] = 0;
        return;
    }
    int i = (bx - NB_SCAN) * 256 + t;
    if (i < 256 * 192) {
        int k = i / 192, n = i % 192;
        float v;
        if (n < 64)       v = W1[k * 64 + n];
        else if (n < 128) v = W1[256 * 64 + k * 64 + (n - 64)];
        else              v = R1[k * 64 + (n - 128)];
        g_B1[i] = v;
    }
    if (i < 192 * 64) {
        int r = i / 64, c = i % 64;
        float va, vb;
        if (r < 64)       { va = Ra[r * 64 + c];                   vb = Rb[r * 64 + c]; }
        else if (r < 128) { va = Wa[(r - 64) * 64 + c];            vb = Wb[(r - 64) * 64 + c]; }
        else              { va = Wa[64 * 64 + (r - 128) * 64 + c]; vb = Wb[64 * 64 + (r - 128) * 64 + c]; }
        g_Bh1[i] = va;
        g_Bh2[i] = vb;
    }
    if (i < 64 * 48) {
        int k = i / 48, n = i % 48;
        float v;
        if (n < 16)      v = W2[k * 16 + n];
        else if (n < 32) v = W2[64 * 16 + k * 16 + (n - 16)];
        else             v = R2[k * 16 + (n - 32)];
        g_B2[i] = v;
    }
}

// ---------------- CSR build ----------------
__global__ void k_count(const int* __restrict__ dst) {
    int e = blockIdx.x * blockDim.x + threadIdx.x;
    if (e < N_EDGES) atomicAdd(&g_cnt[dst[e]], 1);
}
__global__ void k_bsum() {
    __shared__ int ss[256];
    int t = threadIdx.x;
    int idx = blockIdx.x * 256 + t;
    ss[t] = (idx < N_NODES) ? g_cnt[idx] : 0;
    __syncthreads();
    for (int off = 128; off > 0; off >>= 1) {
        if (t < off) ss[t] += ss[t + off];
        __syncthreads();
    }
    if (t == 0) g_bsum[blockIdx.x] = ss[0];
}
__global__ void k_bscan() {
    __shared__ int ss[256];
    int t = threadIdx.x;
    int v = (t < NB_SCAN) ? g_bsum[t] : 0;
    ss[t] = v;
    __syncthreads();
    for (int off = 1; off < 256; off <<= 1) {
        int u = (t >= off) ? ss[t - off] : 0;
        __syncthreads();
        ss[t] += u;
        __syncthreads();
    }
    g_boff[t] = ss[t] - v;
    if (t == 255) g_rowptr[N_NODES] = ss[255];
}
__global__ void k_bapply() {
    __shared__ int ss[256];
    int t = threadIdx.x;
    int idx = blockIdx.x * 256 + t;
    int v = (idx < N_NODES) ? g_cnt[idx] : 0;
    ss[t] = v;
    __syncthreads();
    for (int off = 1; off < 256; off <<= 1) {
        int u = (t >= off) ? ss[t - off] : 0;
        __syncthreads();
        ss[t] += u;
        __syncthreads();
    }
    if (idx < N_NODES) {
        int base = g_boff[blockIdx.x] + ss[t] - v;
        g_rowptr[idx] = base;
        g_cursor[idx] = base;
        g_rdeg[idx] = 1.0f / (float)(v > 0 ? v : 1);
    }
}

// ---------------- tf32 GEMM (conv1/conv2), EPI: 0=conv1(+fill slice), 3=conv2 ----------------
template <int K, int NTOT, int BN, int EPI>
__global__ void __launch_bounds__(256) k_mm(const float* __restrict__ A,
                                            const float* __restrict__ B,
                                            const float* __restrict__ bias,
                                            __nv_bfloat16* __restrict__ Cb,
                                            float* __restrict__ aux,
                                            const int* __restrict__ src,
                                            const int* __restrict__ dst,
                                            const float* __restrict__ ea) {
    __shared__ unsigned As[128][36];
    __shared__ unsigned Bs[32][BN + 8];

    if (EPI == 0 && blockIdx.y == 3) {   // fused CSR-fill slice
        int stride = gridDim.x * 256;
        for (int e = blockIdx.x * 256 + threadIdx.x; e < N_EDGES; e += stride) {
            int pos = atomicAdd(&g_cursor[dst[e]], 1);
            g_es[pos] = src[e];
            g_ep[pos] = ea[e];
        }
        return;
    }

    constexpr int BM = 128, BK = 32;
    constexpr int WN = BN / 2, NF = WN / 8;
    const int tid = threadIdx.x;
    const int lane = tid & 31, warp = tid >> 5;
    const int wm = warp & 3, wn = warp >> 2;
    const int mBase = blockIdx.x * BM;
    const int nBase = blockIdx.y * BN;
    const int g = lane >> 2, t = lane & 3;

    float acc[2][NF][4];
#pragma unroll
    for (int mf = 0; mf < 2; ++mf)
#pragma unroll
        for (int nf = 0; nf < NF; ++nf)
#pragma unroll
            for (int q = 0; q < 4; ++q) acc[mf][nf][q] = 0.f;

    const int ar = tid >> 3, ac = (tid & 7) * 4;

    for (int k0 = 0; k0 < K; k0 += BK) {
#pragma unroll
        for (int p = 0; p < 4; ++p) {
            int row = p * 32 + ar;
            int gm = mBase + row;
            float4 v = make_float4(0.f, 0.f, 0.f, 0.f);
            if (gm < N_NODES) v = *reinterpret_cast<const float4*>(A + (size_t)gm * K + k0 + ac);
            unsigned* s = &As[row][ac];
            s[0] = f2tf(v.x); s[1] = f2tf(v.y); s[2] = f2tf(v.z); s[3] = f2tf(v.w);
        }
        for (int i = tid; i < BK * BN / 4; i += 256) {
            int bk = i / (BN / 4), bc = (i % (BN / 4)) * 4;
            float4 v = *reinterpret_cast<const float4*>(B + (size_t)(k0 + bk) * NTOT + nBase + bc);
            unsigned* s = &Bs[bk][bc];
            s[0] = f2tf(v.x); s[1] = f2tf(v.y); s[2] = f2tf(v.z); s[3] = f2tf(v.w);
        }
        __syncthreads();
#pragma unroll
        for (int kk = 0; kk < BK / 8; ++kk) {
            const int kb = kk * 8;
            unsigned a[2][4];
#pragma unroll
            for (int mf = 0; mf < 2; ++mf) {
                int r = wm * 32 + mf * 16;
                a[mf][0] = As[r + g][kb + t];
                a[mf][1] = As[r + g + 8][kb + t];
                a[mf][2] = As[r + g][kb + t + 4];
                a[mf][3] = As[r + g + 8][kb + t + 4];
            }
#pragma unroll
            for (int nf = 0; nf < NF; ++nf) {
                int n = wn * WN + nf * 8;
                unsigned b[2] = { Bs[kb + t][n + g], Bs[kb + t + 4][n + g] };
                mma_tf32(acc[0][nf], a[0], b);
                mma_tf32(acc[1][nf], a[1], b);
            }
        }
        __syncthreads();
    }

    const int by = blockIdx.y;
    auto emit = [&](int row, int col, float a0, float a1) {
        if (row >= N_NODES) return;
        if (EPI == 0) {
            int c = col - (by << 6);
            if (by < 2) {
                Cb[(size_t)row * 128 + 2 * c + by]       = __float2bfloat16(a0);
                Cb[(size_t)row * 128 + 2 * (c + 1) + by] = __float2bfloat16(a1);
            } else {
                *reinterpret_cast<float2*>(aux + (size_t)row * 64 + c) =
                    make_float2(a0 + bias[c], a1 + bias[c + 1]);
            }
        } else {  // EPI == 3 (conv2)
            if (col < 32) {
                int sec = col >> 4, c = col & 15;
                Cb[(size_t)row * 32 + 2 * c + sec]       = __float2bfloat16(a0);
                Cb[(size_t)row * 32 + 2 * (c + 1) + sec] = __float2bfloat16(a1);
            } else {
                *reinterpret_cast<float2*>(aux + (size_t)row * 16 + (col - 32)) =
                    make_float2(a0 + bias[col - 32], a1 + bias[col - 31]);
            }
        }
    };

#pragma unroll
    for (int mf = 0; mf < 2; ++mf)
#pragma unroll
        for (int nf = 0; nf < NF; ++nf) {
            int row = mBase + wm * 32 + mf * 16 + g;
            int col = nBase + wn * WN + nf * 8 + 2 * t;
            emit(row, col, acc[mf][nf][0], acc[mf][nf][1]);
            emit(row + 8, col, acc[mf][nf][2], acc[mf][nf][3]);
        }
}

// ---------------- fused hidden conv: preagg (phase 1, smem) + GEMM (phase 2) ----------------
// A = [inb(bf16) | S0n | S1n], B = [R; W0; W1].  EPI: 1 = write midb, 2 = RK stage epilogue.
#define HID_SMEM (128 * 136 * 2 + 128 * 36 * 4 + 32 * 72 * 4)
template <int EPI>
__global__ void __launch_bounds__(256) k_hidden(const __nv_bfloat16* __restrict__ inb,
                                                const float* __restrict__ B,
                                                const float* __restrict__ bias,
                                                __nv_bfloat16* __restrict__ outb,
                                                int estage, float curMul) {
    extern __shared__ char smraw[];
    __nv_bfloat16* Sbuf = reinterpret_cast<__nv_bfloat16*>(smraw);        // [128][136]
    unsigned* As = reinterpret_cast<unsigned*>(smraw + 128 * 136 * 2);    // [128][36]
    unsigned* Bs = As + 128 * 36;                                          // [32][72]

    const int tid = threadIdx.x;
    const int lane = tid & 31, warp = tid >> 5;
    const int mBase = blockIdx.x * 128;

    // ---- phase 1: per-node gather aggregation into Sbuf (bf16) ----
    for (int j = 0; j < 16; ++j) {
        int r = warp * 16 + j;
        int node = mBase + r;
        if (node >= N_NODES) break;
        int i = g_rowptr[node], end = g_rowptr[node + 1];
        float sa0 = 0.f, sa1 = 0.f, sp0 = 0.f, sp1 = 0.f;
        for (; i + 3 < end; i += 4) {
            int s0 = g_es[i], s1 = g_es[i + 1], s2 = g_es[i + 2], s3 = g_es[i + 3];
            float p0 = g_ep[i], p1 = g_ep[i + 1], p2 = g_ep[i + 2], p3 = g_ep[i + 3];
            float2 x0 = __bfloat1622float2(*reinterpret_cast<const __nv_bfloat162*>(inb + (size_t)s0 * 64 + 2 * lane));
            float2 x1 = __bfloat1622float2(*reinterpret_cast<const __nv_bfloat162*>(inb + (size_t)s1 * 64 + 2 * lane));
            float2 x2 = __bfloat1622float2(*reinterpret_cast<const __nv_bfloat162*>(inb + (size_t)s2 * 64 + 2 * lane));
            float2 x3 = __bfloat1622float2(*reinterpret_cast<const __nv_bfloat162*>(inb + (size_t)s3 * 64 + 2 * lane));
            sa0 += (x0.x + x1.x) + (x2.x + x3.x);
            sa1 += (x0.y + x1.y) + (x2.y + x3.y);
            sp0 = fmaf(p0, x0.x, fmaf(p1, x1.x, fmaf(p2, x2.x, fmaf(p3, x3.x, sp0))));
            sp1 = fmaf(p0, x0.y, fmaf(p1, x1.y, fmaf(p2, x2.y, fmaf(p3, x3.y, sp1))));
        }
        for (; i < end; ++i) {
            int s = g_es[i];
            float p = g_ep[i];
            float2 xv = __bfloat1622float2(*reinterpret_cast<const __nv_bfloat162*>(inb + (size_t)s * 64 + 2 * lane));
            sa0 += xv.x; sa1 += xv.y;
            sp0 = fmaf(p, xv.x, sp0);
            sp1 = fmaf(p, xv.y, sp1);
        }
        float rd = g_rdeg[node];
        __nv_bfloat162* s0r = reinterpret_cast<__nv_bfloat162*>(Sbuf + r * 136);
        __nv_bfloat162* s1r = reinterpret_cast<__nv_bfloat162*>(Sbuf + r * 136 + 64);
        s0r[lane] = __float22bfloat162_rn(make_float2((sa0 - sp0) * rd, (sa1 - sp1) * rd));
        s1r[lane] = __float22bfloat162_rn(make_float2(sp0 * rd, sp1 * rd));
    }
    __syncthreads();

    // ---- phase 2: GEMM, K=192 ----
    const int wm = warp & 3, wn = warp >> 2;
    const int g = lane >> 2, t = lane & 3;
    float acc[2][4][4];
#pragma unroll
    for (int mf = 0; mf < 2; ++mf)
#pragma unroll
        for (int nf = 0; nf < 4; ++nf)
#pragma unroll
            for (int q = 0; q < 4; ++q) acc[mf][nf][q] = 0.f;

    const int ar = tid >> 3, ac = (tid & 7) * 4;

    for (int k0 = 0; k0 < 192; k0 += 32) {
#pragma unroll
        for (int p = 0; p < 4; ++p) {
            int row = p * 32 + ar;
            unsigned* s = &As[row * 36 + ac];
            if (k0 < 64) {
                int gm = mBase + row;
                float2 f01 = make_float2(0.f, 0.f), f23 = make_float2(0.f, 0.f);
                if (gm < N_NODES) {
                    uint2 u = *reinterpret_cast<const uint2*>(inb + (size_t)gm * 64 + k0 + ac);
                    f01 = __bfloat1622float2(*reinterpret_cast<__nv_bfloat162*>(&u.x));
                    f23 = __bfloat1622float2(*reinterpret_cast<__nv_bfloat162*>(&u.y));
                }
                s[0] = f2tf(f01.x); s[1] = f2tf(f01.y); s[2] = f2tf(f23.x); s[3] = f2tf(f23.y);
            } else {
                uint2 u = *reinterpret_cast<const uint2*>(Sbuf + row * 136 + (k0 - 64) + ac);
                float2 f01 = __bfloat1622float2(*reinterpret_cast<__nv_bfloat162*>(&u.x));
                float2 f23 = __bfloat1622float2(*reinterpret_cast<__nv_bfloat162*>(&u.y));
                s[0] = f2tf(f01.x); s[1] = f2tf(f01.y); s[2] = f2tf(f23.x); s[3] = f2tf(f23.y);
            }
        }
        {   // B tile: full 32 rows (2 rows per thread) — FIXED from round 6
            int bk = tid >> 4, bc = (tid & 15) * 4;
#pragma unroll
            for (int half = 0; half < 2; ++half) {
                int bkk = bk + half * 16;
                float4 v = *reinterpret_cast<const float4*>(B + (size_t)(k0 + bkk) * 64 + bc);
                unsigned* s = &Bs[bkk * 72 + bc];
                s[0] = f2tf(v.x); s[1] = f2tf(v.y); s[2] = f2tf(v.z); s[3] = f2tf(v.w);
            }
        }
        __syncthreads();
#pragma unroll
        for (int kk = 0; kk < 4; ++kk) {
            const int kb = kk * 8;
            unsigned a[2][4];
#pragma unroll
            for (int mf = 0; mf < 2; ++mf) {
                int r = wm * 32 + mf * 16;
                a[mf][0] = As[(r + g) * 36 + kb + t];
                a[mf][1] = As[(r + g + 8) * 36 + kb + t];
                a[mf][2] = As[(r + g) * 36 + kb + t + 4];
                a[mf][3] = As[(r + g + 8) * 36 + kb + t + 4];
            }
#pragma unroll
            for (int nf = 0; nf < 4; ++nf) {
                int n = wn * 32 + nf * 8;
                unsigned b[2] = { Bs[(kb + t) * 72 + n + g], Bs[(kb + t + 4) * 72 + n + g] };
                mma_tf32(acc[0][nf], a[0], b);
                mma_tf32(acc[1][nf], a[1], b);
            }
        }
        __syncthreads();
    }

    auto emit = [&](int row, int col, float a0, float a1) {
        if (row >= N_NODES) return;
        float2 kv = make_float2(a0 + bias[col], a1 + bias[col + 1]);
        size_t idx = (size_t)row * 64 + col;
        if (EPI == 1) {
            *reinterpret_cast<__nv_bfloat162*>(outb + idx) = __float22bfloat162_rn(kv);
        } else {
            float2 h2 = *reinterpret_cast<const float2*>(g_h + idx);
            if (estage == 4) {
                float2 a2 = *reinterpret_cast<const float2*>(g_acc + idx);
                *reinterpret_cast<float2*>(g_h + idx) =
                    make_float2(h2.x + 0.5f * (a2.x + kv.x), h2.y + 0.5f * (a2.y + kv.y));
            } else {
                float2 a2;
                if (estage == 1) a2 = kv;
                else {
                    a2 = *reinterpret_cast<const float2*>(g_acc + idx);
                    a2.x = fmaf(2.f, kv.x, a2.x); a2.y = fmaf(2.f, kv.y, a2.y);
                }
                *reinterpret_cast<float2*>(g_acc + idx) = a2;
                float2 c2 = make_float2(fmaf(curMul, kv.x, h2.x), fmaf(curMul, kv.y, h2.y));
                *reinterpret_cast<__nv_bfloat162*>(outb + idx) = __float22bfloat162_rn(c2);
            }
        }
    };

#pragma unroll
    for (int mf = 0; mf < 2; ++mf)
#pragma unroll
        for (int nf = 0; nf < 4; ++nf) {
            int row = mBase + wm * 32 + mf * 16 + g;
            int col = wn * 32 + nf * 8 + 2 * t;
            emit(row, col, acc[mf][nf][0], acc[mf][nf][1]);
            emit(row + 8, col, acc[mf][nf][2], acc[mf][nf][3]);
        }
}

// ---------------- conv1 aggregation: warp/node, bf16 interleaved gather, tanh ----------------
__global__ void __launch_bounds__(256) k_agg1() {
    int w = (blockIdx.x * 256 + threadIdx.x) >> 5;
    int lane = threadIdx.x & 31;
    if (w >= N_NODES) return;
    int i = g_rowptr[w], end = g_rowptr[w + 1];
    float a0 = 0.f, a1 = 0.f;
    for (; i + 1 < end; i += 2) {
        int sA = g_es[i], sB = g_es[i + 1];
        float pA = g_ep[i], pB = g_ep[i + 1];
        uint2 uA = *reinterpret_cast<const uint2*>(g_c1 + (size_t)sA * 128 + 4 * lane);
        uint2 uB = *reinterpret_cast<const uint2*>(g_c1 + (size_t)sB * 128 + 4 * lane);
        float2 vA0 = __bfloat1622float2(*reinterpret_cast<__nv_bfloat162*>(&uA.x));
        float2 vA1 = __bfloat1622float2(*reinterpret_cast<__nv_bfloat162*>(&uA.y));
        float2 vB0 = __bfloat1622float2(*reinterpret_cast<__nv_bfloat162*>(&uB.x));
        float2 vB1 = __bfloat1622float2(*reinterpret_cast<__nv_bfloat162*>(&uB.y));
        a0 += fmaf(pA, vA0.y - vA0.x, vA0.x) + fmaf(pB, vB0.y - vB0.x, vB0.x);
        a1 += fmaf(pA, vA1.y - vA1.x, vA1.x) + fmaf(pB, vB1.y - vB1.x, vB1.x);
    }
    if (i < end) {
        int s = g_es[i];
        float p = g_ep[i];
        uint2 u = *reinterpret_cast<const uint2*>(g_c1 + (size_t)s * 128 + 4 * lane);
        float2 v0 = __bfloat1622float2(*reinterpret_cast<__nv_bfloat162*>(&u.x));
        float2 v1 = __bfloat1622float2(*reinterpret_cast<__nv_bfloat162*>(&u.y));
        a0 += fmaf(p, v0.y - v0.x, v0.x);
        a1 += fmaf(p, v1.y - v1.x, v1.x);
    }
    float rd = g_rdeg[w];
    float2 xr = *reinterpret_cast<const float2*>(g_xr1 + (size_t)w * 64 + 2 * lane);
    float2 hv = make_float2(tanhf(fmaf(a0, rd, xr.x)), tanhf(fmaf(a1, rd, xr.y)));
    *reinterpret_cast<float2*>(g_h + (size_t)w * 64 + 2 * lane) = hv;
    *reinterpret_cast<__nv_bfloat162*>(g_hb + (size_t)w * 64 + 2 * lane) = __float22bfloat162_rn(hv);
}

// ---------------- conv2 aggregation + log_softmax (half-warp/node) ----------------
__global__ void __launch_bounds__(256) k_agg2_lsm(float* __restrict__ out) {
    int hw = (blockIdx.x * 256 + threadIdx.x) >> 4;
    int c = threadIdx.x & 15;
    if (hw >= N_NODES) return;
    int i = g_rowptr[hw], end = g_rowptr[hw + 1];
    float acc = 0.f;
    for (; i + 1 < end; i += 2) {
        int sA = g_es[i], sB = g_es[i + 1];
        float pA = g_ep[i], pB = g_ep[i + 1];
        float2 vA = __bfloat1622float2(*reinterpret_cast<const __nv_bfloat162*>(g_c2 + (size_t)sA * 32 + 2 * c));
        float2 vB = __bfloat1622float2(*reinterpret_cast<const __nv_bfloat162*>(g_c2 + (size_t)sB * 32 + 2 * c));
        acc += fmaf(pA, vA.y - vA.x, vA.x) + fmaf(pB, vB.y - vB.x, vB.x);
    }
    if (i < end) {
        int s = g_es[i];
        float p = g_ep[i];
        float2 v = __bfloat1622float2(*reinterpret_cast<const __nv_bfloat162*>(g_c2 + (size_t)s * 32 + 2 * c));
        acc += fmaf(p, v.y - v.x, v.x);
    }
    float v = tanhf(fmaf(acc, g_rdeg[hw], g_xr2[(size_t)hw * 16 + c]));
    float m = v;
    for (int o = 8; o > 0; o >>= 1) m = fmaxf(m, __shfl_xor_sync(0xffffffffu, m, o, 16));
    float e = expf(v - m);
    float s = e;
    for (int o = 8; o > 0; o >>= 1) s += __shfl_xor_sync(0xffffffffu, s, o, 16);
    out[(size_t)hw * 16 + c] = v - m - logf(s);
}

// ---------------- launch ----------------
extern "C" void kernel_launch(void* const* d_in, const int* in_sizes, int n_in,
                              void* d_out, int out_size) {
    const float* x  = (const float*)d_in[0];
    const float* ea = (const float*)d_in[1];
    const int*   src = (const int*)d_in[2];
    const int*   dst = (const int*)d_in[3];
    const float* W1 = (const float*)d_in[4];
    const float* R1 = (const float*)d_in[5];
    const float* b1 = (const float*)d_in[6];
    const float* Wa = (const float*)d_in[7];
    const float* Ra = (const float*)d_in[8];
    const float* ba = (const float*)d_in[9];
    const float* Wb = (const float*)d_in[10];
    const float* Rb = (const float*)d_in[11];
    const float* bb = (const float*)d_in[12];
    const float* W2 = (const float*)d_in[13];
    const float* R2 = (const float*)d_in[14];
    const float* b2 = (const float*)d_in[15];
    float* out = (float*)d_out;

    float *h, *B1, *Bh1, *Bh2, *B2, *xr1, *xr2;
    __nv_bfloat16 *hb, *midb, *curb, *c1, *c2;
    cudaGetSymbolAddress((void**)&h, g_h);
    cudaGetSymbolAddress((void**)&hb, g_hb);
    cudaGetSymbolAddress((void**)&midb, g_midb);
    cudaGetSymbolAddress((void**)&curb, g_curb);
    cudaGetSymbolAddress((void**)&B1, g_B1);
    cudaGetSymbolAddress((void**)&Bh1, g_Bh1);
    cudaGetSymbolAddress((void**)&Bh2, g_Bh2);
    cudaGetSymbolAddress((void**)&B2, g_B2);
    cudaGetSymbolAddress((void**)&c1, g_c1);
    cudaGetSymbolAddress((void**)&c2, g_c2);
    cudaGetSymbolAddress((void**)&xr1, g_xr1);
    cudaGetSymbolAddress((void**)&xr2, g_xr2);

    static bool attr_done = false;
    if (!attr_done) {
        cudaFuncSetAttribute(k_hidden<1>, cudaFuncAttributeMaxDynamicSharedMemorySize, HID_SMEM);
        cudaFuncSetAttribute(k_hidden<2>, cudaFuncAttributeMaxDynamicSharedMemorySize, HID_SMEM);
        attr_done = true;
    }

    // CSR build + weight cat
    k_init<<<NB_SCAN + 192, 256>>>(W1, R1, Wa, Ra, Wb, Rb, W2, R2);
    k_count<<<N_EDGES / 256, 256>>>(dst);
    k_bsum<<<NB_SCAN, 256>>>();
    k_bscan<<<1, 256>>>();
    k_bapply<<<NB_SCAN, 256>>>();

    const int WG = (N_NODES * 32 + 255) / 256;
    const int HG = (N_NODES * 16 + 255) / 256;

    // conv1 GEMM (+ CSR fill hidden in the 4th y-slice)
    k_mm<256, 192, 64, 0><<<dim3(MG, 4), 256>>>(x, B1, b1, c1, xr1, src, dst, ea);
    k_agg1<<<WG, 256>>>();

    // RK4: each stage = two fused (preagg+GEMM) kernels
    auto fstep = [&](const __nv_bfloat16* inb, int stage, float curMul) {
        k_hidden<1><<<MG, 256, HID_SMEM>>>(inb, Bh1, ba, midb, 0, 0.f);
        k_hidden<2><<<MG, 256, HID_SMEM>>>(midb, Bh2, bb, curb, stage, curMul);
    };
    fstep(hb, 1, 1.5f);
    fstep(curb, 2, 1.5f);
    fstep(curb, 3, 3.0f);
    fstep(curb, 4, 0.f);

    // conv2 + log_softmax
    k_mm<64, 48, 48, 3><<<dim3(MG, 1), 256>>>(h, B2, b2, c2, xr2, nullptr, nullptr, nullptr);
    k_agg2_lsm<<<HG, 256>>>(out);
}

// round 8
// speedup vs baseline: 1.2573x; 1.2573x over previous
#include <cuda_runtime.h>
#include <cuda_bf16.h>
#include <cstdint>

#define N_NODES 50000
#define N_EDGES 800000
#define F_IN 256
#define HID 64
#define NCLS 16
#define NB_SCAN 196   // ceil(50000/256)
#define MG 391        // ceil(50000/128)

// ---------------- scratch ----------------
__device__ int   g_cnt[N_NODES];
__device__ int   g_rowptr[N_NODES + 1];
__device__ int   g_cursor[N_NODES];
__device__ int   g_bsum[256];
__device__ int   g_boff[256];
__device__ int   g_es[N_EDGES];
__device__ float g_ep[N_EDGES];
__device__ float g_rdeg[N_NODES];

__device__ __align__(16) float g_h[(size_t)N_NODES * HID];     // fp32 ODE state
__device__ __align__(16) float g_acc[(size_t)N_NODES * HID];   // fp32 RK accumulator
__device__ __align__(16) __nv_bfloat16 g_hb[(size_t)N_NODES * HID];
__device__ __align__(16) __nv_bfloat16 g_midb[(size_t)N_NODES * HID];
__device__ __align__(16) __nv_bfloat16 g_curb[(size_t)N_NODES * HID];
__device__ __align__(16) __nv_bfloat16 g_Ypreb[(size_t)N_NODES * 128]; // [S0n|S1n] bf16
__device__ __align__(16) __nv_bfloat16 g_c1[(size_t)N_NODES * 128]; // interleaved y0/y1, conv1
__device__ __align__(16) float g_xr1[(size_t)N_NODES * HID];
__device__ __align__(16) __nv_bfloat16 g_c2[(size_t)N_NODES * 32];  // interleaved y0/y1, conv2
__device__ __align__(16) float g_xr2[(size_t)N_NODES * NCLS];
// concatenated weights
__device__ __align__(16) float g_B1[256 * 192];    // cols [W1_0 | W1_1 | R1]
__device__ __align__(16) float g_Bh1[192 * 64];    // rows [Ra; Wa0; Wa1]
__device__ __align__(16) float g_Bh2[192 * 64];    // rows [Rb; Wb0; Wb1]
__device__ __align__(16) float g_B2[64 * 48];      // cols [W2_0 | W2_1 | R2]

// ---------------- tf32 mma helpers ----------------
__device__ __forceinline__ unsigned f2tf(float f) {
    unsigned r; asm("cvt.rna.tf32.f32 %0, %1;" : "=r"(r) : "f"(f)); return r;
}
__device__ __forceinline__ void mma_tf32(float* d, const unsigned* a, const unsigned* b) {
    asm volatile("mma.sync.aligned.m16n8k8.row.col.f32.tf32.tf32.f32 "
        "{%0,%1,%2,%3}, {%4,%5,%6,%7}, {%8,%9}, {%0,%1,%2,%3};"
        : "+f"(d[0]), "+f"(d[1]), "+f"(d[2]), "+f"(d[3])
        : "r"(a[0]), "r"(a[1]), "r"(a[2]), "r"(a[3]), "r"(b[0]), "r"(b[1]));
}

// ---------------- init: zero counts + concatenate weights ----------------
__global__ void k_init(const float* __restrict__ W1, const float* __restrict__ R1,
                       const float* __restrict__ Wa, const float* __restrict__ Ra,
                       const float* __restrict__ Wb, const float* __restrict__ Rb,
                       const float* __restrict__ W2, const float* __restrict__ R2) {
    int bx = blockIdx.x, t = threadIdx.x;
    if (bx < NB_SCAN) {
        int i = bx * 256 + t;
        if (i < N_NODES) g_cnt[i] = 0;
        return;
    }
    int i = (bx - NB_SCAN) * 256 + t;
    if (i < 256 * 192) {
        int k = i / 192, n = i % 192;
        float v;
        if (n < 64)       v = W1[k * 64 + n];
        else if (n < 128) v = W1[256 * 64 + k * 64 + (n - 64)];
        else              v = R1[k * 64 + (n - 128)];
        g_B1[i] = v;
    }
    if (i < 192 * 64) {
        int r = i / 64, c = i % 64;
        float va, vb;
        if (r < 64)       { va = Ra[r * 64 + c];                   vb = Rb[r * 64 + c]; }
        else if (r < 128) { va = Wa[(r - 64) * 64 + c];            vb = Wb[(r - 64) * 64 + c]; }
        else              { va = Wa[64 * 64 + (r - 128) * 64 + c]; vb = Wb[64 * 64 + (r - 128) * 64 + c]; }
        g_Bh1[i] = va;
        g_Bh2[i] = vb;
    }
    if (i < 64 * 48) {
        int k = i / 48, n = i % 48;
        float v;
        if (n < 16)      v = W2[k * 16 + n];
        else if (n < 32) v = W2[64 * 16 + k * 16 + (n - 16)];
        else             v = R2[k * 16 + (n - 32)];
        g_B2[i] = v;
    }
}

// ---------------- CSR build ----------------
__global__ void k_count(const int* __restrict__ dst) {
    int e = blockIdx.x * blockDim.x + threadIdx.x;
    if (e < N_EDGES) atomicAdd(&g_cnt[dst[e]], 1);
}
__global__ void k_bsum() {
    __shared__ int ss[256];
    int t = threadIdx.x;
    int idx = blockIdx.x * 256 + t;
    ss[t] = (idx < N_NODES) ? g_cnt[idx] : 0;
    __syncthreads();
    for (int off = 128; off > 0; off >>= 1) {
        if (t < off) ss[t] += ss[t + off];
        __syncthreads();
    }
    if (t == 0) g_bsum[blockIdx.x] = ss[0];
}
__global__ void k_bscan() {
    __shared__ int ss[256];
    int t = threadIdx.x;
    int v = (t < NB_SCAN) ? g_bsum[t] : 0;
    ss[t] = v;
    __syncthreads();
    for (int off = 1; off < 256; off <<= 1) {
        int u = (t >= off) ? ss[t - off] : 0;
        __syncthreads();
        ss[t] += u;
        __syncthreads();
    }
    g_boff[t] = ss[t] - v;
    if (t == 255) g_rowptr[N_NODES] = ss[255];
}
__global__ void k_bapply() {
    __shared__ int ss[256];
    int t = threadIdx.x;
    int idx = blockIdx.x * 256 + t;
    int v = (idx < N_NODES) ? g_cnt[idx] : 0;
    ss[t] = v;
    __syncthreads();
    for (int off = 1; off < 256; off <<= 1) {
        int u = (t >= off) ? ss[t - off] : 0;
        __syncthreads();
        ss[t] += u;
        __syncthreads();
    }
    if (idx < N_NODES) {
        int base = g_boff[blockIdx.x] + ss[t] - v;
        g_rowptr[idx] = base;
        g_cursor[idx] = base;
        g_rdeg[idx] = 1.0f / (float)(v > 0 ? v : 1);
    }
}

// ---------------- tf32 GEMM (conv1/conv2), EPI: 0=conv1(+fill slice), 3=conv2 ----------------
template <int K, int NTOT, int BN, int EPI>
__global__ void __launch_bounds__(256) k_mm(const float* __restrict__ A,
                                            const float* __restrict__ B,
                                            const float* __restrict__ bias,
                                            __nv_bfloat16* __restrict__ Cb,
                                            float* __restrict__ aux,
                                            const int* __restrict__ src,
                                            const int* __restrict__ dst,
                                            const float* __restrict__ ea) {
    __shared__ unsigned As[128][36];
    __shared__ unsigned Bs[32][BN + 8];

    if (EPI == 0 && blockIdx.y == 3) {   // fused CSR-fill slice
        int stride = gridDim.x * 256;
        for (int e = blockIdx.x * 256 + threadIdx.x; e < N_EDGES; e += stride) {
            int pos = atomicAdd(&g_cursor[dst[e]], 1);
            g_es[pos] = src[e];
            g_ep[pos] = ea[e];
        }
        return;
    }

    constexpr int BM = 128, BK = 32;
    constexpr int WN = BN / 2, NF = WN / 8;
    const int tid = threadIdx.x;
    const int lane = tid & 31, warp = tid >> 5;
    const int wm = warp & 3, wn = warp >> 2;
    const int mBase = blockIdx.x * BM;
    const int nBase = blockIdx.y * BN;
    const int g = lane >> 2, t = lane & 3;

    float acc[2][NF][4];
#pragma unroll
    for (int mf = 0; mf < 2; ++mf)
#pragma unroll
        for (int nf = 0; nf < NF; ++nf)
#pragma unroll
            for (int q = 0; q < 4; ++q) acc[mf][nf][q] = 0.f;

    const int ar = tid >> 3, ac = (tid & 7) * 4;

    for (int k0 = 0; k0 < K; k0 += BK) {
#pragma unroll
        for (int p = 0; p < 4; ++p) {
            int row = p * 32 + ar;
            int gm = mBase + row;
            float4 v = make_float4(0.f, 0.f, 0.f, 0.f);
            if (gm < N_NODES) v = *reinterpret_cast<const float4*>(A + (size_t)gm * K + k0 + ac);
            unsigned* s = &As[row][ac];
            s[0] = f2tf(v.x); s[1] = f2tf(v.y); s[2] = f2tf(v.z); s[3] = f2tf(v.w);
        }
        for (int i = tid; i < BK * BN / 4; i += 256) {
            int bk = i / (BN / 4), bc = (i % (BN / 4)) * 4;
            float4 v = *reinterpret_cast<const float4*>(B + (size_t)(k0 + bk) * NTOT + nBase + bc);
            unsigned* s = &Bs[bk][bc];
            s[0] = f2tf(v.x); s[1] = f2tf(v.y); s[2] = f2tf(v.z); s[3] = f2tf(v.w);
        }
        __syncthreads();
#pragma unroll
        for (int kk = 0; kk < BK / 8; ++kk) {
            const int kb = kk * 8;
            unsigned a[2][4];
#pragma unroll
            for (int mf = 0; mf < 2; ++mf) {
                int r = wm * 32 + mf * 16;
                a[mf][0] = As[r + g][kb + t];
                a[mf][1] = As[r + g + 8][kb + t];
                a[mf][2] = As[r + g][kb + t + 4];
                a[mf][3] = As[r + g + 8][kb + t + 4];
            }
#pragma unroll
            for (int nf = 0; nf < NF; ++nf) {
                int n = wn * WN + nf * 8;
                unsigned b[2] = { Bs[kb + t][n + g], Bs[kb + t + 4][n + g] };
                mma_tf32(acc[0][nf], a[0], b);
                mma_tf32(acc[1][nf], a[1], b);
            }
        }
        __syncthreads();
    }

    const int by = blockIdx.y;
    auto emit = [&](int row, int col, float a0, float a1) {
        if (row >= N_NODES) return;
        if (EPI == 0) {
            int c = col - (by << 6);
            if (by < 2) {
                Cb[(size_t)row * 128 + 2 * c + by]       = __float2bfloat16(a0);
                Cb[(size_t)row * 128 + 2 * (c + 1) + by] = __float2bfloat16(a1);
            } else {
                *reinterpret_cast<float2*>(aux + (size_t)row * 64 + c) =
                    make_float2(a0 + bias[c], a1 + bias[c + 1]);
            }
        } else {  // EPI == 3 (conv2)
            if (col < 32) {
                int sec = col >> 4, c = col & 15;
                Cb[(size_t)row * 32 + 2 * c + sec]       = __float2bfloat16(a0);
                Cb[(size_t)row * 32 + 2 * (c + 1) + sec] = __float2bfloat16(a1);
            } else {
                *reinterpret_cast<float2*>(aux + (size_t)row * 16 + (col - 32)) =
                    make_float2(a0 + bias[col - 32], a1 + bias[col - 31]);
            }
        }
    };

#pragma unroll
    for (int mf = 0; mf < 2; ++mf)
#pragma unroll
        for (int nf = 0; nf < NF; ++nf) {
            int row = mBase + wm * 32 + mf * 16 + g;
            int col = nBase + wn * WN + nf * 8 + 2 * t;
            emit(row, col, acc[mf][nf][0], acc[mf][nf][1]);
            emit(row + 8, col, acc[mf][nf][2], acc[mf][nf][3]);
        }
}

// ---------------- hidden pre-aggregation: warp/node, bf16 gather -> bf16 [S0n|S1n] ----------------
__global__ void __launch_bounds__(256) k_preagg(const __nv_bfloat16* __restrict__ inb) {
    int w = (blockIdx.x * 256 + threadIdx.x) >> 5;
    int lane = threadIdx.x & 31;
    if (w >= N_NODES) return;
    int i = g_rowptr[w], end = g_rowptr[w + 1];
    float sa0 = 0.f, sa1 = 0.f, sp0 = 0.f, sp1 = 0.f;
    for (; i + 1 < end; i += 2) {
        int sA = g_es[i], sB = g_es[i + 1];
        float pA = g_ep[i], pB = g_ep[i + 1];
        float2 xA = __bfloat1622float2(*reinterpret_cast<const __nv_bfloat162*>(inb + (size_t)sA * 64 + 2 * lane));
        float2 xB = __bfloat1622float2(*reinterpret_cast<const __nv_bfloat162*>(inb + (size_t)sB * 64 + 2 * lane));
        sa0 += xA.x + xB.x;
        sa1 += xA.y + xB.y;
        sp0 = fmaf(pA, xA.x, fmaf(pB, xB.x, sp0));
        sp1 = fmaf(pA, xA.y, fmaf(pB, xB.y, sp1));
    }
    if (i < end) {
        int s = g_es[i];
        float p = g_ep[i];
        float2 xv = __bfloat1622float2(*reinterpret_cast<const __nv_bfloat162*>(inb + (size_t)s * 64 + 2 * lane));
        sa0 += xv.x; sa1 += xv.y;
        sp0 = fmaf(p, xv.x, sp0);
        sp1 = fmaf(p, xv.y, sp1);
    }
    float rd = g_rdeg[w];
    __nv_bfloat16* yr = g_Ypreb + (size_t)w * 128;
    *reinterpret_cast<__nv_bfloat162*>(yr + 2 * lane) =
        __float22bfloat162_rn(make_float2((sa0 - sp0) * rd, (sa1 - sp1) * rd));
    *reinterpret_cast<__nv_bfloat162*>(yr + 64 + 2 * lane) =
        __float22bfloat162_rn(make_float2(sp0 * rd, sp1 * rd));
}

// ---------------- hidden GEMM: A=[inb | Ypreb] (all bf16), B=[R;W0;W1], K=192 ----------------
// EPI: 1 = write midb (bf16), 2 = RK stage epilogue
template <int EPI>
__global__ void __launch_bounds__(256) k_hmm(const __nv_bfloat16* __restrict__ inb,
                                             const float* __restrict__ B,
                                             const float* __restrict__ bias,
                                             __nv_bfloat16* __restrict__ outb,
                                             int estage, float curMul) {
    __shared__ unsigned As[128][36];
    __shared__ unsigned Bs[32][72];

    const int tid = threadIdx.x;
    const int lane = tid & 31, warp = tid >> 5;
    const int wm = warp & 3, wn = warp >> 2;
    const int mBase = blockIdx.x * 128;
    const int g = lane >> 2, t = lane & 3;

    float acc[2][4][4];
#pragma unroll
    for (int mf = 0; mf < 2; ++mf)
#pragma unroll
        for (int nf = 0; nf < 4; ++nf)
#pragma unroll
            for (int q = 0; q < 4; ++q) acc[mf][nf][q] = 0.f;

    const int ar = tid >> 3, ac = (tid & 7) * 4;

    for (int k0 = 0; k0 < 192; k0 += 32) {
#pragma unroll
        for (int p = 0; p < 4; ++p) {
            int row = p * 32 + ar;
            int gm = mBase + row;
            unsigned* s = &As[row][ac];
            float2 f01 = make_float2(0.f, 0.f), f23 = make_float2(0.f, 0.f);
            if (gm < N_NODES) {
                uint2 u;
                if (k0 < 64) u = *reinterpret_cast<const uint2*>(inb + (size_t)gm * 64 + k0 + ac);
                else         u = *reinterpret_cast<const uint2*>(g_Ypreb + (size_t)gm * 128 + (k0 - 64) + ac);
                f01 = __bfloat1622float2(*reinterpret_cast<__nv_bfloat162*>(&u.x));
                f23 = __bfloat1622float2(*reinterpret_cast<__nv_bfloat162*>(&u.y));
            }
            s[0] = f2tf(f01.x); s[1] = f2tf(f01.y); s[2] = f2tf(f23.x); s[3] = f2tf(f23.y);
        }
        {   // B tile: full 32 rows, 2 rows per thread
            int bk = tid >> 4, bc = (tid & 15) * 4;
#pragma unroll
            for (int half = 0; half < 2; ++half) {
                int bkk = bk + half * 16;
                float4 v = *reinterpret_cast<const float4*>(B + (size_t)(k0 + bkk) * 64 + bc);
                unsigned* s = &Bs[bkk][bc];
                s[0] = f2tf(v.x); s[1] = f2tf(v.y); s[2] = f2tf(v.z); s[3] = f2tf(v.w);
            }
        }
        __syncthreads();
#pragma unroll
        for (int kk = 0; kk < 4; ++kk) {
            const int kb = kk * 8;
            unsigned a[2][4];
#pragma unroll
            for (int mf = 0; mf < 2; ++mf) {
                int r = wm * 32 + mf * 16;
                a[mf][0] = As[r + g][kb + t];
                a[mf][1] = As[r + g + 8][kb + t];
                a[mf][2] = As[r + g][kb + t + 4];
                a[mf][3] = As[r + g + 8][kb + t + 4];
            }
#pragma unroll
            for (int nf = 0; nf < 4; ++nf) {
                int n = wn * 32 + nf * 8;
                unsigned b[2] = { Bs[kb + t][n + g], Bs[kb + t + 4][n + g] };
                mma_tf32(acc[0][nf], a[0], b);
                mma_tf32(acc[1][nf], a[1], b);
            }
        }
        __syncthreads();
    }

    auto emit = [&](int row, int col, float a0, float a1) {
        if (row >= N_NODES) return;
        float2 kv = make_float2(a0 + bias[col], a1 + bias[col + 1]);
        size_t idx = (size_t)row * 64 + col;
        if (EPI == 1) {
            *reinterpret_cast<__nv_bfloat162*>(outb + idx) = __float22bfloat162_rn(kv);
        } else {
            float2 h2 = *reinterpret_cast<const float2*>(g_h + idx);
            if (estage == 4) {
                float2 a2 = *reinterpret_cast<const float2*>(g_acc + idx);
                *reinterpret_cast<float2*>(g_h + idx) =
                    make_float2(h2.x + 0.5f * (a2.x + kv.x), h2.y + 0.5f * (a2.y + kv.y));
            } else {
                float2 a2;
                if (estage == 1) a2 = kv;
                else {
                    a2 = *reinterpret_cast<const float2*>(g_acc + idx);
                    a2.x = fmaf(2.f, kv.x, a2.x); a2.y = fmaf(2.f, kv.y, a2.y);
                }
                *reinterpret_cast<float2*>(g_acc + idx) = a2;
                float2 c2 = make_float2(fmaf(curMul, kv.x, h2.x), fmaf(curMul, kv.y, h2.y));
                *reinterpret_cast<__nv_bfloat162*>(outb + idx) = __float22bfloat162_rn(c2);
            }
        }
    };

#pragma unroll
    for (int mf = 0; mf < 2; ++mf)
#pragma unroll
        for (int nf = 0; nf < 4; ++nf) {
            int row = mBase + wm * 32 + mf * 16 + g;
            int col = wn * 32 + nf * 8 + 2 * t;
            emit(row, col, acc[mf][nf][0], acc[mf][nf][1]);
            emit(row + 8, col, acc[mf][nf][2], acc[mf][nf][3]);
        }
}

// ---------------- conv1 aggregation: warp/node, bf16 interleaved gather, tanh ----------------
__global__ void __launch_bounds__(256) k_agg1() {
    int w = (blockIdx.x * 256 + threadIdx.x) >> 5;
    int lane = threadIdx.x & 31;
    if (w >= N_NODES) return;
    int i = g_rowptr[w], end = g_rowptr[w + 1];
    float a0 = 0.f, a1 = 0.f;
    for (; i + 1 < end; i += 2) {
        int sA = g_es[i], sB = g_es[i + 1];
        float pA = g_ep[i], pB = g_ep[i + 1];
        uint2 uA = *reinterpret_cast<const uint2*>(g_c1 + (size_t)sA * 128 + 4 * lane);
        uint2 uB = *reinterpret_cast<const uint2*>(g_c1 + (size_t)sB * 128 + 4 * lane);
        float2 vA0 = __bfloat1622float2(*reinterpret_cast<__nv_bfloat162*>(&uA.x));
        float2 vA1 = __bfloat1622float2(*reinterpret_cast<__nv_bfloat162*>(&uA.y));
        float2 vB0 = __bfloat1622float2(*reinterpret_cast<__nv_bfloat162*>(&uB.x));
        float2 vB1 = __bfloat1622float2(*reinterpret_cast<__nv_bfloat162*>(&uB.y));
        a0 += fmaf(pA, vA0.y - vA0.x, vA0.x) + fmaf(pB, vB0.y - vB0.x, vB0.x);
        a1 += fmaf(pA, vA1.y - vA1.x, vA1.x) + fmaf(pB, vB1.y - vB1.x, vB1.x);
    }
    if (i < end) {
        int s = g_es[i];
        float p = g_ep[i];
        uint2 u = *reinterpret_cast<const uint2*>(g_c1 + (size_t)s * 128 + 4 * lane);
        float2 v0 = __bfloat1622float2(*reinterpret_cast<__nv_bfloat162*>(&u.x));
        float2 v1 = __bfloat1622float2(*reinterpret_cast<__nv_bfloat162*>(&u.y));
        a0 += fmaf(p, v0.y - v0.x, v0.x);
        a1 += fmaf(p, v1.y - v1.x, v1.x);
    }
    float rd = g_rdeg[w];
    float2 xr = *reinterpret_cast<const float2*>(g_xr1 + (size_t)w * 64 + 2 * lane);
    float2 hv = make_float2(tanhf(fmaf(a0, rd, xr.x)), tanhf(fmaf(a1, rd, xr.y)));
    *reinterpret_cast<float2*>(g_h + (size_t)w * 64 + 2 * lane) = hv;
    *reinterpret_cast<__nv_bfloat162*>(g_hb + (size_t)w * 64 + 2 * lane) = __float22bfloat162_rn(hv);
}

// ---------------- conv2 aggregation + log_softmax (half-warp/node) ----------------
__global__ void __launch_bounds__(256) k_agg2_lsm(float* __restrict__ out) {
    int hw = (blockIdx.x * 256 + threadIdx.x) >> 4;
    int c = threadIdx.x & 15;
    if (hw >= N_NODES) return;
    int i = g_rowptr[hw], end = g_rowptr[hw + 1];
    float acc = 0.f;
    for (; i + 1 < end; i += 2) {
        int sA = g_es[i], sB = g_es[i + 1];
        float pA = g_ep[i], pB = g_ep[i + 1];
        float2 vA = __bfloat1622float2(*reinterpret_cast<const __nv_bfloat162*>(g_c2 + (size_t)sA * 32 + 2 * c));
        float2 vB = __bfloat1622float2(*reinterpret_cast<const __nv_bfloat162*>(g_c2 + (size_t)sB * 32 + 2 * c));
        acc += fmaf(pA, vA.y - vA.x, vA.x) + fmaf(pB, vB.y - vB.x, vB.x);
    }
    if (i < end) {
        int s = g_es[i];
        float p = g_ep[i];
        float2 v = __bfloat1622float2(*reinterpret_cast<const __nv_bfloat162*>(g_c2 + (size_t)s * 32 + 2 * c));
        acc += fmaf(p, v.y - v.x, v.x);
    }
    float v = tanhf(fmaf(acc, g_rdeg[hw], g_xr2[(size_t)hw * 16 + c]));
    float m = v;
    for (int o = 8; o > 0; o >>= 1) m = fmaxf(m, __shfl_xor_sync(0xffffffffu, m, o, 16));
    float e = expf(v - m);
    float s = e;
    for (int o = 8; o > 0; o >>= 1) s += __shfl_xor_sync(0xffffffffu, s, o, 16);
    out[(size_t)hw * 16 + c] = v - m - logf(s);
}

// ---------------- launch ----------------
extern "C" void kernel_launch(void* const* d_in, const int* in_sizes, int n_in,
                              void* d_out, int out_size) {
    const float* x  = (const float*)d_in[0];
    const float* ea = (const float*)d_in[1];
    const int*   src = (const int*)d_in[2];
    const int*   dst = (const int*)d_in[3];
    const float* W1 = (const float*)d_in[4];
    const float* R1 = (const float*)d_in[5];
    const float* b1 = (const float*)d_in[6];
    const float* Wa = (const float*)d_in[7];
    const float* Ra = (const float*)d_in[8];
    const float* ba = (const float*)d_in[9];
    const float* Wb = (const float*)d_in[10];
    const float* Rb = (const float*)d_in[11];
    const float* bb = (const float*)d_in[12];
    const float* W2 = (const float*)d_in[13];
    const float* R2 = (const float*)d_in[14];
    const float* b2 = (const float*)d_in[15];
    float* out = (float*)d_out;

    float *h, *B1, *Bh1, *Bh2, *B2, *xr1, *xr2;
    __nv_bfloat16 *hb, *midb, *curb, *c1, *c2;
    cudaGetSymbolAddress((void**)&h, g_h);
    cudaGetSymbolAddress((void**)&hb, g_hb);
    cudaGetSymbolAddress((void**)&midb, g_midb);
    cudaGetSymbolAddress((void**)&curb, g_curb);
    cudaGetSymbolAddress((void**)&B1, g_B1);
    cudaGetSymbolAddress((void**)&Bh1, g_Bh1);
    cudaGetSymbolAddress((void**)&Bh2, g_Bh2);
    cudaGetSymbolAddress((void**)&B2, g_B2);
    cudaGetSymbolAddress((void**)&c1, g_c1);
    cudaGetSymbolAddress((void**)&c2, g_c2);
    cudaGetSymbolAddress((void**)&xr1, g_xr1);
    cudaGetSymbolAddress((void**)&xr2, g_xr2);

    // CSR build + weight cat
    k_init<<<NB_SCAN + 192, 256>>>(W1, R1, Wa, Ra, Wb, Rb, W2, R2);
    k_count<<<N_EDGES / 256, 256>>>(dst);
    k_bsum<<<NB_SCAN, 256>>>();
    k_bscan<<<1, 256>>>();
    k_bapply<<<NB_SCAN, 256>>>();

    const int WG = (N_NODES * 32 + 255) / 256;
    const int HG = (N_NODES * 16 + 255) / 256;

    // conv1 GEMM (+ CSR fill hidden in the 4th y-slice)
    k_mm<256, 192, 64, 0><<<dim3(MG, 4), 256>>>(x, B1, b1, c1, xr1, src, dst, ea);
    k_agg1<<<WG, 256>>>();

    // RK4: each stage = (preagg -> GEMM1) -> (preagg -> GEMM2 w/ RK epilogue)
    auto fstep = [&](const __nv_bfloat16* inb, int stage, float curMul) {
        k_preagg<<<WG, 256>>>(inb);
        k_hmm<1><<<MG, 256>>>(inb, Bh1, ba, midb, 0, 0.f);
        k_preagg<<<WG, 256>>>(midb);
        k_hmm<2><<<MG, 256>>>(midb, Bh2, bb, curb, stage, curMul);
    };
    fstep(hb, 1, 1.5f);
    fstep(curb, 2, 1.5f);
    fstep(curb, 3, 3.0f);
    fstep(curb, 4, 0.f);

    // conv2 + log_softmax
    k_mm<64, 48, 48, 3><<<dim3(MG, 1), 256>>>(h, B2, b2, c2, xr2, nullptr, nullptr, nullptr);
    k_agg2_lsm<<<HG, 256>>>(out);
}

// round 9
// speedup vs baseline: 1.3855x; 1.1020x over previous
#include <cuda_runtime.h>
#include <cuda_bf16.h>
#include <cstdint>

#define N_NODES 50000
#define N_EDGES 800000
#define F_IN 256
#define HID 64
#define NCLS 16
#define NB_SCAN 196   // ceil(50000/256)
#define MG 391        // ceil(50000/128)

// ---------------- scratch ----------------
__device__ int   g_cnt[N_NODES];
__device__ int   g_rowptr[N_NODES + 1];
__device__ int   g_cursor[N_NODES];
__device__ int   g_bsum[256];
__device__ int   g_boff[256];
__device__ int   g_es[N_EDGES];
__device__ float g_ep[N_EDGES];
__device__ float g_rdeg[N_NODES];

__device__ __align__(16) float g_h[(size_t)N_NODES * HID];     // fp32 ODE state
__device__ __align__(16) float g_acc[(size_t)N_NODES * HID];   // fp32 RK accumulator
__device__ __align__(16) __nv_bfloat16 g_hb[(size_t)N_NODES * HID];
__device__ __align__(16) __nv_bfloat16 g_midb[(size_t)N_NODES * HID];
__device__ __align__(16) __nv_bfloat16 g_curb[(size_t)N_NODES * HID];
__device__ __align__(16) __nv_bfloat16 g_Ypreb[(size_t)N_NODES * 128]; // [S0n|S1n] bf16
__device__ __align__(16) __nv_bfloat16 g_c1[(size_t)N_NODES * 128]; // interleaved y0/y1, conv1
__device__ __align__(16) float g_xr1[(size_t)N_NODES * HID];
__device__ __align__(16) __nv_bfloat16 g_c2[(size_t)N_NODES * 32];  // interleaved y0/y1, conv2
__device__ __align__(16) float g_xr2[(size_t)N_NODES * NCLS];
// concatenated weights
__device__ __align__(16) float g_B1[256 * 192];            // cols [W1_0 | W1_1 | R1]
__device__ __align__(16) __nv_bfloat16 g_Bh1t[64 * 192];   // bf16, n-major: Bt[n][k], rows-of-B=[Ra;Wa0;Wa1]
__device__ __align__(16) __nv_bfloat16 g_Bh2t[64 * 192];   // bf16, n-major: [Rb;Wb0;Wb1]
__device__ __align__(16) float g_B2[64 * 48];              // cols [W2_0 | W2_1 | R2]

// ---------------- mma helpers ----------------
__device__ __forceinline__ unsigned f2tf(float f) {
    unsigned r; asm("cvt.rna.tf32.f32 %0, %1;" : "=r"(r) : "f"(f)); return r;
}
__device__ __forceinline__ void mma_tf32(float* d, const unsigned* a, const unsigned* b) {
    asm volatile("mma.sync.aligned.m16n8k8.row.col.f32.tf32.tf32.f32 "
        "{%0,%1,%2,%3}, {%4,%5,%6,%7}, {%8,%9}, {%0,%1,%2,%3};"
        : "+f"(d[0]), "+f"(d[1]), "+f"(d[2]), "+f"(d[3])
        : "r"(a[0]), "r"(a[1]), "r"(a[2]), "r"(a[3]), "r"(b[0]), "r"(b[1]));
}
__device__ __forceinline__ void mma_bf16(float* d, const unsigned* a, const unsigned* b) {
    asm volatile("mma.sync.aligned.m16n8k16.row.col.f32.bf16.bf16.f32 "
        "{%0,%1,%2,%3}, {%4,%5,%6,%7}, {%8,%9}, {%0,%1,%2,%3};"
        : "+f"(d[0]), "+f"(d[1]), "+f"(d[2]), "+f"(d[3])
        : "r"(a[0]), "r"(a[1]), "r"(a[2]), "r"(a[3]), "r"(b[0]), "r"(b[1]));
}

// ---------------- init: zero counts + concatenate weights ----------------
__global__ void k_init(const float* __restrict__ W1, const float* __restrict__ R1,
                       const float* __restrict__ Wa, const float* __restrict__ Ra,
                       const float* __restrict__ Wb, const float* __restrict__ Rb,
                       const float* __restrict__ W2, const float* __restrict__ R2) {
    int bx = blockIdx.x, t = threadIdx.x;
    if (bx < NB_SCAN) {
        int i = bx * 256 + t;
        if (i < N_NODES) g_cnt[i] = 0;
        return;
    }
    int i = (bx - NB_SCAN) * 256 + t;
    if (i < 256 * 192) {
        int k = i / 192, n = i % 192;
        float v;
        if (n < 64)       v = W1[k * 64 + n];
        else if (n < 128) v = W1[256 * 64 + k * 64 + (n - 64)];
        else              v = R1[k * 64 + (n - 128)];
        g_B1[i] = v;
    }
    if (i < 64 * 192) {   // bf16 transposed hidden weights: Bt[n][k] = B[k][n]
        int n = i / 192, k = i % 192;
        float va, vb;
        if (k < 64)       { va = Ra[k * 64 + n];                   vb = Rb[k * 64 + n]; }
        else if (k < 128) { va = Wa[(k - 64) * 64 + n];            vb = Wb[(k - 64) * 64 + n]; }
        else              { va = Wa[64 * 64 + (k - 128) * 64 + n]; vb = Wb[64 * 64 + (k - 128) * 64 + n]; }
        g_Bh1t[i] = __float2bfloat16(va);
        g_Bh2t[i] = __float2bfloat16(vb);
    }
    if (i < 64 * 48) {
        int k = i / 48, n = i % 48;
        float v;
        if (n < 16)      v = W2[k * 16 + n];
        else if (n < 32) v = W2[64 * 16 + k * 16 + (n - 16)];
        else             v = R2[k * 16 + (n - 32)];
        g_B2[i] = v;
    }
}

// ---------------- CSR build ----------------
__global__ void k_count(const int* __restrict__ dst) {
    int e = blockIdx.x * blockDim.x + threadIdx.x;
    if (e < N_EDGES) atomicAdd(&g_cnt[dst[e]], 1);
}
__global__ void k_bsum() {
    __shared__ int ss[256];
    int t = threadIdx.x;
    int idx = blockIdx.x * 256 + t;
    ss[t] = (idx < N_NODES) ? g_cnt[idx] : 0;
    __syncthreads();
    for (int off = 128; off > 0; off >>= 1) {
        if (t < off) ss[t] += ss[t + off];
        __syncthreads();
    }
    if (t == 0) g_bsum[blockIdx.x] = ss[0];
}
__global__ void k_bscan() {
    __shared__ int ss[256];
    int t = threadIdx.x;
    int v = (t < NB_SCAN) ? g_bsum[t] : 0;
    ss[t] = v;
    __syncthreads();
    for (int off = 1; off < 256; off <<= 1) {
        int u = (t >= off) ? ss[t - off] : 0;
        __syncthreads();
        ss[t] += u;
        __syncthreads();
    }
    g_boff[t] = ss[t] - v;
    if (t == 255) g_rowptr[N_NODES] = ss[255];
}
__global__ void k_bapply() {
    __shared__ int ss[256];
    int t = threadIdx.x;
    int idx = blockIdx.x * 256 + t;
    int v = (idx < N_NODES) ? g_cnt[idx] : 0;
    ss[t] = v;
    __syncthreads();
    for (int off = 1; off < 256; off <<= 1) {
        int u = (t >= off) ? ss[t - off] : 0;
        __syncthreads();
        ss[t] += u;
        __syncthreads();
    }
    if (idx < N_NODES) {
        int base = g_boff[blockIdx.x] + ss[t] - v;
        g_rowptr[idx] = base;
        g_cursor[idx] = base;
        g_rdeg[idx] = 1.0f / (float)(v > 0 ? v : 1);
    }
}
__global__ void k_fill(const int* __restrict__ src, const int* __restrict__ dst,
                       const float* __restrict__ ea) {
    int e = blockIdx.x * blockDim.x + threadIdx.x;
    if (e < N_EDGES) {
        int pos = atomicAdd(&g_cursor[dst[e]], 1);
        g_es[pos] = src[e];
        g_ep[pos] = ea[e];
    }
}

// ---------------- tf32 GEMM (conv1/conv2), EPI: 0=conv1, 3=conv2 ----------------
template <int K, int NTOT, int BN, int EPI>
__global__ void __launch_bounds__(256) k_mm(const float* __restrict__ A,
                                            const float* __restrict__ B,
                                            const float* __restrict__ bias,
                                            __nv_bfloat16* __restrict__ Cb,
                                            float* __restrict__ aux) {
    __shared__ unsigned As[128][36];
    __shared__ unsigned Bs[32][BN + 8];

    constexpr int BM = 128, BK = 32;
    constexpr int WN = BN / 2, NF = WN / 8;
    const int tid = threadIdx.x;
    const int lane = tid & 31, warp = tid >> 5;
    const int wm = warp & 3, wn = warp >> 2;
    const int mBase = blockIdx.x * BM;
    const int nBase = blockIdx.y * BN;
    const int g = lane >> 2, t = lane & 3;

    float acc[2][NF][4];
#pragma unroll
    for (int mf = 0; mf < 2; ++mf)
#pragma unroll
        for (int nf = 0; nf < NF; ++nf)
#pragma unroll
            for (int q = 0; q < 4; ++q) acc[mf][nf][q] = 0.f;

    const int ar = tid >> 3, ac = (tid & 7) * 4;

    for (int k0 = 0; k0 < K; k0 += BK) {
#pragma unroll
        for (int p = 0; p < 4; ++p) {
            int row = p * 32 + ar;
            int gm = mBase + row;
            float4 v = make_float4(0.f, 0.f, 0.f, 0.f);
            if (gm < N_NODES) v = *reinterpret_cast<const float4*>(A + (size_t)gm * K + k0 + ac);
            unsigned* s = &As[row][ac];
            s[0] = f2tf(v.x); s[1] = f2tf(v.y); s[2] = f2tf(v.z); s[3] = f2tf(v.w);
        }
        for (int i = tid; i < BK * BN / 4; i += 256) {
            int bk = i / (BN / 4), bc = (i % (BN / 4)) * 4;
            float4 v = *reinterpret_cast<const float4*>(B + (size_t)(k0 + bk) * NTOT + nBase + bc);
            unsigned* s = &Bs[bk][bc];
            s[0] = f2tf(v.x); s[1] = f2tf(v.y); s[2] = f2tf(v.z); s[3] = f2tf(v.w);
        }
        __syncthreads();
#pragma unroll
        for (int kk = 0; kk < BK / 8; ++kk) {
            const int kb = kk * 8;
            unsigned a[2][4];
#pragma unroll
            for (int mf = 0; mf < 2; ++mf) {
                int r = wm * 32 + mf * 16;
                a[mf][0] = As[r + g][kb + t];
                a[mf][1] = As[r + g + 8][kb + t];
                a[mf][2] = As[r + g][kb + t + 4];
                a[mf][3] = As[r + g + 8][kb + t + 4];
            }
#pragma unroll
            for (int nf = 0; nf < NF; ++nf) {
                int n = wn * WN + nf * 8;
                unsigned b[2] = { Bs[kb + t][n + g], Bs[kb + t + 4][n + g] };
                mma_tf32(acc[0][nf], a[0], b);
                mma_tf32(acc[1][nf], a[1], b);
            }
        }
        __syncthreads();
    }

    const int by = blockIdx.y;
    auto emit = [&](int row, int col, float a0, float a1) {
        if (row >= N_NODES) return;
        if (EPI == 0) {
            int c = col - (by << 6);
            if (by < 2) {
                Cb[(size_t)row * 128 + 2 * c + by]       = __float2bfloat16(a0);
                Cb[(size_t)row * 128 + 2 * (c + 1) + by] = __float2bfloat16(a1);
            } else {
                *reinterpret_cast<float2*>(aux + (size_t)row * 64 + c) =
                    make_float2(a0 + bias[c], a1 + bias[c + 1]);
            }
        } else {  // EPI == 3 (conv2)
            if (col < 32) {
                int sec = col >> 4, c = col & 15;
                Cb[(size_t)row * 32 + 2 * c + sec]       = __float2bfloat16(a0);
                Cb[(size_t)row * 32 + 2 * (c + 1) + sec] = __float2bfloat16(a1);
            } else {
                *reinterpret_cast<float2*>(aux + (size_t)row * 16 + (col - 32)) =
                    make_float2(a0 + bias[col - 32], a1 + bias[col - 31]);
            }
        }
    };

#pragma unroll
    for (int mf = 0; mf < 2; ++mf)
#pragma unroll
        for (int nf = 0; nf < NF; ++nf) {
            int row = mBase + wm * 32 + mf * 16 + g;
            int col = nBase + wn * WN + nf * 8 + 2 * t;
            emit(row, col, acc[mf][nf][0], acc[mf][nf][1]);
            emit(row + 8, col, acc[mf][nf][2], acc[mf][nf][3]);
        }
}

// ---------------- hidden pre-aggregation: warp/node, bf16 gather x4 -> bf16 [S0n|S1n] ----------------
__global__ void __launch_bounds__(256) k_preagg(const __nv_bfloat16* __restrict__ inb) {
    int w = (blockIdx.x * 256 + threadIdx.x) >> 5;
    int lane = threadIdx.x & 31;
    if (w >= N_NODES) return;
    int i = g_rowptr[w], end = g_rowptr[w + 1];
    float sa0 = 0.f, sa1 = 0.f, sp0 = 0.f, sp1 = 0.f;
    for (; i + 3 < end; i += 4) {
        int s0 = g_es[i], s1 = g_es[i + 1], s2 = g_es[i + 2], s3 = g_es[i + 3];
        float p0 = g_ep[i], p1 = g_ep[i + 1], p2 = g_ep[i + 2], p3 = g_ep[i + 3];
        float2 x0 = __bfloat1622float2(*reinterpret_cast<const __nv_bfloat162*>(inb + (size_t)s0 * 64 + 2 * lane));
        float2 x1 = __bfloat1622float2(*reinterpret_cast<const __nv_bfloat162*>(inb + (size_t)s1 * 64 + 2 * lane));
        float2 x2 = __bfloat1622float2(*reinterpret_cast<const __nv_bfloat162*>(inb + (size_t)s2 * 64 + 2 * lane));
        float2 x3 = __bfloat1622float2(*reinterpret_cast<const __nv_bfloat162*>(inb + (size_t)s3 * 64 + 2 * lane));
        sa0 += (x0.x + x1.x) + (x2.x + x3.x);
        sa1 += (x0.y + x1.y) + (x2.y + x3.y);
        sp0 = fmaf(p0, x0.x, fmaf(p1, x1.x, fmaf(p2, x2.x, fmaf(p3, x3.x, sp0))));
        sp1 = fmaf(p0, x0.y, fmaf(p1, x1.y, fmaf(p2, x2.y, fmaf(p3, x3.y, sp1))));
    }
    for (; i < end; ++i) {
        int s = g_es[i];
        float p = g_ep[i];
        float2 xv = __bfloat1622float2(*reinterpret_cast<const __nv_bfloat162*>(inb + (size_t)s * 64 + 2 * lane));
        sa0 += xv.x; sa1 += xv.y;
        sp0 = fmaf(p, xv.x, sp0);
        sp1 = fmaf(p, xv.y, sp1);
    }
    float rd = g_rdeg[w];
    __nv_bfloat16* yr = g_Ypreb + (size_t)w * 128;
    *reinterpret_cast<__nv_bfloat162*>(yr + 2 * lane) =
        __float22bfloat162_rn(make_float2((sa0 - sp0) * rd, (sa1 - sp1) * rd));
    *reinterpret_cast<__nv_bfloat162*>(yr + 64 + 2 * lane) =
        __float22bfloat162_rn(make_float2(sp0 * rd, sp1 * rd));
}

// ---------------- hidden GEMM (bf16 mma): A=[inb | Ypreb], Bt n-major bf16, K=192 ----------------
// EPI: 1 = write midb (bf16), 2 = RK stage epilogue
template <int EPI>
__global__ void __launch_bounds__(256) k_hmm(const __nv_bfloat16* __restrict__ inb,
                                             const __nv_bfloat16* __restrict__ Bt,
                                             const float* __restrict__ bias,
                                             __nv_bfloat16* __restrict__ outb,
                                             int estage, float curMul) {
    __shared__ __nv_bfloat16 Asm[128][72];    // K-chunk of 64, pad to 72
    __shared__ __nv_bfloat16 Bsm[64][200];    // full B, n-major, pad 192->200

    const int tid = threadIdx.x;
    const int lane = tid & 31, warp = tid >> 5;
    const int wm = warp & 3, wn = warp >> 2;
    const int mBase = blockIdx.x * 128;
    const int g = lane >> 2, t = lane & 3;

    // load full B once (64 x 192 bf16)
    for (int i = tid; i < 64 * 192 / 8; i += 256) {
        int n = i / 24, c8 = (i % 24) * 8;
        *reinterpret_cast<uint4*>(&Bsm[n][c8]) = *reinterpret_cast<const uint4*>(Bt + n * 192 + c8);
    }

    float acc[2][4][4];
#pragma unroll
    for (int mf = 0; mf < 2; ++mf)
#pragma unroll
        for (int nf = 0; nf < 4; ++nf)
#pragma unroll
            for (int q = 0; q < 4; ++q) acc[mf][nf][q] = 0.f;

#pragma unroll
    for (int chunk = 0; chunk < 3; ++chunk) {
        // load A chunk: 128 rows x 64 bf16
#pragma unroll
        for (int i2 = 0; i2 < 4; ++i2) {
            int i = i2 * 256 + tid;
            int row = i >> 3, c8 = (i & 7) * 8;
            int gm = mBase + row;
            uint4 v = make_uint4(0, 0, 0, 0);
            if (gm < N_NODES) {
                if (chunk == 0) v = *reinterpret_cast<const uint4*>(inb + (size_t)gm * 64 + c8);
                else            v = *reinterpret_cast<const uint4*>(g_Ypreb + (size_t)gm * 128 + (chunk - 1) * 64 + c8);
            }
            *reinterpret_cast<uint4*>(&Asm[row][c8]) = v;
        }
        __syncthreads();
#pragma unroll
        for (int kk = 0; kk < 4; ++kk) {
            const int kb = kk * 16;
            unsigned a[2][4];
#pragma unroll
            for (int mf = 0; mf < 2; ++mf) {
                int r = wm * 32 + mf * 16;
                a[mf][0] = *reinterpret_cast<const unsigned*>(&Asm[r + g][kb + 2 * t]);
                a[mf][1] = *reinterpret_cast<const unsigned*>(&Asm[r + g + 8][kb + 2 * t]);
                a[mf][2] = *reinterpret_cast<const unsigned*>(&Asm[r + g][kb + 2 * t + 8]);
                a[mf][3] = *reinterpret_cast<const unsigned*>(&Asm[r + g + 8][kb + 2 * t + 8]);
            }
#pragma unroll
            for (int nf = 0; nf < 4; ++nf) {
                int n = wn * 32 + nf * 8;
                unsigned b[2] = {
                    *reinterpret_cast<const unsigned*>(&Bsm[n + g][chunk * 64 + kb + 2 * t]),
                    *reinterpret_cast<const unsigned*>(&Bsm[n + g][chunk * 64 + kb + 2 * t + 8])
                };
                mma_bf16(acc[0][nf], a[0], b);
                mma_bf16(acc[1][nf], a[1], b);
            }
        }
        __syncthreads();
    }

    auto emit = [&](int row, int col, float a0, float a1) {
        if (row >= N_NODES) return;
        float2 kv = make_float2(a0 + bias[col], a1 + bias[col + 1]);
        size_t idx = (size_t)row * 64 + col;
        if (EPI == 1) {
            *reinterpret_cast<__nv_bfloat162*>(outb + idx) = __float22bfloat162_rn(kv);
        } else {
            float2 h2 = *reinterpret_cast<const float2*>(g_h + idx);
            if (estage == 4) {
                float2 a2 = *reinterpret_cast<const float2*>(g_acc + idx);
                *reinterpret_cast<float2*>(g_h + idx) =
                    make_float2(h2.x + 0.5f * (a2.x + kv.x), h2.y + 0.5f * (a2.y + kv.y));
            } else {
                float2 a2;
                if (estage == 1) a2 = kv;
                else {
                    a2 = *reinterpret_cast<const float2*>(g_acc + idx);
                    a2.x = fmaf(2.f, kv.x, a2.x); a2.y = fmaf(2.f, kv.y, a2.y);
                }
                *reinterpret_cast<float2*>(g_acc + idx) = a2;
                float2 c2 = make_float2(fmaf(curMul, kv.x, h2.x), fmaf(curMul, kv.y, h2.y));
                *reinterpret_cast<__nv_bfloat162*>(outb + idx) = __float22bfloat162_rn(c2);
            }
        }
    };

#pragma unroll
    for (int mf = 0; mf < 2; ++mf)
#pragma unroll
        for (int nf = 0; nf < 4; ++nf) {
            int row = mBase + wm * 32 + mf * 16 + g;
            int col = wn * 32 + nf * 8 + 2 * t;
            emit(row, col, acc[mf][nf][0], acc[mf][nf][1]);
            emit(row + 8, col, acc[mf][nf][2], acc[mf][nf][3]);
        }
}

// ---------------- conv1 aggregation: warp/node, bf16 interleaved gather, tanh ----------------
__global__ void __launch_bounds__(256) k_agg1() {
    int w = (blockIdx.x * 256 + threadIdx.x) >> 5;
    int lane = threadIdx.x & 31;
    if (w >= N_NODES) return;
    int i = g_rowptr[w], end = g_rowptr[w + 1];
    float a0 = 0.f, a1 = 0.f;
    for (; i + 1 < end; i += 2) {
        int sA = g_es[i], sB = g_es[i + 1];
        float pA = g_ep[i], pB = g_ep[i + 1];
        uint2 uA = *reinterpret_cast<const uint2*>(g_c1 + (size_t)sA * 128 + 4 * lane);
        uint2 uB = *reinterpret_cast<const uint2*>(g_c1 + (size_t)sB * 128 + 4 * lane);
        float2 vA0 = __bfloat1622float2(*reinterpret_cast<__nv_bfloat162*>(&uA.x));
        float2 vA1 = __bfloat1622float2(*reinterpret_cast<__nv_bfloat162*>(&uA.y));
        float2 vB0 = __bfloat1622float2(*reinterpret_cast<__nv_bfloat162*>(&uB.x));
        float2 vB1 = __bfloat1622float2(*reinterpret_cast<__nv_bfloat162*>(&uB.y));
        a0 += fmaf(pA, vA0.y - vA0.x, vA0.x) + fmaf(pB, vB0.y - vB0.x, vB0.x);
        a1 += fmaf(pA, vA1.y - vA1.x, vA1.x) + fmaf(pB, vB1.y - vB1.x, vB1.x);
    }
    if (i < end) {
        int s = g_es[i];
        float p = g_ep[i];
        uint2 u = *reinterpret_cast<const uint2*>(g_c1 + (size_t)s * 128 + 4 * lane);
        float2 v0 = __bfloat1622float2(*reinterpret_cast<__nv_bfloat162*>(&u.x));
        float2 v1 = __bfloat1622float2(*reinterpret_cast<__nv_bfloat162*>(&u.y));
        a0 += fmaf(p, v0.y - v0.x, v0.x);
        a1 += fmaf(p, v1.y - v1.x, v1.x);
    }
    float rd = g_rdeg[w];
    float2 xr = *reinterpret_cast<const float2*>(g_xr1 + (size_t)w * 64 + 2 * lane);
    float2 hv = make_float2(tanhf(fmaf(a0, rd, xr.x)), tanhf(fmaf(a1, rd, xr.y)));
    *reinterpret_cast<float2*>(g_h + (size_t)w * 64 + 2 * lane) = hv;
    *reinterpret_cast<__nv_bfloat162*>(g_hb + (size_t)w * 64 + 2 * lane) = __float22bfloat162_rn(hv);
}

// ---------------- conv2 aggregation + log_softmax (half-warp/node) ----------------
__global__ void __launch_bounds__(256) k_agg2_lsm(float* __restrict__ out) {
    int hw = (blockIdx.x * 256 + threadIdx.x) >> 4;
    int c = threadIdx.x & 15;
    if (hw >= N_NODES) return;
    int i = g_rowptr[hw], end = g_rowptr[hw + 1];
    float acc = 0.f;
    for (; i + 1 < end; i += 2) {
        int sA = g_es[i], sB = g_es[i + 1];
        float pA = g_ep[i], pB = g_ep[i + 1];
        float2 vA = __bfloat1622float2(*reinterpret_cast<const __nv_bfloat162*>(g_c2 + (size_t)sA * 32 + 2 * c));
        float2 vB = __bfloat1622float2(*reinterpret_cast<const __nv_bfloat162*>(g_c2 + (size_t)sB * 32 + 2 * c));
        acc += fmaf(pA, vA.y - vA.x, vA.x) + fmaf(pB, vB.y - vB.x, vB.x);
    }
    if (i < end) {
        int s = g_es[i];
        float p = g_ep[i];
        float2 v = __bfloat1622float2(*reinterpret_cast<const __nv_bfloat162*>(g_c2 + (size_t)s * 32 + 2 * c));
        acc += fmaf(p, v.y - v.x, v.x);
    }
    float v = tanhf(fmaf(acc, g_rdeg[hw], g_xr2[(size_t)hw * 16 + c]));
    float m = v;
    for (int o = 8; o > 0; o >>= 1) m = fmaxf(m, __shfl_xor_sync(0xffffffffu, m, o, 16));
    float e = expf(v - m);
    float s = e;
    for (int o = 8; o > 0; o >>= 1) s += __shfl_xor_sync(0xffffffffu, s, o, 16);
    out[(size_t)hw * 16 + c] = v - m - logf(s);
}

// ---------------- launch ----------------
extern "C" void kernel_launch(void* const* d_in, const int* in_sizes, int n_in,
                              void* d_out, int out_size) {
    const float* x  = (const float*)d_in[0];
    const float* ea = (const float*)d_in[1];
    const int*   src = (const int*)d_in[2];
    const int*   dst = (const int*)d_in[3];
    const float* W1 = (const float*)d_in[4];
    const float* R1 = (const float*)d_in[5];
    const float* b1 = (const float*)d_in[6];
    const float* Wa = (const float*)d_in[7];
    const float* Ra = (const float*)d_in[8];
    const float* ba = (const float*)d_in[9];
    const float* Wb = (const float*)d_in[10];
    const float* Rb = (const float*)d_in[11];
    const float* bb = (const float*)d_in[12];
    const float* W2 = (const float*)d_in[13];
    const float* R2 = (const float*)d_in[14];
    const float* b2 = (const float*)d_in[15];
    float* out = (float*)d_out;

    float *h, *B1, *B2, *xr1, *xr2;
    __nv_bfloat16 *hb, *midb, *curb, *c1, *c2, *Bh1t, *Bh2t;
    cudaGetSymbolAddress((void**)&h, g_h);
    cudaGetSymbolAddress((void**)&hb, g_hb);
    cudaGetSymbolAddress((void**)&midb, g_midb);
    cudaGetSymbolAddress((void**)&curb, g_curb);
    cudaGetSymbolAddress((void**)&B1, g_B1);
    cudaGetSymbolAddress((void**)&Bh1t, g_Bh1t);
    cudaGetSymbolAddress((void**)&Bh2t, g_Bh2t);
    cudaGetSymbolAddress((void**)&B2, g_B2);
    cudaGetSymbolAddress((void**)&c1, g_c1);
    cudaGetSymbolAddress((void**)&c2, g_c2);
    cudaGetSymbolAddress((void**)&xr1, g_xr1);
    cudaGetSymbolAddress((void**)&xr2, g_xr2);

    static cudaStream_t s2 = nullptr;
    static cudaEvent_t e1 = nullptr, e2 = nullptr;
    if (s2 == nullptr) {
        cudaStreamCreateWithFlags(&s2, cudaStreamNonBlocking);
        cudaEventCreateWithFlags(&e1, cudaEventDisableTiming);
        cudaEventCreateWithFlags(&e2, cudaEventDisableTiming);
    }

    // init (zero cnt + weight concat) on main stream
    k_init<<<NB_SCAN + 192, 256>>>(W1, R1, Wa, Ra, Wb, Rb, W2, R2);

    // fork: CSR chain on side stream, conv1 GEMM on main stream (independent)
    cudaEventRecord(e1, 0);
    cudaStreamWaitEvent(s2, e1, 0);
    k_count<<<N_EDGES / 256, 256, 0, s2>>>(dst);
    k_bsum<<<NB_SCAN, 256, 0, s2>>>();
    k_bscan<<<1, 256, 0, s2>>>();
    k_bapply<<<NB_SCAN, 256, 0, s2>>>();
    k_fill<<<N_EDGES / 256, 256, 0, s2>>>(src, dst, ea);
    cudaEventRecord(e2, s2);

    k_mm<256, 192, 64, 0><<<dim3(MG, 3), 256>>>(x, B1, b1, c1, xr1);

    // join: everything below needs both CSR and conv1 output
    cudaStreamWaitEvent(0, e2, 0);

    const int WG = (N_NODES * 32 + 255) / 256;
    const int HG = (N_NODES * 16 + 255) / 256;

    k_agg1<<<WG, 256>>>();

    // RK4: each stage = (preagg -> GEMM1) -> (preagg -> GEMM2 w/ RK epilogue)
    auto fstep = [&](const __nv_bfloat16* inb, int stage, float curMul) {
        k_preagg<<<WG, 256>>>(inb);
        k_hmm<1><<<MG, 256>>>(inb, Bh1t, ba, midb, 0, 0.f);
        k_preagg<<<WG, 256>>>(midb);
        k_hmm<2><<<MG, 256>>>(midb, Bh2t, bb, curb, stage, curMul);
    };
    fstep(hb, 1, 1.5f);
    fstep(curb, 2, 1.5f);
    fstep(curb, 3, 3.0f);
    fstep(curb, 4, 0.f);

    // conv2 + log_softmax
    k_mm<64, 48, 48, 3><<<dim3(MG, 1), 256>>>(h, B2, b2, c2, xr2);
    k_agg2_lsm<<<HG, 256>>>(out);
}

// round 10
// speedup vs baseline: 1.4605x; 1.0541x over previous
#include <cuda_runtime.h>
#include <cuda_bf16.h>
#include <cstdint>

#define N_NODES 50000
#define N_EDGES 800000
#define F_IN 256
#define HID 64
#define NCLS 16
#define NB_SCAN 196   // ceil(50000/256)
#define MG 391        // ceil(50000/128)

// PDL: allow dependents to launch early; wait gates consumption of predecessor data.
#define PDL_TRIGGER() asm volatile("griddepcontrol.launch_dependents;" ::: "memory")
#define PDL_WAIT()    asm volatile("griddepcontrol.wait;" ::: "memory")

// ---------------- scratch ----------------
__device__ int   g_cnt[N_NODES];
__device__ int   g_rowptr[N_NODES + 1];
__device__ int   g_cursor[N_NODES];
__device__ int   g_bsum[256];
__device__ int   g_boff[256];
__device__ int   g_es[N_EDGES];
__device__ float g_ep[N_EDGES];
__device__ float g_rdeg[N_NODES];

__device__ __align__(16) float g_h[(size_t)N_NODES * HID];     // fp32 ODE state
__device__ __align__(16) float g_acc[(size_t)N_NODES * HID];   // fp32 RK accumulator
__device__ __align__(16) __nv_bfloat16 g_hb[(size_t)N_NODES * HID];
__device__ __align__(16) __nv_bfloat16 g_midb[(size_t)N_NODES * HID];
__device__ __align__(16) __nv_bfloat16 g_curb[(size_t)N_NODES * HID];
__device__ __align__(16) __nv_bfloat16 g_Ypreb[(size_t)N_NODES * 128]; // [S0n|S1n] bf16
__device__ __align__(16) __nv_bfloat16 g_c1[(size_t)N_NODES * 128]; // interleaved y0/y1, conv1
__device__ __align__(16) float g_xr1[(size_t)N_NODES * HID];
__device__ __align__(16) __nv_bfloat16 g_c2[(size_t)N_NODES * 32];  // interleaved y0/y1, conv2
__device__ __align__(16) float g_xr2[(size_t)N_NODES * NCLS];
// concatenated weights
__device__ __align__(16) float g_B1[256 * 192];            // cols [W1_0 | W1_1 | R1]
__device__ __align__(16) __nv_bfloat16 g_Bh1t[64 * 192];   // bf16 n-major: [Ra;Wa0;Wa1]^T
__device__ __align__(16) __nv_bfloat16 g_Bh2t[64 * 192];   // bf16 n-major: [Rb;Wb0;Wb1]^T
__device__ __align__(16) float g_B2[64 * 48];              // cols [W2_0 | W2_1 | R2]

// ---------------- mma helpers ----------------
__device__ __forceinline__ unsigned f2tf(float f) {
    unsigned r; asm("cvt.rna.tf32.f32 %0, %1;" : "=r"(r) : "f"(f)); return r;
}
__device__ __forceinline__ void mma_tf32(float* d, const unsigned* a, const unsigned* b) {
    asm volatile("mma.sync.aligned.m16n8k8.row.col.f32.tf32.tf32.f32 "
        "{%0,%1,%2,%3}, {%4,%5,%6,%7}, {%8,%9}, {%0,%1,%2,%3};"
        : "+f"(d[0]), "+f"(d[1]), "+f"(d[2]), "+f"(d[3])
        : "r"(a[0]), "r"(a[1]), "r"(a[2]), "r"(a[3]), "r"(b[0]), "r"(b[1]));
}
__device__ __forceinline__ void mma_bf16(float* d, const unsigned* a, const unsigned* b) {
    asm volatile("mma.sync.aligned.m16n8k16.row.col.f32.bf16.bf16.f32 "
        "{%0,%1,%2,%3}, {%4,%5,%6,%7}, {%8,%9}, {%0,%1,%2,%3};"
        : "+f"(d[0]), "+f"(d[1]), "+f"(d[2]), "+f"(d[3])
        : "r"(a[0]), "r"(a[1]), "r"(a[2]), "r"(a[3]), "r"(b[0]), "r"(b[1]));
}

// ---------------- PDL launch helper ----------------
template <typename... P, typename... A>
static inline void launch_pdl(dim3 g, dim3 b, cudaStream_t st, void (*k)(P...), A... args) {
    cudaLaunchConfig_t cfg = {};
    cfg.gridDim = g; cfg.blockDim = b; cfg.dynamicSmemBytes = 0; cfg.stream = st;
    cudaLaunchAttribute at[1];
    at[0].id = cudaLaunchAttributeProgrammaticStreamSerialization;
    at[0].val.programmaticStreamSerializationAllowed = 1;
    cfg.attrs = at; cfg.numAttrs = 1;
    cudaLaunchKernelEx(&cfg, k, static_cast<P>(args)...);
}

// ---------------- init: concatenate weights (main stream) ----------------
__global__ void k_initW(const float* __restrict__ W1, const float* __restrict__ R1,
                        const float* __restrict__ Wa, const float* __restrict__ Ra,
                        const float* __restrict__ Wb, const float* __restrict__ Rb,
                        const float* __restrict__ W2, const float* __restrict__ R2) {
    PDL_TRIGGER();
    int i = blockIdx.x * 256 + threadIdx.x;
    if (i < 256 * 192) {
        int k = i / 192, n = i % 192;
        float v;
        if (n < 64)       v = W1[k * 64 + n];
        else if (n < 128) v = W1[256 * 64 + k * 64 + (n - 64)];
        else              v = R1[k * 64 + (n - 128)];
        g_B1[i] = v;
    }
    if (i < 64 * 192) {   // bf16 transposed hidden weights: Bt[n][k] = B[k][n]
        int n = i / 192, k = i % 192;
        float va, vb;
        if (k < 64)       { va = Ra[k * 64 + n];                   vb = Rb[k * 64 + n]; }
        else if (k < 128) { va = Wa[(k - 64) * 64 + n];            vb = Wb[(k - 64) * 64 + n]; }
        else              { va = Wa[64 * 64 + (k - 128) * 64 + n]; vb = Wb[64 * 64 + (k - 128) * 64 + n]; }
        g_Bh1t[i] = __float2bfloat16(va);
        g_Bh2t[i] = __float2bfloat16(vb);
    }
    if (i < 64 * 48) {
        int k = i / 48, n = i % 48;
        float v;
        if (n < 16)      v = W2[k * 16 + n];
        else if (n < 32) v = W2[64 * 16 + k * 16 + (n - 16)];
        else             v = R2[k * 16 + (n - 32)];
        g_B2[i] = v;
    }
}

// ---------------- CSR build (side stream, PDL chained) ----------------
__global__ void k_zero() {
    PDL_TRIGGER();
    int i = blockIdx.x * 256 + threadIdx.x;
    if (i < N_NODES) g_cnt[i] = 0;
}
__global__ void k_count(const int* __restrict__ dst) {
    PDL_TRIGGER();
    int e = blockIdx.x * blockDim.x + threadIdx.x;
    int d = (e < N_EDGES) ? dst[e] : -1;
    PDL_WAIT();
    if (e < N_EDGES) atomicAdd(&g_cnt[d], 1);
}
__global__ void k_bsum() {
    PDL_TRIGGER();
    __shared__ int ss[256];
    int t = threadIdx.x;
    int idx = blockIdx.x * 256 + t;
    PDL_WAIT();
    ss[t] = (idx < N_NODES) ? g_cnt[idx] : 0;
    __syncthreads();
    for (int off = 128; off > 0; off >>= 1) {
        if (t < off) ss[t] += ss[t + off];
        __syncthreads();
    }
    if (t == 0) g_bsum[blockIdx.x] = ss[0];
}
__global__ void k_bscan() {
    PDL_TRIGGER();
    __shared__ int ss[256];
    int t = threadIdx.x;
    PDL_WAIT();
    int v = (t < NB_SCAN) ? g_bsum[t] : 0;
    ss[t] = v;
    __syncthreads();
    for (int off = 1; off < 256; off <<= 1) {
        int u = (t >= off) ? ss[t - off] : 0;
        __syncthreads();
        ss[t] += u;
        __syncthreads();
    }
    g_boff[t] = ss[t] - v;
    if (t == 255) g_rowptr[N_NODES] = ss[255];
}
__global__ void k_bapply() {
    PDL_TRIGGER();
    __shared__ int ss[256];
    int t = threadIdx.x;
    int idx = blockIdx.x * 256 + t;
    PDL_WAIT();
    int v = (idx < N_NODES) ? g_cnt[idx] : 0;
    ss[t] = v;
    __syncthreads();
    for (int off = 1; off < 256; off <<= 1) {
        int u = (t >= off) ? ss[t - off] : 0;
        __syncthreads();
        ss[t] += u;
        __syncthreads();
    }
    if (idx < N_NODES) {
        int base = g_boff[blockIdx.x] + ss[t] - v;
        g_rowptr[idx] = base;
        g_cursor[idx] = base;
        g_rdeg[idx] = 1.0f / (float)(v > 0 ? v : 1);
    }
}
__global__ void k_fill(const int* __restrict__ src, const int* __restrict__ dst,
                       const float* __restrict__ ea) {
    PDL_TRIGGER();
    int e = blockIdx.x * blockDim.x + threadIdx.x;
    int s = 0, d = 0; float p = 0.f;
    if (e < N_EDGES) { s = src[e]; d = dst[e]; p = ea[e]; }
    PDL_WAIT();
    if (e < N_EDGES) {
        int pos = atomicAdd(&g_cursor[d], 1);
        g_es[pos] = s;
        g_ep[pos] = p;
    }
}

// ---------------- tf32 GEMM (conv1/conv2), EPI: 0=conv1, 3=conv2 ----------------
template <int K, int NTOT, int BN, int EPI>
__global__ void __launch_bounds__(256) k_mm(const float* __restrict__ A,
                                            const float* __restrict__ B,
                                            const float* __restrict__ bias,
                                            __nv_bfloat16* __restrict__ Cb,
                                            float* __restrict__ aux) {
    PDL_TRIGGER();
    __shared__ unsigned As[128][36];
    __shared__ unsigned Bs[32][BN + 8];

    constexpr int BM = 128, BK = 32;
    constexpr int WN = BN / 2, NF = WN / 8;
    const int tid = threadIdx.x;
    const int lane = tid & 31, warp = tid >> 5;
    const int wm = warp & 3, wn = warp >> 2;
    const int mBase = blockIdx.x * BM;
    const int nBase = blockIdx.y * BN;
    const int g = lane >> 2, t = lane & 3;

    float acc[2][NF][4];
#pragma unroll
    for (int mf = 0; mf < 2; ++mf)
#pragma unroll
        for (int nf = 0; nf < NF; ++nf)
#pragma unroll
            for (int q = 0; q < 4; ++q) acc[mf][nf][q] = 0.f;

    const int ar = tid >> 3, ac = (tid & 7) * 4;
    PDL_WAIT();   // conv1: B1 from k_initW; conv2: g_h from last k_hmm

    for (int k0 = 0; k0 < K; k0 += BK) {
#pragma unroll
        for (int p = 0; p < 4; ++p) {
            int row = p * 32 + ar;
            int gm = mBase + row;
            float4 v = make_float4(0.f, 0.f, 0.f, 0.f);
            if (gm < N_NODES) v = *reinterpret_cast<const float4*>(A + (size_t)gm * K + k0 + ac);
            unsigned* s = &As[row][ac];
            s[0] = f2tf(v.x); s[1] = f2tf(v.y); s[2] = f2tf(v.z); s[3] = f2tf(v.w);
        }
        for (int i = tid; i < BK * BN / 4; i += 256) {
            int bk = i / (BN / 4), bc = (i % (BN / 4)) * 4;
            float4 v = *reinterpret_cast<const float4*>(B + (size_t)(k0 + bk) * NTOT + nBase + bc);
            unsigned* s = &Bs[bk][bc];
            s[0] = f2tf(v.x); s[1] = f2tf(v.y); s[2] = f2tf(v.z); s[3] = f2tf(v.w);
        }
        __syncthreads();
#pragma unroll
        for (int kk = 0; kk < BK / 8; ++kk) {
            const int kb = kk * 8;
            unsigned a[2][4];
#pragma unroll
            for (int mf = 0; mf < 2; ++mf) {
                int r = wm * 32 + mf * 16;
                a[mf][0] = As[r + g][kb + t];
                a[mf][1] = As[r + g + 8][kb + t];
                a[mf][2] = As[r + g][kb + t + 4];
                a[mf][3] = As[r + g + 8][kb + t + 4];
            }
#pragma unroll
            for (int nf = 0; nf < NF; ++nf) {
                int n = wn * WN + nf * 8;
                unsigned b[2] = { Bs[kb + t][n + g], Bs[kb + t + 4][n + g] };
                mma_tf32(acc[0][nf], a[0], b);
                mma_tf32(acc[1][nf], a[1], b);
            }
        }
        __syncthreads();
    }

    const int by = blockIdx.y;
    auto emit = [&](int row, int col, float a0, float a1) {
        if (row >= N_NODES) return;
        if (EPI == 0) {
            int c = col - (by << 6);
            if (by < 2) {
                Cb[(size_t)row * 128 + 2 * c + by]       = __float2bfloat16(a0);
                Cb[(size_t)row * 128 + 2 * (c + 1) + by] = __float2bfloat16(a1);
            } else {
                *reinterpret_cast<float2*>(aux + (size_t)row * 64 + c) =
                    make_float2(a0 + bias[c], a1 + bias[c + 1]);
            }
        } else {  // EPI == 3 (conv2)
            if (col < 32) {
                int sec = col >> 4, c = col & 15;
                Cb[(size_t)row * 32 + 2 * c + sec]       = __float2bfloat16(a0);
                Cb[(size_t)row * 32 + 2 * (c + 1) + sec] = __float2bfloat16(a1);
            } else {
                *reinterpret_cast<float2*>(aux + (size_t)row * 16 + (col - 32)) =
                    make_float2(a0 + bias[col - 32], a1 + bias[col - 31]);
            }
        }
    };

#pragma unroll
    for (int mf = 0; mf < 2; ++mf)
#pragma unroll
        for (int nf = 0; nf < NF; ++nf) {
            int row = mBase + wm * 32 + mf * 16 + g;
            int col = nBase + wn * WN + nf * 8 + 2 * t;
            emit(row, col, acc[mf][nf][0], acc[mf][nf][1]);
            emit(row + 8, col, acc[mf][nf][2], acc[mf][nf][3]);
        }
}

// ---------------- hidden pre-aggregation: warp/node, bf16 gather x4 -> bf16 [S0n|S1n] ----------------
__global__ void __launch_bounds__(256) k_preagg(const __nv_bfloat16* __restrict__ inb) {
    PDL_TRIGGER();
    int w = (blockIdx.x * 256 + threadIdx.x) >> 5;
    int lane = threadIdx.x & 31;
    if (w >= N_NODES) { PDL_WAIT(); return; }
    int i = g_rowptr[w], end = g_rowptr[w + 1];
    float rd = g_rdeg[w];
    PDL_WAIT();   // features (inb) from predecessor
    float sa0 = 0.f, sa1 = 0.f, sp0 = 0.f, sp1 = 0.f;
    for (; i + 3 < end; i += 4) {
        int s0 = g_es[i], s1 = g_es[i + 1], s2 = g_es[i + 2], s3 = g_es[i + 3];
        float p0 = g_ep[i], p1 = g_ep[i + 1], p2 = g_ep[i + 2], p3 = g_ep[i + 3];
        float2 x0 = __bfloat1622float2(*reinterpret_cast<const __nv_bfloat162*>(inb + (size_t)s0 * 64 + 2 * lane));
        float2 x1 = __bfloat1622float2(*reinterpret_cast<const __nv_bfloat162*>(inb + (size_t)s1 * 64 + 2 * lane));
        float2 x2 = __bfloat1622float2(*reinterpret_cast<const __nv_bfloat162*>(inb + (size_t)s2 * 64 + 2 * lane));
        float2 x3 = __bfloat1622float2(*reinterpret_cast<const __nv_bfloat162*>(inb + (size_t)s3 * 64 + 2 * lane));
        sa0 += (x0.x + x1.x) + (x2.x + x3.x);
        sa1 += (x0.y + x1.y) + (x2.y + x3.y);
        sp0 = fmaf(p0, x0.x, fmaf(p1, x1.x, fmaf(p2, x2.x, fmaf(p3, x3.x, sp0))));
        sp1 = fmaf(p0, x0.y, fmaf(p1, x1.y, fmaf(p2, x2.y, fmaf(p3, x3.y, sp1))));
    }
    for (; i < end; ++i) {
        int s = g_es[i];
        float p = g_ep[i];
        float2 xv = __bfloat1622float2(*reinterpret_cast<const __nv_bfloat162*>(inb + (size_t)s * 64 + 2 * lane));
        sa0 += xv.x; sa1 += xv.y;
        sp0 = fmaf(p, xv.x, sp0);
        sp1 = fmaf(p, xv.y, sp1);
    }
    __nv_bfloat16* yr = g_Ypreb + (size_t)w * 128;
    *reinterpret_cast<__nv_bfloat162*>(yr + 2 * lane) =
        __float22bfloat162_rn(make_float2((sa0 - sp0) * rd, (sa1 - sp1) * rd));
    *reinterpret_cast<__nv_bfloat162*>(yr + 64 + 2 * lane) =
        __float22bfloat162_rn(make_float2(sp0 * rd, sp1 * rd));
}

// ---------------- hidden GEMM (bf16 mma): A=[inb | Ypreb], Bt n-major bf16, K=192 ----------------
// EPI: 1 = write midb (bf16), 2 = RK stage epilogue
template <int EPI>
__global__ void __launch_bounds__(256) k_hmm(const __nv_bfloat16* __restrict__ inb,
                                             const __nv_bfloat16* __restrict__ Bt,
                                             const float* __restrict__ bias,
                                             __nv_bfloat16* __restrict__ outb,
                                             int estage, float curMul) {
    PDL_TRIGGER();
    __shared__ __nv_bfloat16 Asm[128][72];    // K-chunk of 64, pad to 72
    __shared__ __nv_bfloat16 Bsm[64][200];    // full B, n-major, pad 192->200

    const int tid = threadIdx.x;
    const int lane = tid & 31, warp = tid >> 5;
    const int wm = warp & 3, wn = warp >> 2;
    const int mBase = blockIdx.x * 128;
    const int g = lane >> 2, t = lane & 3;

    // load full B once (64 x 192 bf16) — static weights, pre-wait prologue
    for (int i = tid; i < 64 * 192 / 8; i += 256) {
        int n = i / 24, c8 = (i % 24) * 8;
        *reinterpret_cast<uint4*>(&Bsm[n][c8]) = *reinterpret_cast<const uint4*>(Bt + n * 192 + c8);
    }

    float acc[2][4][4];
#pragma unroll
    for (int mf = 0; mf < 2; ++mf)
#pragma unroll
        for (int nf = 0; nf < 4; ++nf)
#pragma unroll
            for (int q = 0; q < 4; ++q) acc[mf][nf][q] = 0.f;

    PDL_WAIT();   // inb/Ypreb from predecessors

#pragma unroll
    for (int chunk = 0; chunk < 3; ++chunk) {
        // load A chunk: 128 rows x 64 bf16
#pragma unroll
        for (int i2 = 0; i2 < 4; ++i2) {
            int i = i2 * 256 + tid;
            int row = i >> 3, c8 = (i & 7) * 8;
            int gm = mBase + row;
            uint4 v = make_uint4(0, 0, 0, 0);
            if (gm < N_NODES) {
                if (chunk == 0) v = *reinterpret_cast<const uint4*>(inb + (size_t)gm * 64 + c8);
                else            v = *reinterpret_cast<const uint4*>(g_Ypreb + (size_t)gm * 128 + (chunk - 1) * 64 + c8);
            }
            *reinterpret_cast<uint4*>(&Asm[row][c8]) = v;
        }
        __syncthreads();
#pragma unroll
        for (int kk = 0; kk < 4; ++kk) {
            const int kb = kk * 16;
            unsigned a[2][4];
#pragma unroll
            for (int mf = 0; mf < 2; ++mf) {
                int r = wm * 32 + mf * 16;
                a[mf][0] = *reinterpret_cast<const unsigned*>(&Asm[r + g][kb + 2 * t]);
                a[mf][1] = *reinterpret_cast<const unsigned*>(&Asm[r + g + 8][kb + 2 * t]);
                a[mf][2] = *reinterpret_cast<const unsigned*>(&Asm[r + g][kb + 2 * t + 8]);
                a[mf][3] = *reinterpret_cast<const unsigned*>(&Asm[r + g + 8][kb + 2 * t + 8]);
            }
#pragma unroll
            for (int nf = 0; nf < 4; ++nf) {
                int n = wn * 32 + nf * 8;
                unsigned b[2] = {
                    *reinterpret_cast<const unsigned*>(&Bsm[n + g][chunk * 64 + kb + 2 * t]),
                    *reinterpret_cast<const unsigned*>(&Bsm[n + g][chunk * 64 + kb + 2 * t + 8])
                };
                mma_bf16(acc[0][nf], a[0], b);
                mma_bf16(acc[1][nf], a[1], b);
            }
        }
        __syncthreads();
    }

    auto emit = [&](int row, int col, float a0, float a1) {
        if (row >= N_NODES) return;
        float2 kv = make_float2(a0 + bias[col], a1 + bias[col + 1]);
        size_t idx = (size_t)row * 64 + col;
        if (EPI == 1) {
            *reinterpret_cast<__nv_bfloat162*>(outb + idx) = __float22bfloat162_rn(kv);
        } else {
            float2 h2 = *reinterpret_cast<const float2*>(g_h + idx);
            if (estage == 4) {
                float2 a2 = *reinterpret_cast<const float2*>(g_acc + idx);
                *reinterpret_cast<float2*>(g_h + idx) =
                    make_float2(h2.x + 0.5f * (a2.x + kv.x), h2.y + 0.5f * (a2.y + kv.y));
            } else {
                float2 a2;
                if (estage == 1) a2 = kv;
                else {
                    a2 = *reinterpret_cast<const float2*>(g_acc + idx);
                    a2.x = fmaf(2.f, kv.x, a2.x); a2.y = fmaf(2.f, kv.y, a2.y);
                }
                *reinterpret_cast<float2*>(g_acc + idx) = a2;
                float2 c2 = make_float2(fmaf(curMul, kv.x, h2.x), fmaf(curMul, kv.y, h2.y));
                *reinterpret_cast<__nv_bfloat162*>(outb + idx) = __float22bfloat162_rn(c2);
            }
        }
    };

#pragma unroll
    for (int mf = 0; mf < 2; ++mf)
#pragma unroll
        for (int nf = 0; nf < 4; ++nf) {
            int row = mBase + wm * 32 + mf * 16 + g;
            int col = wn * 32 + nf * 8 + 2 * t;
            emit(row, col, acc[mf][nf][0], acc[mf][nf][1]);
            emit(row + 8, col, acc[mf][nf][2], acc[mf][nf][3]);
        }
}

// ---------------- conv1 aggregation: warp/node, bf16 interleaved gather x4, tanh ----------------
__global__ void __launch_bounds__(256) k_agg1() {
    PDL_TRIGGER();
    int w = (blockIdx.x * 256 + threadIdx.x) >> 5;
    int lane = threadIdx.x & 31;
    if (w >= N_NODES) { PDL_WAIT(); return; }
    int i = g_rowptr[w], end = g_rowptr[w + 1];
    float rd = g_rdeg[w];
    PDL_WAIT();   // g_c1 / g_xr1 from conv1 GEMM
    float a0 = 0.f, a1 = 0.f;
    for (; i + 3 < end; i += 4) {
        int s0 = g_es[i], s1 = g_es[i + 1], s2 = g_es[i + 2], s3 = g_es[i + 3];
        float p0 = g_ep[i], p1 = g_ep[i + 1], p2 = g_ep[i + 2], p3 = g_ep[i + 3];
        uint2 u0 = *reinterpret_cast<const uint2*>(g_c1 + (size_t)s0 * 128 + 4 * lane);
        uint2 u1 = *reinterpret_cast<const uint2*>(g_c1 + (size_t)s1 * 128 + 4 * lane);
        uint2 u2 = *reinterpret_cast<const uint2*>(g_c1 + (size_t)s2 * 128 + 4 * lane);
        uint2 u3 = *reinterpret_cast<const uint2*>(g_c1 + (size_t)s3 * 128 + 4 * lane);
        float2 w00 = __bfloat1622float2(*reinterpret_cast<__nv_bfloat162*>(&u0.x));
        float2 w01 = __bfloat1622float2(*reinterpret_cast<__nv_bfloat162*>(&u0.y));
        float2 w10 = __bfloat1622float2(*reinterpret_cast<__nv_bfloat162*>(&u1.x));
        float2 w11 = __bfloat1622float2(*reinterpret_cast<__nv_bfloat162*>(&u1.y));
        float2 w20 = __bfloat1622float2(*reinterpret_cast<__nv_bfloat162*>(&u2.x));
        float2 w21 = __bfloat1622float2(*reinterpret_cast<__nv_bfloat162*>(&u2.y));
        float2 w30 = __bfloat1622float2(*reinterpret_cast<__nv_bfloat162*>(&u3.x));
        float2 w31 = __bfloat1622float2(*reinterpret_cast<__nv_bfloat162*>(&u3.y));
        a0 += fmaf(p0, w00.y - w00.x, w00.x) + fmaf(p1, w10.y - w10.x, w10.x)
            + fmaf(p2, w20.y - w20.x, w20.x) + fmaf(p3, w30.y - w30.x, w30.x);
        a1 += fmaf(p0, w01.y - w01.x, w01.x) + fmaf(p1, w11.y - w11.x, w11.x)
            + fmaf(p2, w21.y - w21.x, w21.x) + fmaf(p3, w31.y - w31.x, w31.x);
    }
    for (; i < end; ++i) {
        int s = g_es[i];
        float p = g_ep[i];
        uint2 u = *reinterpret_cast<const uint2*>(g_c1 + (size_t)s * 128 + 4 * lane);
        float2 v0 = __bfloat1622float2(*reinterpret_cast<__nv_bfloat162*>(&u.x));
        float2 v1 = __bfloat1622float2(*reinterpret_cast<__nv_bfloat162*>(&u.y));
        a0 += fmaf(p, v0.y - v0.x, v0.x);
        a1 += fmaf(p, v1.y - v1.x, v1.x);
    }
    float2 xr = *reinterpret_cast<const float2*>(g_xr1 + (size_t)w * 64 + 2 * lane);
    float2 hv = make_float2(tanhf(fmaf(a0, rd, xr.x)), tanhf(fmaf(a1, rd, xr.y)));
    *reinterpret_cast<float2*>(g_h + (size_t)w * 64 + 2 * lane) = hv;
    *reinterpret_cast<__nv_bfloat162*>(g_hb + (size_t)w * 64 + 2 * lane) = __float22bfloat162_rn(hv);
}

// ---------------- conv2 aggregation + log_softmax (half-warp/node) ----------------
__global__ void __launch_bounds__(256) k_agg2_lsm(float* __restrict__ out) {
    PDL_TRIGGER();
    int hw = (blockIdx.x * 256 + threadIdx.x) >> 4;
    int c = threadIdx.x & 15;
    if (hw >= N_NODES) { PDL_WAIT(); return; }
    int i = g_rowptr[hw], end = g_rowptr[hw + 1];
    float rd = g_rdeg[hw];
    PDL_WAIT();   // g_c2 / g_xr2 from conv2 GEMM
    float acc = 0.f;
    for (; i + 1 < end; i += 2) {
        int sA = g_es[i], sB = g_es[i + 1];
        float pA = g_ep[i], pB = g_ep[i + 1];
        float2 vA = __bfloat1622float2(*reinterpret_cast<const __nv_bfloat162*>(g_c2 + (size_t)sA * 32 + 2 * c));
        float2 vB = __bfloat1622float2(*reinterpret_cast<const __nv_bfloat162*>(g_c2 + (size_t)sB * 32 + 2 * c));
        acc += fmaf(pA, vA.y - vA.x, vA.x) + fmaf(pB, vB.y - vB.x, vB.x);
    }
    if (i < end) {
        int s = g_es[i];
        float p = g_ep[i];
        float2 v = __bfloat1622float2(*reinterpret_cast<const __nv_bfloat162*>(g_c2 + (size_t)s * 32 + 2 * c));
        acc += fmaf(p, v.y - v.x, v.x);
    }
    float v = tanhf(fmaf(acc, rd, g_xr2[(size_t)hw * 16 + c]));
    float m = v;
    for (int o = 8; o > 0; o >>= 1) m = fmaxf(m, __shfl_xor_sync(0xffffffffu, m, o, 16));
    float e = expf(v - m);
    float s = e;
    for (int o = 8; o > 0; o >>= 1) s += __shfl_xor_sync(0xffffffffu, s, o, 16);
    out[(size_t)hw * 16 + c] = v - m - logf(s);
}

// ---------------- launch ----------------
extern "C" void kernel_launch(void* const* d_in, const int* in_sizes, int n_in,
                              void* d_out, int out_size) {
    const float* x  = (const float*)d_in[0];
    const float* ea = (const float*)d_in[1];
    const int*   src = (const int*)d_in[2];
    const int*   dst = (const int*)d_in[3];
    const float* W1 = (const float*)d_in[4];
    const float* R1 = (const float*)d_in[5];
    const float* b1 = (const float*)d_in[6];
    const float* Wa = (const float*)d_in[7];
    const float* Ra = (const float*)d_in[8];
    const float* ba = (const float*)d_in[9];
    const float* Wb = (const float*)d_in[10];
    const float* Rb = (const float*)d_in[11];
    const float* bb = (const float*)d_in[12];
    const float* W2 = (const float*)d_in[13];
    const float* R2 = (const float*)d_in[14];
    const float* b2 = (const float*)d_in[15];
    float* out = (float*)d_out;

    float *h, *B1, *B2, *xr1, *xr2;
    __nv_bfloat16 *hb, *midb, *curb, *c1, *c2, *Bh1t, *Bh2t;
    cudaGetSymbolAddress((void**)&h, g_h);
    cudaGetSymbolAddress((void**)&hb, g_hb);
    cudaGetSymbolAddress((void**)&midb, g_midb);
    cudaGetSymbolAddress((void**)&curb, g_curb);
    cudaGetSymbolAddress((void**)&B1, g_B1);
    cudaGetSymbolAddress((void**)&Bh1t, g_Bh1t);
    cudaGetSymbolAddress((void**)&Bh2t, g_Bh2t);
    cudaGetSymbolAddress((void**)&B2, g_B2);
    cudaGetSymbolAddress((void**)&c1, g_c1);
    cudaGetSymbolAddress((void**)&c2, g_c2);
    cudaGetSymbolAddress((void**)&xr1, g_xr1);
    cudaGetSymbolAddress((void**)&xr2, g_xr2);

    static cudaStream_t s2 = nullptr;
    static cudaEvent_t e1 = nullptr, e2 = nullptr;
    if (s2 == nullptr) {
        cudaStreamCreateWithFlags(&s2, cudaStreamNonBlocking);
        cudaEventCreateWithFlags(&e1, cudaEventDisableTiming);
        cudaEventCreateWithFlags(&e2, cudaEventDisableTiming);
    }

    cudaStream_t m = 0;

    // fork: CSR chain on side stream (zero -> count -> scan -> apply -> fill, PDL-chained)
    cudaEventRecord(e1, m);
    cudaStreamWaitEvent(s2, e1, 0);
    launch_pdl(NB_SCAN, 256, s2, k_zero);
    launch_pdl(N_EDGES / 256, 256, s2, k_count, dst);
    launch_pdl(NB_SCAN, 256, s2, k_bsum);
    launch_pdl(1, 256, s2, k_bscan);
    launch_pdl(NB_SCAN, 256, s2, k_bapply);
    launch_pdl(N_EDGES / 256, 256, s2, k_fill, src, dst, ea);
    cudaEventRecord(e2, s2);

    // main: weight concat -> conv1 GEMM (overlaps CSR chain)
    launch_pdl(192, 256, m, k_initW, W1, R1, Wa, Ra, Wb, Rb, W2, R2);
    launch_pdl(dim3(MG, 3), 256, m, k_mm<256, 192, 64, 0>, x, B1, b1, c1, xr1);

    // join: everything below needs both CSR and conv1 output
    cudaStreamWaitEvent(m, e2, 0);

    const int WG = (N_NODES * 32 + 255) / 256;
    const int HG = (N_NODES * 16 + 255) / 256;

    launch_pdl(WG, 256, m, k_agg1);

    // RK4: each stage = (preagg -> GEMM1) -> (preagg -> GEMM2 w/ RK epilogue), all PDL-chained
    auto fstep = [&](const __nv_bfloat16* inb, int stage, float curMul) {
        launch_pdl(WG, 256, m, k_preagg, inb);
        launch_pdl(MG, 256, m, k_hmm<1>, inb, Bh1t, ba, midb, 0, 0.f);
        launch_pdl(WG, 256, m, k_preagg, (const __nv_bfloat16*)midb);
        launch_pdl(MG, 256, m, k_hmm<2>, (const __nv_bfloat16*)midb, Bh2t, bb, curb, stage, curMul);
    };
    fstep(hb, 1, 1.5f);
    fstep(curb, 2, 1.5f);
    fstep(curb, 3, 3.0f);
    fstep(curb, 4, 0.f);

    // conv2 + log_softmax
    launch_pdl(dim3(MG, 1), 256, m, k_mm<64, 48, 48, 3>, (const float*)h, B2, b2, c2, xr2);
    launch_pdl(HG, 256, m, k_agg2_lsm, out);
}

// round 13
// speedup vs baseline: 1.4998x; 1.0269x over previous
#include <cuda_runtime.h>
#include <cuda_bf16.h>
#include <cstdint>

#define N_NODES 50000
#define N_EDGES 800000
#define F_IN 256
#define HID 64
#define NCLS 16
#define NB_SCAN 196   // ceil(50000/256)
#define MG 391        // ceil(50000/128)

// PDL: allow dependents to launch early; wait gates consumption of predecessor data.
#define PDL_TRIGGER() asm volatile("griddepcontrol.launch_dependents;" ::: "memory")
#define PDL_WAIT()    asm volatile("griddepcontrol.wait;" ::: "memory")

// ---------------- scratch ----------------
__device__ int   g_cnt[N_NODES];       // zero-initialized; re-zeroed by k_bapply each call
__device__ int   g_rowptr[N_NODES + 1];
__device__ int   g_cursor[N_NODES];
__device__ int   g_bsum[256];
__device__ int   g_es[N_EDGES];
__device__ float g_ep[N_EDGES];
__device__ float g_rdeg[N_NODES];

__device__ __align__(16) float g_h[(size_t)N_NODES * HID];     // fp32 ODE state
__device__ __align__(16) float g_acc[(size_t)N_NODES * HID];   // fp32 RK accumulator
__device__ __align__(16) __nv_bfloat16 g_hb[(size_t)N_NODES * HID];
__device__ __align__(16) __nv_bfloat16 g_midb[(size_t)N_NODES * HID];
__device__ __align__(16) __nv_bfloat16 g_curb[(size_t)N_NODES * HID];
__device__ __align__(16) __nv_bfloat16 g_Ypreb[(size_t)N_NODES * 128]; // [S0n|S1n] bf16
__device__ __align__(16) __nv_bfloat16 g_c1[(size_t)N_NODES * 128]; // interleaved y0/y1, conv1
__device__ __align__(16) float g_xr1[(size_t)N_NODES * HID];
__device__ __align__(16) __nv_bfloat16 g_c2[(size_t)N_NODES * 32];  // interleaved y0/y1, conv2
__device__ __align__(16) float g_xr2[(size_t)N_NODES * NCLS];
// concatenated weights
__device__ __align__(16) float g_B1[256 * 192];            // fp32 cols [W1_0 | W1_1 | R1]
__device__ __align__(16) __nv_bfloat16 g_Bh1t[64 * 192];   // bf16 n-major: [Ra;Wa0;Wa1]^T
__device__ __align__(16) __nv_bfloat16 g_Bh2t[64 * 192];   // bf16 n-major: [Rb;Wb0;Wb1]^T
__device__ __align__(16) float g_B2[64 * 48];              // fp32 cols [W2_0 | W2_1 | R2]

// ---------------- mma helpers ----------------
__device__ __forceinline__ unsigned f2tf(float f) {
    unsigned r; asm("cvt.rna.tf32.f32 %0, %1;" : "=r"(r) : "f"(f)); return r;
}
__device__ __forceinline__ void mma_tf32(float* d, const unsigned* a, const unsigned* b) {
    asm volatile("mma.sync.aligned.m16n8k8.row.col.f32.tf32.tf32.f32 "
        "{%0,%1,%2,%3}, {%4,%5,%6,%7}, {%8,%9}, {%0,%1,%2,%3};"
        : "+f"(d[0]), "+f"(d[1]), "+f"(d[2]), "+f"(d[3])
        : "r"(a[0]), "r"(a[1]), "r"(a[2]), "r"(a[3]), "r"(b[0]), "r"(b[1]));
}
__device__ __forceinline__ void mma_bf16(float* d, const unsigned* a, const unsigned* b) {
    asm volatile("mma.sync.aligned.m16n8k16.row.col.f32.bf16.bf16.f32 "
        "{%0,%1,%2,%3}, {%4,%5,%6,%7}, {%8,%9}, {%0,%1,%2,%3};"
        : "+f"(d[0]), "+f"(d[1]), "+f"(d[2]), "+f"(d[3])
        : "r"(a[0]), "r"(a[1]), "r"(a[2]), "r"(a[3]), "r"(b[0]), "r"(b[1]));
}

// ---------------- PDL launch helper ----------------
template <typename... P, typename... A>
static inline void launch_pdl(dim3 g, dim3 b, cudaStream_t st, void (*k)(P...), A... args) {
    cudaLaunchConfig_t cfg = {};
    cfg.gridDim = g; cfg.blockDim = b; cfg.dynamicSmemBytes = 0; cfg.stream = st;
    cudaLaunchAttribute at[1];
    at[0].id = cudaLaunchAttributeProgrammaticStreamSerialization;
    at[0].val.programmaticStreamSerializationAllowed = 1;
    cfg.attrs = at; cfg.numAttrs = 1;
    cudaLaunchKernelEx(&cfg, k, static_cast<P>(args)...);
}

// ---------------- init: concatenate weights (main stream) ----------------
__global__ void k_initW(const float* __restrict__ W1, const float* __restrict__ R1,
                        const float* __restrict__ Wa, const float* __restrict__ Ra,
                        const float* __restrict__ Wb, const float* __restrict__ Rb,
                        const float* __restrict__ W2, const float* __restrict__ R2) {
    PDL_TRIGGER();
    int i = blockIdx.x * 256 + threadIdx.x;
    if (i < 256 * 192) {   // B1[k][n] fp32
        int k = i / 192, n = i % 192;
        float v;
        if (n < 64)       v = W1[k * 64 + n];
        else if (n < 128) v = W1[256 * 64 + k * 64 + (n - 64)];
        else              v = R1[k * 64 + (n - 128)];
        g_B1[i] = v;
    }
    if (i < 64 * 192) {    // Bh1t/Bh2t[n][k] bf16
        int n = i / 192, k = i % 192;
        float va, vb;
        if (k < 64)       { va = Ra[k * 64 + n];                   vb = Rb[k * 64 + n]; }
        else if (k < 128) { va = Wa[(k - 64) * 64 + n];            vb = Wb[(k - 64) * 64 + n]; }
        else              { va = Wa[64 * 64 + (k - 128) * 64 + n]; vb = Wb[64 * 64 + (k - 128) * 64 + n]; }
        g_Bh1t[i] = __float2bfloat16(va);
        g_Bh2t[i] = __float2bfloat16(vb);
    }
    if (i < 64 * 48) {     // B2[k][n] fp32
        int k = i / 48, n = i % 48;
        float v;
        if (n < 16)      v = W2[k * 16 + n];
        else if (n < 32) v = W2[64 * 16 + k * 16 + (n - 16)];
        else             v = R2[k * 16 + (n - 32)];
        g_B2[i] = v;
    }
}

// ---------------- CSR build (side stream, PDL chained) ----------------
__global__ void k_count(const int* __restrict__ dst) {
    PDL_TRIGGER();
    int e = blockIdx.x * blockDim.x + threadIdx.x;
    int d = (e < N_EDGES) ? dst[e] : -1;
    PDL_WAIT();
    if (e < N_EDGES) atomicAdd(&g_cnt[d], 1);
}
__global__ void k_bsum() {
    PDL_TRIGGER();
    __shared__ int ss[256];
    int t = threadIdx.x;
    int idx = blockIdx.x * 256 + t;
    PDL_WAIT();
    ss[t] = (idx < N_NODES) ? g_cnt[idx] : 0;
    __syncthreads();
    for (int off = 128; off > 0; off >>= 1) {
        if (t < off) ss[t] += ss[t + off];
        __syncthreads();
    }
    if (t == 0) g_bsum[blockIdx.x] = ss[0];
}
// bapply: inline exclusive prefix of block sums + block scan + cnt reset
__global__ void k_bapply() {
    PDL_TRIGGER();
    __shared__ int ss[256];
    __shared__ int s_boff;
    int t = threadIdx.x;
    int idx = blockIdx.x * 256 + t;
    PDL_WAIT();
    int pv = (t < (int)blockIdx.x) ? g_bsum[t] : 0;   // blockIdx.x <= 195 < 256
    ss[t] = pv;
    __syncthreads();
    for (int off = 128; off > 0; off >>= 1) {
        if (t < off) ss[t] += ss[t + off];
        __syncthreads();
    }
    if (t == 0) s_boff = ss[0];
    __syncthreads();
    int v = (idx < N_NODES) ? g_cnt[idx] : 0;
    if (idx < N_NODES) g_cnt[idx] = 0;                // reset for next call (zero-init covers call 1)
    ss[t] = v;
    __syncthreads();
    for (int off = 1; off < 256; off <<= 1) {
        int u = (t >= off) ? ss[t - off] : 0;
        __syncthreads();
        ss[t] += u;
        __syncthreads();
    }
    if (idx < N_NODES) {
        int base = s_boff + ss[t] - v;
        g_rowptr[idx] = base;
        g_cursor[idx] = base;
        g_rdeg[idx] = 1.0f / (float)(v > 0 ? v : 1);
        if (idx == N_NODES - 1) g_rowptr[N_NODES] = base + v;
    }
}
__global__ void k_fill(const int* __restrict__ src, const int* __restrict__ dst,
                       const float* __restrict__ ea) {
    PDL_TRIGGER();
    int e = blockIdx.x * blockDim.x + threadIdx.x;
    int s = 0, d = 0; float p = 0.f;
    if (e < N_EDGES) { s = src[e]; d = dst[e]; p = ea[e]; }
    PDL_WAIT();
    if (e < N_EDGES) {
        int pos = atomicAdd(&g_cursor[d], 1);
        g_es[pos] = s;
        g_ep[pos] = p;
    }
}

// ---------------- tf32 GEMM (conv1/conv2), EPI: 0=conv1, 3=conv2 ----------------
template <int K, int NTOT, int BN, int EPI>
__global__ void __launch_bounds__(256) k_mm(const float* __restrict__ A,
                                            const float* __restrict__ B,
                                            const float* __restrict__ bias,
                                            __nv_bfloat16* __restrict__ Cb,
                                            float* __restrict__ aux) {
    PDL_TRIGGER();
    __shared__ unsigned As[128][36];
    __shared__ unsigned Bs[32][BN + 8];

    constexpr int BM = 128, BK = 32;
    constexpr int WN = BN / 2, NF = WN / 8;
    const int tid = threadIdx.x;
    const int lane = tid & 31, warp = tid >> 5;
    const int wm = warp & 3, wn = warp >> 2;
    const int mBase = blockIdx.x * BM;
    const int nBase = blockIdx.y * BN;
    const int g = lane >> 2, t = lane & 3;

    float acc[2][NF][4];
#pragma unroll
    for (int mf = 0; mf < 2; ++mf)
#pragma unroll
        for (int nf = 0; nf < NF; ++nf)
#pragma unroll
            for (int q = 0; q < 4; ++q) acc[mf][nf][q] = 0.f;

    const int ar = tid >> 3, ac = (tid & 7) * 4;
    PDL_WAIT();   // conv1: B1 from k_initW; conv2: g_h from last k_hmm

    for (int k0 = 0; k0 < K; k0 += BK) {
#pragma unroll
        for (int p = 0; p < 4; ++p) {
            int row = p * 32 + ar;
            int gm = mBase + row;
            float4 v = make_float4(0.f, 0.f, 0.f, 0.f);
            if (gm < N_NODES) v = *reinterpret_cast<const float4*>(A + (size_t)gm * K + k0 + ac);
            unsigned* s = &As[row][ac];
            s[0] = f2tf(v.x); s[1] = f2tf(v.y); s[2] = f2tf(v.z); s[3] = f2tf(v.w);
        }
        for (int i = tid; i < BK * BN / 4; i += 256) {
            int bk = i / (BN / 4), bc = (i % (BN / 4)) * 4;
            float4 v = *reinterpret_cast<const float4*>(B + (size_t)(k0 + bk) * NTOT + nBase + bc);
            unsigned* s = &Bs[bk][bc];
            s[0] = f2tf(v.x); s[1] = f2tf(v.y); s[2] = f2tf(v.z); s[3] = f2tf(v.w);
        }
        __syncthreads();
#pragma unroll
        for (int kk = 0; kk < BK / 8; ++kk) {
            const int kb = kk * 8;
            unsigned a[2][4];
#pragma unroll
            for (int mf = 0; mf < 2; ++mf) {
                int r = wm * 32 + mf * 16;
                a[mf][0] = As[r + g][kb + t];
                a[mf][1] = As[r + g + 8][kb + t];
                a[mf][2] = As[r + g][kb + t + 4];
                a[mf][3] = As[r + g + 8][kb + t + 4];
            }
#pragma unroll
            for (int nf = 0; nf < NF; ++nf) {
                int n = wn * WN + nf * 8;
                unsigned b[2] = { Bs[kb + t][n + g], Bs[kb + t + 4][n + g] };
                mma_tf32(acc[0][nf], a[0], b);
                mma_tf32(acc[1][nf], a[1], b);
            }
        }
        __syncthreads();
    }

    const int by = blockIdx.y;
    auto emit = [&](int row, int col, float a0, float a1) {
        if (row >= N_NODES) return;
        if (EPI == 0) {
            int c = col - (by << 6);
            if (by < 2) {
                Cb[(size_t)row * 128 + 2 * c + by]       = __float2bfloat16(a0);
                Cb[(size_t)row * 128 + 2 * (c + 1) + by] = __float2bfloat16(a1);
            } else {
                *reinterpret_cast<float2*>(aux + (size_t)row * 64 + c) =
                    make_float2(a0 + bias[c], a1 + bias[c + 1]);
            }
        } else {  // EPI == 3 (conv2)
            if (col < 32) {
                int sec = col >> 4, c = col & 15;
                Cb[(size_t)row * 32 + 2 * c + sec]       = __float2bfloat16(a0);
                Cb[(size_t)row * 32 + 2 * (c + 1) + sec] = __float2bfloat16(a1);
            } else {
                *reinterpret_cast<float2*>(aux + (size_t)row * 16 + (col - 32)) =
                    make_float2(a0 + bias[col - 32], a1 + bias[col - 31]);
            }
        }
    };

#pragma unroll
    for (int mf = 0; mf < 2; ++mf)
#pragma unroll
        for (int nf = 0; nf < NF; ++nf) {
            int row = mBase + wm * 32 + mf * 16 + g;
            int col = nBase + wn * WN + nf * 8 + 2 * t;
            emit(row, col, acc[mf][nf][0], acc[mf][nf][1]);
            emit(row + 8, col, acc[mf][nf][2], acc[mf][nf][3]);
        }
}

// ---------------- hidden pre-aggregation: warp/node, bf16 gather x8 -> bf16 [S0n|S1n] ----------------
__global__ void __launch_bounds__(256) k_preagg(const __nv_bfloat16* __restrict__ inb) {
    PDL_TRIGGER();
    int w = (blockIdx.x * 256 + threadIdx.x) >> 5;
    int lane = threadIdx.x & 31;
    if (w >= N_NODES) { PDL_WAIT(); return; }
    int i = g_rowptr[w], end = g_rowptr[w + 1];
    float rd = g_rdeg[w];
    PDL_WAIT();   // features (inb) from predecessor
    float sa0 = 0.f, sa1 = 0.f, sp0 = 0.f, sp1 = 0.f;
    for (; i + 7 < end; i += 8) {
        int   si[8]; float pi[8]; float2 xi[8];
#pragma unroll
        for (int q = 0; q < 8; ++q) { si[q] = g_es[i + q]; pi[q] = g_ep[i + q]; }
#pragma unroll
        for (int q = 0; q < 8; ++q)
            xi[q] = __bfloat1622float2(*reinterpret_cast<const __nv_bfloat162*>(inb + (size_t)si[q] * 64 + 2 * lane));
#pragma unroll
        for (int q = 0; q < 8; ++q) {
            sa0 += xi[q].x;
            sa1 += xi[q].y;
            sp0 = fmaf(pi[q], xi[q].x, sp0);
            sp1 = fmaf(pi[q], xi[q].y, sp1);
        }
    }
    for (; i < end; ++i) {
        int s = g_es[i];
        float p = g_ep[i];
        float2 xv = __bfloat1622float2(*reinterpret_cast<const __nv_bfloat162*>(inb + (size_t)s * 64 + 2 * lane));
        sa0 += xv.x; sa1 += xv.y;
        sp0 = fmaf(p, xv.x, sp0);
        sp1 = fmaf(p, xv.y, sp1);
    }
    __nv_bfloat16* yr = g_Ypreb + (size_t)w * 128;
    *reinterpret_cast<__nv_bfloat162*>(yr + 2 * lane) =
        __float22bfloat162_rn(make_float2((sa0 - sp0) * rd, (sa1 - sp1) * rd));
    *reinterpret_cast<__nv_bfloat162*>(yr + 64 + 2 * lane) =
        __float22bfloat162_rn(make_float2(sp0 * rd, sp1 * rd));
}

// ---------------- hidden GEMM (bf16 mma): A=[inb | Ypreb], Bt n-major bf16, K=192 ----------------
// EPI: 1 = write midb (bf16), 2 = RK stage epilogue
template <int EPI>
__global__ void __launch_bounds__(256) k_hmm(const __nv_bfloat16* __restrict__ inb,
                                             const __nv_bfloat16* __restrict__ Bt,
                                             const float* __restrict__ bias,
                                             __nv_bfloat16* __restrict__ outb,
                                             int estage, float curMul) {
    PDL_TRIGGER();
    __shared__ __nv_bfloat16 Asm[128][72];
    __shared__ __nv_bfloat16 Bsm[64][200];

    const int tid = threadIdx.x;
    const int lane = tid & 31, warp = tid >> 5;
    const int wm = warp & 3, wn = warp >> 2;
    const int mBase = blockIdx.x * 128;
    const int g = lane >> 2, t = lane & 3;

    for (int i = tid; i < 64 * 192 / 8; i += 256) {
        int n = i / 24, c8 = (i % 24) * 8;
        *reinterpret_cast<uint4*>(&Bsm[n][c8]) = *reinterpret_cast<const uint4*>(Bt + n * 192 + c8);
    }

    float acc[2][4][4];
#pragma unroll
    for (int mf = 0; mf < 2; ++mf)
#pragma unroll
        for (int nf = 0; nf < 4; ++nf)
#pragma unroll
            for (int q = 0; q < 4; ++q) acc[mf][nf][q] = 0.f;

    PDL_WAIT();

#pragma unroll
    for (int chunk = 0; chunk < 3; ++chunk) {
#pragma unroll
        for (int i2 = 0; i2 < 4; ++i2) {
            int i = i2 * 256 + tid;
            int row = i >> 3, c8 = (i & 7) * 8;
            int gm = mBase + row;
            uint4 v = make_uint4(0, 0, 0, 0);
            if (gm < N_NODES) {
                if (chunk == 0) v = *reinterpret_cast<const uint4*>(inb + (size_t)gm * 64 + c8);
                else            v = *reinterpret_cast<const uint4*>(g_Ypreb + (size_t)gm * 128 + (chunk - 1) * 64 + c8);
            }
            *reinterpret_cast<uint4*>(&Asm[row][c8]) = v;
        }
        __syncthreads();
#pragma unroll
        for (int kk = 0; kk < 4; ++kk) {
            const int kb = kk * 16;
            unsigned a[2][4];
#pragma unroll
            for (int mf = 0; mf < 2; ++mf) {
                int r = wm * 32 + mf * 16;
                a[mf][0] = *reinterpret_cast<const unsigned*>(&Asm[r + g][kb + 2 * t]);
                a[mf][1] = *reinterpret_cast<const unsigned*>(&Asm[r + g + 8][kb + 2 * t]);
                a[mf][2] = *reinterpret_cast<const unsigned*>(&Asm[r + g][kb + 2 * t + 8]);
                a[mf][3] = *reinterpret_cast<const unsigned*>(&Asm[r + g + 8][kb + 2 * t + 8]);
            }
#pragma unroll
            for (int nf = 0; nf < 4; ++nf) {
                int n = wn * 32 + nf * 8;
                unsigned b[2] = {
                    *reinterpret_cast<const unsigned*>(&Bsm[n + g][chunk * 64 + kb + 2 * t]),
                    *reinterpret_cast<const unsigned*>(&Bsm[n + g][chunk * 64 + kb + 2 * t + 8])
                };
                mma_bf16(acc[0][nf], a[0], b);
                mma_bf16(acc[1][nf], a[1], b);
            }
        }
        __syncthreads();
    }

    auto emit = [&](int row, int col, float a0, float a1) {
        if (row >= N_NODES) return;
        float2 kv = make_float2(a0 + bias[col], a1 + bias[col + 1]);
        size_t idx = (size_t)row * 64 + col;
        if (EPI == 1) {
            *reinterpret_cast<__nv_bfloat162*>(outb + idx) = __float22bfloat162_rn(kv);
        } else {
            float2 h2 = *reinterpret_cast<const float2*>(g_h + idx);
            if (estage == 4) {
                float2 a2 = *reinterpret_cast<const float2*>(g_acc + idx);
                *reinterpret_cast<float2*>(g_h + idx) =
                    make_float2(h2.x + 0.5f * (a2.x + kv.x), h2.y + 0.5f * (a2.y + kv.y));
            } else {
                float2 a2;
                if (estage == 1) a2 = kv;
                else {
                    a2 = *reinterpret_cast<const float2*>(g_acc + idx);
                    a2.x = fmaf(2.f, kv.x, a2.x); a2.y = fmaf(2.f, kv.y, a2.y);
                }
                *reinterpret_cast<float2*>(g_acc + idx) = a2;
                float2 c2 = make_float2(fmaf(curMul, kv.x, h2.x), fmaf(curMul, kv.y, h2.y));
                *reinterpret_cast<__nv_bfloat162*>(outb + idx) = __float22bfloat162_rn(c2);
            }
        }
    };

#pragma unroll
    for (int mf = 0; mf < 2; ++mf)
#pragma unroll
        for (int nf = 0; nf < 4; ++nf) {
            int row = mBase + wm * 32 + mf * 16 + g;
            int col = wn * 32 + nf * 8 + 2 * t;
            emit(row, col, acc[mf][nf][0], acc[mf][nf][1]);
            emit(row + 8, col, acc[mf][nf][2], acc[mf][nf][3]);
        }
}

// ---------------- conv1 aggregation: warp/node, bf16 interleaved gather x4, tanh ----------------
__global__ void __launch_bounds__(256) k_agg1() {
    PDL_TRIGGER();
    int w = (blockIdx.x * 256 + threadIdx.x) >> 5;
    int lane = threadIdx.x & 31;
    if (w >= N_NODES) { PDL_WAIT(); return; }
    int i = g_rowptr[w], end = g_rowptr[w + 1];
    float rd = g_rdeg[w];
    PDL_WAIT();   // g_c1 / g_xr1 from conv1 GEMM
    float a0 = 0.f, a1 = 0.f;
    for (; i + 3 < end; i += 4) {
        int s0 = g_es[i], s1 = g_es[i + 1], s2 = g_es[i + 2], s3 = g_es[i + 3];
        float p0 = g_ep[i], p1 = g_ep[i + 1], p2 = g_ep[i + 2], p3 = g_ep[i + 3];
        uint2 u0 = *reinterpret_cast<const uint2*>(g_c1 + (size_t)s0 * 128 + 4 * lane);
        uint2 u1 = *reinterpret_cast<const uint2*>(g_c1 + (size_t)s1 * 128 + 4 * lane);
        uint2 u2 = *reinterpret_cast<const uint2*>(g_c1 + (size_t)s2 * 128 + 4 * lane);
        uint2 u3 = *reinterpret_cast<const uint2*>(g_c1 + (size_t)s3 * 128 + 4 * lane);
        float2 w00 = __bfloat1622float2(*reinterpret_cast<__nv_bfloat162*>(&u0.x));
        float2 w01 = __bfloat1622float2(*reinterpret_cast<__nv_bfloat162*>(&u0.y));
        float2 w10 = __bfloat1622float2(*reinterpret_cast<__nv_bfloat162*>(&u1.x));
        float2 w11 = __bfloat1622float2(*reinterpret_cast<__nv_bfloat162*>(&u1.y));
        float2 w20 = __bfloat1622float2(*reinterpret_cast<__nv_bfloat162*>(&u2.x));
        float2 w21 = __bfloat1622float2(*reinterpret_cast<__nv_bfloat162*>(&u2.y));
        float2 w30 = __bfloat1622float2(*reinterpret_cast<__nv_bfloat162*>(&u3.x));
        float2 w31 = __bfloat1622float2(*reinterpret_cast<__nv_bfloat162*>(&u3.y));
        a0 += fmaf(p0, w00.y - w00.x, w00.x) + fmaf(p1, w10.y - w10.x, w10.x)
            + fmaf(p2, w20.y - w20.x, w20.x) + fmaf(p3, w30.y - w30.x, w30.x);
        a1 += fmaf(p0, w01.y - w01.x, w01.x) + fmaf(p1, w11.y - w11.x, w11.x)
            + fmaf(p2, w21.y - w21.x, w21.x) + fmaf(p3, w31.y - w31.x, w31.x);
    }
    for (; i < end; ++i) {
        int s = g_es[i];
        float p = g_ep[i];
        uint2 u = *reinterpret_cast<const uint2*>(g_c1 + (size_t)s * 128 + 4 * lane);
        float2 v0 = __bfloat1622float2(*reinterpret_cast<__nv_bfloat162*>(&u.x));
        float2 v1 = __bfloat1622float2(*reinterpret_cast<__nv_bfloat162*>(&u.y));
        a0 += fmaf(p, v0.y - v0.x, v0.x);
        a1 += fmaf(p, v1.y - v1.x, v1.x);
    }
    float2 xr = *reinterpret_cast<const float2*>(g_xr1 + (size_t)w * 64 + 2 * lane);
    float2 hv = make_float2(tanhf(fmaf(a0, rd, xr.x)), tanhf(fmaf(a1, rd, xr.y)));
    *reinterpret_cast<float2*>(g_h + (size_t)w * 64 + 2 * lane) = hv;
    *reinterpret_cast<__nv_bfloat162*>(g_hb + (size_t)w * 64 + 2 * lane) = __float22bfloat162_rn(hv);
}

// ---------------- conv2 aggregation + log_softmax (half-warp/node) ----------------
__global__ void __launch_bounds__(256) k_agg2_lsm(float* __restrict__ out) {
    PDL_TRIGGER();
    int hw = (blockIdx.x * 256 + threadIdx.x) >> 4;
    int c = threadIdx.x & 15;
    if (hw >= N_NODES) { PDL_WAIT(); return; }
    int i = g_rowptr[hw], end = g_rowptr[hw + 1];
    float rd = g_rdeg[hw];
    PDL_WAIT();   // g_c2 / g_xr2 from conv2 GEMM
    float acc = 0.f;
    for (; i + 1 < end; i += 2) {
        int sA = g_es[i], sB = g_es[i + 1];
        float pA = g_ep[i], pB = g_ep[i + 1];
        float2 vA = __bfloat1622float2(*reinterpret_cast<const __nv_bfloat162*>(g_c2 + (size_t)sA * 32 + 2 * c));
        float2 vB = __bfloat1622float2(*reinterpret_cast<const __nv_bfloat162*>(g_c2 + (size_t)sB * 32 + 2 * c));
        acc += fmaf(pA, vA.y - vA.x, vA.x) + fmaf(pB, vB.y - vB.x, vB.x);
    }
    if (i < end) {
        int s = g_es[i];
        float p = g_ep[i];
        float2 v = __bfloat1622float2(*reinterpret_cast<const __nv_bfloat162*>(g_c2 + (size_t)s * 32 + 2 * c));
        acc += fmaf(p, v.y - v.x, v.x);
    }
    float v = tanhf(fmaf(acc, rd, g_xr2[(size_t)hw * 16 + c]));
    float m = v;
    for (int o = 8; o > 0; o >>= 1) m = fmaxf(m, __shfl_xor_sync(0xffffffffu, m, o, 16));
    float e = expf(v - m);
    float s = e;
    for (int o = 8; o > 0; o >>= 1) s += __shfl_xor_sync(0xffffffffu, s, o, 16);
    out[(size_t)hw * 16 + c] = v - m - logf(s);
}

// ---------------- launch ----------------
extern "C" void kernel_launch(void* const* d_in, const int* in_sizes, int n_in,
                              void* d_out, int out_size) {
    const float* x  = (const float*)d_in[0];
    const float* ea = (const float*)d_in[1];
    const int*   src = (const int*)d_in[2];
    const int*   dst = (const int*)d_in[3];
    const float* W1 = (const float*)d_in[4];
    const float* R1 = (const float*)d_in[5];
    const float* b1 = (const float*)d_in[6];
    const float* Wa = (const float*)d_in[7];
    const float* Ra = (const float*)d_in[8];
    const float* ba = (const float*)d_in[9];
    const float* Wb = (const float*)d_in[10];
    const float* Rb = (const float*)d_in[11];
    const float* bb = (const float*)d_in[12];
    const float* W2 = (const float*)d_in[13];
    const float* R2 = (const float*)d_in[14];
    const float* b2 = (const float*)d_in[15];
    float* out = (float*)d_out;

    float *h, *B1, *B2, *xr1, *xr2;
    __nv_bfloat16 *hb, *midb, *curb, *c1, *c2, *Bh1t, *Bh2t;
    cudaGetSymbolAddress((void**)&h, g_h);
    cudaGetSymbolAddress((void**)&hb, g_hb);
    cudaGetSymbolAddress((void**)&midb, g_midb);
    cudaGetSymbolAddress((void**)&curb, g_curb);
    cudaGetSymbolAddress((void**)&B1, g_B1);
    cudaGetSymbolAddress((void**)&Bh1t, g_Bh1t);
    cudaGetSymbolAddress((void**)&Bh2t, g_Bh2t);
    cudaGetSymbolAddress((void**)&B2, g_B2);
    cudaGetSymbolAddress((void**)&c1, g_c1);
    cudaGetSymbolAddress((void**)&c2, g_c2);
    cudaGetSymbolAddress((void**)&xr1, g_xr1);
    cudaGetSymbolAddress((void**)&xr2, g_xr2);

    static cudaStream_t s2 = nullptr;
    static cudaEvent_t e1 = nullptr, e2 = nullptr;
    if (s2 == nullptr) {
        cudaStreamCreateWithFlags(&s2, cudaStreamNonBlocking);
        cudaEventCreateWithFlags(&e1, cudaEventDisableTiming);
        cudaEventCreateWithFlags(&e2, cudaEventDisableTiming);
    }

    cudaStream_t m = 0;

    // fork: CSR chain on side stream (count -> bsum -> bapply[+scan+reset] -> fill)
    cudaEventRecord(e1, m);
    cudaStreamWaitEvent(s2, e1, 0);
    launch_pdl(N_EDGES / 256, 256, s2, k_count, dst);
    launch_pdl(NB_SCAN, 256, s2, k_bsum);
    launch_pdl(NB_SCAN, 256, s2, k_bapply);
    launch_pdl(N_EDGES / 256, 256, s2, k_fill, src, dst, ea);
    cudaEventRecord(e2, s2);

    // main: weight concat -> conv1 tf32 GEMM (overlaps CSR chain)
    launch_pdl(192, 256, m, k_initW, W1, R1, Wa, Ra, Wb, Rb, W2, R2);
    launch_pdl(dim3(MG, 3), 256, m, k_mm<256, 192, 64, 0>, x, (const float*)B1, b1, c1, xr1);

    // join
    cudaStreamWaitEvent(m, e2, 0);

    const int WG = (N_NODES * 32 + 255) / 256;
    const int HG = (N_NODES * 16 + 255) / 256;

    launch_pdl(WG, 256, m, k_agg1);

    // RK4 stages (PDL-chained)
    auto fstep = [&](const __nv_bfloat16* inb, int stage, float curMul) {
        launch_pdl(WG, 256, m, k_preagg, inb);
        launch_pdl(MG, 256, m, k_hmm<1>, inb, Bh1t, ba, midb, 0, 0.f);
        launch_pdl(WG, 256, m, k_preagg, (const __nv_bfloat16*)midb);
        launch_pdl(MG, 256, m, k_hmm<2>, (const __nv_bfloat16*)midb, Bh2t, bb, curb, stage, curMul);
    };
    fstep(hb, 1, 1.5f);
    fstep(curb, 2, 1.5f);
    fstep(curb, 3, 3.0f);
    fstep(curb, 4, 0.f);

    // conv2 + log_softmax
    launch_pdl(dim3(MG, 1), 256, m, k_mm<64, 48, 48, 3>, (const float*)h, (const float*)B2, b2, c2, xr2);
    launch_pdl(HG, 256, m, k_agg2_lsm, out);
}

// round 14
// speedup vs baseline: 1.5017x; 1.0012x over previous
#include <cuda_runtime.h>
#include <cuda_bf16.h>
#include <cstdint>

#define N_NODES 50000
#define N_EDGES 800000
#define F_IN 256
#define HID 64
#define NCLS 16
#define NB_SCAN 196   // ceil(50000/256)
#define MG 391        // ceil(50000/128)

// PDL: allow dependents to launch early; wait gates consumption of predecessor data.
#define PDL_TRIGGER() asm volatile("griddepcontrol.launch_dependents;" ::: "memory")
#define PDL_WAIT()    asm volatile("griddepcontrol.wait;" ::: "memory")

// ---------------- scratch ----------------
__device__ int   g_cnt[N_NODES];       // zero-initialized; re-zeroed by k_bapply each call
__device__ int   g_rowptr[N_NODES + 1];
__device__ int   g_cursor[N_NODES];
__device__ int   g_bsum[256];
__device__ int   g_es[N_EDGES];
__device__ float g_ep[N_EDGES];
__device__ float g_rdeg[N_NODES];

__device__ __align__(16) float g_h[(size_t)N_NODES * HID];     // fp32 ODE state
__device__ __align__(16) float g_acc[(size_t)N_NODES * HID];   // fp32 RK accumulator
__device__ __align__(16) __nv_bfloat16 g_hb[(size_t)N_NODES * HID];
__device__ __align__(16) __nv_bfloat16 g_midb[(size_t)N_NODES * HID];
__device__ __align__(16) __nv_bfloat16 g_curb[(size_t)N_NODES * HID];
__device__ __align__(16) __nv_bfloat16 g_Ypreb[(size_t)N_NODES * 128]; // [S0n|S1n] bf16
__device__ __align__(16) __nv_bfloat16 g_c1[(size_t)N_NODES * 128]; // interleaved y0/y1, conv1
__device__ __align__(16) float g_xr1[(size_t)N_NODES * HID];
__device__ __align__(16) __nv_bfloat16 g_c2[(size_t)N_NODES * 32];  // interleaved y0/y1, conv2
__device__ __align__(16) float g_xr2[(size_t)N_NODES * NCLS];
// concatenated weights
__device__ __align__(16) float g_B1[256 * 192];            // fp32 cols [W1_0 | W1_1 | R1]
__device__ __align__(16) __nv_bfloat16 g_Bh1t[64 * 192];   // bf16 n-major: [Ra;Wa0;Wa1]^T
__device__ __align__(16) __nv_bfloat16 g_Bh2t[64 * 192];   // bf16 n-major: [Rb;Wb0;Wb1]^T
__device__ __align__(16) float g_B2[64 * 48];              // fp32 cols [W2_0 | W2_1 | R2]

// ---------------- mma helpers ----------------
__device__ __forceinline__ unsigned f2tf(float f) {
    unsigned r; asm("cvt.rna.tf32.f32 %0, %1;" : "=r"(r) : "f"(f)); return r;
}
__device__ __forceinline__ void mma_tf32(float* d, const unsigned* a, const unsigned* b) {
    asm volatile("mma.sync.aligned.m16n8k8.row.col.f32.tf32.tf32.f32 "
        "{%0,%1,%2,%3}, {%4,%5,%6,%7}, {%8,%9}, {%0,%1,%2,%3};"
        : "+f"(d[0]), "+f"(d[1]), "+f"(d[2]), "+f"(d[3])
        : "r"(a[0]), "r"(a[1]), "r"(a[2]), "r"(a[3]), "r"(b[0]), "r"(b[1]));
}
__device__ __forceinline__ void mma_bf16(float* d, const unsigned* a, const unsigned* b) {
    asm volatile("mma.sync.aligned.m16n8k16.row.col.f32.bf16.bf16.f32 "
        "{%0,%1,%2,%3}, {%4,%5,%6,%7}, {%8,%9}, {%0,%1,%2,%3};"
        : "+f"(d[0]), "+f"(d[1]), "+f"(d[2]), "+f"(d[3])
        : "r"(a[0]), "r"(a[1]), "r"(a[2]), "r"(a[3]), "r"(b[0]), "r"(b[1]));
}

// ---------------- PDL launch helper ----------------
template <typename... P, typename... A>
static inline void launch_pdl(dim3 g, dim3 b, cudaStream_t st, void (*k)(P...), A... args) {
    cudaLaunchConfig_t cfg = {};
    cfg.gridDim = g; cfg.blockDim = b; cfg.dynamicSmemBytes = 0; cfg.stream = st;
    cudaLaunchAttribute at[1];
    at[0].id = cudaLaunchAttributeProgrammaticStreamSerialization;
    at[0].val.programmaticStreamSerializationAllowed = 1;
    cfg.attrs = at; cfg.numAttrs = 1;
    cudaLaunchKernelEx(&cfg, k, static_cast<P>(args)...);
}

// ---------------- init: concatenate weights (main stream) ----------------
__global__ void k_initW(const float* __restrict__ W1, const float* __restrict__ R1,
                        const float* __restrict__ Wa, const float* __restrict__ Ra,
                        const float* __restrict__ Wb, const float* __restrict__ Rb,
                        const float* __restrict__ W2, const float* __restrict__ R2) {
    PDL_TRIGGER();
    int i = blockIdx.x * 256 + threadIdx.x;
    if (i < 256 * 192) {   // B1[k][n] fp32
        int k = i / 192, n = i % 192;
        float v;
        if (n < 64)       v = W1[k * 64 + n];
        else if (n < 128) v = W1[256 * 64 + k * 64 + (n - 64)];
        else              v = R1[k * 64 + (n - 128)];
        g_B1[i] = v;
    }
    if (i < 64 * 192) {    // Bh1t/Bh2t[n][k] bf16
        int n = i / 192, k = i % 192;
        float va, vb;
        if (k < 64)       { va = Ra[k * 64 + n];                   vb = Rb[k * 64 + n]; }
        else if (k < 128) { va = Wa[(k - 64) * 64 + n];            vb = Wb[(k - 64) * 64 + n]; }
        else              { va = Wa[64 * 64 + (k - 128) * 64 + n]; vb = Wb[64 * 64 + (k - 128) * 64 + n]; }
        g_Bh1t[i] = __float2bfloat16(va);
        g_Bh2t[i] = __float2bfloat16(vb);
    }
    if (i < 64 * 48) {     // B2[k][n] fp32
        int k = i / 48, n = i % 48;
        float v;
        if (n < 16)      v = W2[k * 16 + n];
        else if (n < 32) v = W2[64 * 16 + k * 16 + (n - 16)];
        else             v = R2[k * 16 + (n - 32)];
        g_B2[i] = v;
    }
}

// ---------------- CSR build (side stream, PDL chained) ----------------
__global__ void k_count(const int* __restrict__ dst) {
    PDL_TRIGGER();
    int e = blockIdx.x * blockDim.x + threadIdx.x;
    int d = (e < N_EDGES) ? dst[e] : -1;
    PDL_WAIT();
    if (e < N_EDGES) atomicAdd(&g_cnt[d], 1);
}
__global__ void k_bsum() {
    PDL_TRIGGER();
    __shared__ int ss[256];
    int t = threadIdx.x;
    int idx = blockIdx.x * 256 + t;
    PDL_WAIT();
    ss[t] = (idx < N_NODES) ? g_cnt[idx] : 0;
    __syncthreads();
    for (int off = 128; off > 0; off >>= 1) {
        if (t < off) ss[t] += ss[t + off];
        __syncthreads();
    }
    if (t == 0) g_bsum[blockIdx.x] = ss[0];
}
// bapply: inline exclusive prefix of block sums + block scan + cnt reset
__global__ void k_bapply() {
    PDL_TRIGGER();
    __shared__ int ss[256];
    __shared__ int s_boff;
    int t = threadIdx.x;
    int idx = blockIdx.x * 256 + t;
    PDL_WAIT();
    int pv = (t < (int)blockIdx.x) ? g_bsum[t] : 0;   // blockIdx.x <= 195 < 256
    ss[t] = pv;
    __syncthreads();
    for (int off = 128; off > 0; off >>= 1) {
        if (t < off) ss[t] += ss[t + off];
        __syncthreads();
    }
    if (t == 0) s_boff = ss[0];
    __syncthreads();
    int v = (idx < N_NODES) ? g_cnt[idx] : 0;
    if (idx < N_NODES) g_cnt[idx] = 0;                // reset for next call (zero-init covers call 1)
    ss[t] = v;
    __syncthreads();
    for (int off = 1; off < 256; off <<= 1) {
        int u = (t >= off) ? ss[t - off] : 0;
        __syncthreads();
        ss[t] += u;
        __syncthreads();
    }
    if (idx < N_NODES) {
        int base = s_boff + ss[t] - v;
        g_rowptr[idx] = base;
        g_cursor[idx] = base;
        g_rdeg[idx] = 1.0f / (float)(v > 0 ? v : 1);
        if (idx == N_NODES - 1) g_rowptr[N_NODES] = base + v;
    }
}
__global__ void k_fill(const int* __restrict__ src, const int* __restrict__ dst,
                       const float* __restrict__ ea) {
    PDL_TRIGGER();
    int e = blockIdx.x * blockDim.x + threadIdx.x;
    int s = 0, d = 0; float p = 0.f;
    if (e < N_EDGES) { s = src[e]; d = dst[e]; p = ea[e]; }
    PDL_WAIT();
    if (e < N_EDGES) {
        int pos = atomicAdd(&g_cursor[d], 1);
        g_es[pos] = s;
        g_ep[pos] = p;
    }
}

// ---------------- tf32 GEMM (conv1/conv2), EPI: 0=conv1, 3=conv2 ----------------
template <int K, int NTOT, int BN, int EPI>
__global__ void __launch_bounds__(256) k_mm(const float* __restrict__ A,
                                            const float* __restrict__ B,
                                            const float* __restrict__ bias,
                                            __nv_bfloat16* __restrict__ Cb,
                                            float* __restrict__ aux) {
    PDL_TRIGGER();
    __shared__ unsigned As[128][36];
    __shared__ unsigned Bs[32][BN + 8];

    constexpr int BM = 128, BK = 32;
    constexpr int WN = BN / 2, NF = WN / 8;
    const int tid = threadIdx.x;
    const int lane = tid & 31, warp = tid >> 5;
    const int wm = warp & 3, wn = warp >> 2;
    const int mBase = blockIdx.x * BM;
    const int nBase = blockIdx.y * BN;
    const int g = lane >> 2, t = lane & 3;

    float acc[2][NF][4];
#pragma unroll
    for (int mf = 0; mf < 2; ++mf)
#pragma unroll
        for (int nf = 0; nf < NF; ++nf)
#pragma unroll
            for (int q = 0; q < 4; ++q) acc[mf][nf][q] = 0.f;

    const int ar = tid >> 3, ac = (tid & 7) * 4;
    PDL_WAIT();   // conv1: B1 from k_initW; conv2: g_h from last k_hmm

    for (int k0 = 0; k0 < K; k0 += BK) {
#pragma unroll
        for (int p = 0; p < 4; ++p) {
            int row = p * 32 + ar;
            int gm = mBase + row;
            float4 v = make_float4(0.f, 0.f, 0.f, 0.f);
            if (gm < N_NODES) v = *reinterpret_cast<const float4*>(A + (size_t)gm * K + k0 + ac);
            unsigned* s = &As[row][ac];
            s[0] = f2tf(v.x); s[1] = f2tf(v.y); s[2] = f2tf(v.z); s[3] = f2tf(v.w);
        }
        for (int i = tid; i < BK * BN / 4; i += 256) {
            int bk = i / (BN / 4), bc = (i % (BN / 4)) * 4;
            float4 v = *reinterpret_cast<const float4*>(B + (size_t)(k0 + bk) * NTOT + nBase + bc);
            unsigned* s = &Bs[bk][bc];
            s[0] = f2tf(v.x); s[1] = f2tf(v.y); s[2] = f2tf(v.z); s[3] = f2tf(v.w);
        }
        __syncthreads();
#pragma unroll
        for (int kk = 0; kk < BK / 8; ++kk) {
            const int kb = kk * 8;
            unsigned a[2][4];
#pragma unroll
            for (int mf = 0; mf < 2; ++mf) {
                int r = wm * 32 + mf * 16;
                a[mf][0] = As[r + g][kb + t];
                a[mf][1] = As[r + g + 8][kb + t];
                a[mf][2] = As[r + g][kb + t + 4];
                a[mf][3] = As[r + g + 8][kb + t + 4];
            }
#pragma unroll
            for (int nf = 0; nf < NF; ++nf) {
                int n = wn * WN + nf * 8;
                unsigned b[2] = { Bs[kb + t][n + g], Bs[kb + t + 4][n + g] };
                mma_tf32(acc[0][nf], a[0], b);
                mma_tf32(acc[1][nf], a[1], b);
            }
        }
        __syncthreads();
    }

    const int by = blockIdx.y;
    auto emit = [&](int row, int col, float a0, float a1) {
        if (row >= N_NODES) return;
        if (EPI == 0) {
            int c = col - (by << 6);
            if (by < 2) {
                Cb[(size_t)row * 128 + 2 * c + by]       = __float2bfloat16(a0);
                Cb[(size_t)row * 128 + 2 * (c + 1) + by] = __float2bfloat16(a1);
            } else {
                *reinterpret_cast<float2*>(aux + (size_t)row * 64 + c) =
                    make_float2(a0 + bias[c], a1 + bias[c + 1]);
            }
        } else {  // EPI == 3 (conv2)
            if (col < 32) {
                int sec = col >> 4, c = col & 15;
                Cb[(size_t)row * 32 + 2 * c + sec]       = __float2bfloat16(a0);
                Cb[(size_t)row * 32 + 2 * (c + 1) + sec] = __float2bfloat16(a1);
            } else {
                *reinterpret_cast<float2*>(aux + (size_t)row * 16 + (col - 32)) =
                    make_float2(a0 + bias[col - 32], a1 + bias[col - 31]);
            }
        }
    };

#pragma unroll
    for (int mf = 0; mf < 2; ++mf)
#pragma unroll
        for (int nf = 0; nf < NF; ++nf) {
            int row = mBase + wm * 32 + mf * 16 + g;
            int col = nBase + wn * WN + nf * 8 + 2 * t;
            emit(row, col, acc[mf][nf][0], acc[mf][nf][1]);
            emit(row + 8, col, acc[mf][nf][2], acc[mf][nf][3]);
        }
}

// ---------------- hidden pre-aggregation: warp/node, bf16 gather x8 -> bf16 [S0n|S1n] ----------------
// NOTE: trigger AFTER wait — guarantees that when dependents (k_hmm) launch, every
// grid before this one (incl. the writer of inb) has completed, making k_hmm's
// pre-wait reads of inb legal.
__global__ void __launch_bounds__(256) k_preagg(const __nv_bfloat16* __restrict__ inb) {
    PDL_WAIT();
    PDL_TRIGGER();
    int w = (blockIdx.x * 256 + threadIdx.x) >> 5;
    int lane = threadIdx.x & 31;
    if (w >= N_NODES) return;
    int i = g_rowptr[w], end = g_rowptr[w + 1];
    float rd = g_rdeg[w];
    float sa0 = 0.f, sa1 = 0.f, sp0 = 0.f, sp1 = 0.f;
    for (; i + 7 < end; i += 8) {
        int   si[8]; float pi[8]; float2 xi[8];
#pragma unroll
        for (int q = 0; q < 8; ++q) { si[q] = g_es[i + q]; pi[q] = g_ep[i + q]; }
#pragma unroll
        for (int q = 0; q < 8; ++q)
            xi[q] = __bfloat1622float2(*reinterpret_cast<const __nv_bfloat162*>(inb + (size_t)si[q] * 64 + 2 * lane));
#pragma unroll
        for (int q = 0; q < 8; ++q) {
            sa0 += xi[q].x;
            sa1 += xi[q].y;
            sp0 = fmaf(pi[q], xi[q].x, sp0);
            sp1 = fmaf(pi[q], xi[q].y, sp1);
        }
    }
    for (; i < end; ++i) {
        int s = g_es[i];
        float p = g_ep[i];
        float2 xv = __bfloat1622float2(*reinterpret_cast<const __nv_bfloat162*>(inb + (size_t)s * 64 + 2 * lane));
        sa0 += xv.x; sa1 += xv.y;
        sp0 = fmaf(p, xv.x, sp0);
        sp1 = fmaf(p, xv.y, sp1);
    }
    __nv_bfloat16* yr = g_Ypreb + (size_t)w * 128;
    *reinterpret_cast<__nv_bfloat162*>(yr + 2 * lane) =
        __float22bfloat162_rn(make_float2((sa0 - sp0) * rd, (sa1 - sp1) * rd));
    *reinterpret_cast<__nv_bfloat162*>(yr + 64 + 2 * lane) =
        __float22bfloat162_rn(make_float2(sp0 * rd, sp1 * rd));
}

// ---------------- hidden GEMM (bf16 mma): A=[inb | Ypreb], Bt n-major bf16, K=192 ----------------
// Software-pipelined across the PDL wait: B-load + chunk0 (inb, safe pre-wait thanks
// to preagg's trigger-after-wait) run BEFORE the wait; Ypreb chunks after.
// EPI: 1 = write midb (bf16), 2 = RK stage epilogue
template <int EPI>
__global__ void __launch_bounds__(256) k_hmm(const __nv_bfloat16* __restrict__ inb,
                                             const __nv_bfloat16* __restrict__ Bt,
                                             const float* __restrict__ bias,
                                             __nv_bfloat16* __restrict__ outb,
                                             int estage, float curMul) {
    PDL_TRIGGER();
    __shared__ __nv_bfloat16 Asm[128][72];
    __shared__ __nv_bfloat16 Bsm[64][200];

    const int tid = threadIdx.x;
    const int lane = tid & 31, warp = tid >> 5;
    const int wm = warp & 3, wn = warp >> 2;
    const int mBase = blockIdx.x * 128;
    const int g = lane >> 2, t = lane & 3;

    for (int i = tid; i < 64 * 192 / 8; i += 256) {
        int n = i / 24, c8 = (i % 24) * 8;
        *reinterpret_cast<uint4*>(&Bsm[n][c8]) = *reinterpret_cast<const uint4*>(Bt + n * 192 + c8);
    }

    float acc[2][4][4];
#pragma unroll
    for (int mf = 0; mf < 2; ++mf)
#pragma unroll
        for (int nf = 0; nf < 4; ++nf)
#pragma unroll
            for (int q = 0; q < 4; ++q) acc[mf][nf][q] = 0.f;

    auto load_A = [&](const __nv_bfloat16* srcbase, size_t rowStride, int off) {
#pragma unroll
        for (int i2 = 0; i2 < 4; ++i2) {
            int i = i2 * 256 + tid;
            int row = i >> 3, c8 = (i & 7) * 8;
            int gm = mBase + row;
            uint4 v = make_uint4(0, 0, 0, 0);
            if (gm < N_NODES)
                v = *reinterpret_cast<const uint4*>(srcbase + (size_t)gm * rowStride + off + c8);
            *reinterpret_cast<uint4*>(&Asm[row][c8]) = v;
        }
    };
    auto mma_chunk = [&](int chunk) {
#pragma unroll
        for (int kk = 0; kk < 4; ++kk) {
            const int kb = kk * 16;
            unsigned a[2][4];
#pragma unroll
            for (int mf = 0; mf < 2; ++mf) {
                int r = wm * 32 + mf * 16;
                a[mf][0] = *reinterpret_cast<const unsigned*>(&Asm[r + g][kb + 2 * t]);
                a[mf][1] = *reinterpret_cast<const unsigned*>(&Asm[r + g + 8][kb + 2 * t]);
                a[mf][2] = *reinterpret_cast<const unsigned*>(&Asm[r + g][kb + 2 * t + 8]);
                a[mf][3] = *reinterpret_cast<const unsigned*>(&Asm[r + g + 8][kb + 2 * t + 8]);
            }
#pragma unroll
            for (int nf = 0; nf < 4; ++nf) {
                int n = wn * 32 + nf * 8;
                unsigned b[2] = {
                    *reinterpret_cast<const unsigned*>(&Bsm[n + g][chunk * 64 + kb + 2 * t]),
                    *reinterpret_cast<const unsigned*>(&Bsm[n + g][chunk * 64 + kb + 2 * t + 8])
                };
                mma_bf16(acc[0][nf], a[0], b);
                mma_bf16(acc[1][nf], a[1], b);
            }
        }
    };

    // chunk 0: inb (R-part) — PRE-WAIT (overlaps the preceding preagg)
    load_A(inb, 64, 0);
    __syncthreads();
    mma_chunk(0);
    __syncthreads();

    PDL_WAIT();   // Ypreb from the immediately preceding k_preagg

    // chunks 1-2: Ypreb (W0/W1 parts)
#pragma unroll
    for (int chunk = 1; chunk < 3; ++chunk) {
        load_A(g_Ypreb, 128, (chunk - 1) * 64);
        __syncthreads();
        mma_chunk(chunk);
        __syncthreads();
    }

    auto emit = [&](int row, int col, float a0, float a1) {
        if (row >= N_NODES) return;
        float2 kv = make_float2(a0 + bias[col], a1 + bias[col + 1]);
        size_t idx = (size_t)row * 64 + col;
        if (EPI == 1) {
            *reinterpret_cast<__nv_bfloat162*>(outb + idx) = __float22bfloat162_rn(kv);
        } else {
            float2 h2 = *reinterpret_cast<const float2*>(g_h + idx);
            if (estage == 4) {
                float2 a2 = *reinterpret_cast<const float2*>(g_acc + idx);
                *reinterpret_cast<float2*>(g_h + idx) =
                    make_float2(h2.x + 0.5f * (a2.x + kv.x), h2.y + 0.5f * (a2.y + kv.y));
            } else {
                float2 a2;
                if (estage == 1) a2 = kv;
                else {
                    a2 = *reinterpret_cast<const float2*>(g_acc + idx);
                    a2.x = fmaf(2.f, kv.x, a2.x); a2.y = fmaf(2.f, kv.y, a2.y);
                }
                *reinterpret_cast<float2*>(g_acc + idx) = a2;
                float2 c2 = make_float2(fmaf(curMul, kv.x, h2.x), fmaf(curMul, kv.y, h2.y));
                *reinterpret_cast<__nv_bfloat162*>(outb + idx) = __float22bfloat162_rn(c2);
            }
        }
    };

#pragma unroll
    for (int mf = 0; mf < 2; ++mf)
#pragma unroll
        for (int nf = 0; nf < 4; ++nf) {
            int row = mBase + wm * 32 + mf * 16 + g;
            int col = wn * 32 + nf * 8 + 2 * t;
            emit(row, col, acc[mf][nf][0], acc[mf][nf][1]);
            emit(row + 8, col, acc[mf][nf][2], acc[mf][nf][3]);
        }
}

// ---------------- conv1 aggregation: warp/node, bf16 interleaved gather x8, tanh ----------------
__global__ void __launch_bounds__(256) k_agg1() {
    PDL_TRIGGER();
    int w = (blockIdx.x * 256 + threadIdx.x) >> 5;
    int lane = threadIdx.x & 31;
    if (w >= N_NODES) { PDL_WAIT(); return; }
    int i = g_rowptr[w], end = g_rowptr[w + 1];
    float rd = g_rdeg[w];
    PDL_WAIT();   // g_c1 / g_xr1 from conv1 GEMM
    float a0 = 0.f, a1 = 0.f;
    for (; i + 7 < end; i += 8) {
        int si[8]; float pi[8]; uint2 ui[8];
#pragma unroll
        for (int q = 0; q < 8; ++q) { si[q] = g_es[i + q]; pi[q] = g_ep[i + q]; }
#pragma unroll
        for (int q = 0; q < 8; ++q)
            ui[q] = *reinterpret_cast<const uint2*>(g_c1 + (size_t)si[q] * 128 + 4 * lane);
#pragma unroll
        for (int q = 0; q < 8; ++q) {
            float2 v0 = __bfloat1622float2(*reinterpret_cast<__nv_bfloat162*>(&ui[q].x));
            float2 v1 = __bfloat1622float2(*reinterpret_cast<__nv_bfloat162*>(&ui[q].y));
            a0 += fmaf(pi[q], v0.y - v0.x, v0.x);
            a1 += fmaf(pi[q], v1.y - v1.x, v1.x);
        }
    }
    for (; i < end; ++i) {
        int s = g_es[i];
        float p = g_ep[i];
        uint2 u = *reinterpret_cast<const uint2*>(g_c1 + (size_t)s * 128 + 4 * lane);
        float2 v0 = __bfloat1622float2(*reinterpret_cast<__nv_bfloat162*>(&u.x));
        float2 v1 = __bfloat1622float2(*reinterpret_cast<__nv_bfloat162*>(&u.y));
        a0 += fmaf(p, v0.y - v0.x, v0.x);
        a1 += fmaf(p, v1.y - v1.x, v1.x);
    }
    float2 xr = *reinterpret_cast<const float2*>(g_xr1 + (size_t)w * 64 + 2 * lane);
    float2 hv = make_float2(tanhf(fmaf(a0, rd, xr.x)), tanhf(fmaf(a1, rd, xr.y)));
    *reinterpret_cast<float2*>(g_h + (size_t)w * 64 + 2 * lane) = hv;
    *reinterpret_cast<__nv_bfloat162*>(g_hb + (size_t)w * 64 + 2 * lane) = __float22bfloat162_rn(hv);
}

// ---------------- conv2 aggregation + log_softmax (half-warp/node) ----------------
__global__ void __launch_bounds__(256) k_agg2_lsm(float* __restrict__ out) {
    PDL_TRIGGER();
    int hw = (blockIdx.x * 256 + threadIdx.x) >> 4;
    int c = threadIdx.x & 15;
    if (hw >= N_NODES) { PDL_WAIT(); return; }
    int i = g_rowptr[hw], end = g_rowptr[hw + 1];
    float rd = g_rdeg[hw];
    PDL_WAIT();   // g_c2 / g_xr2 from conv2 GEMM
    float acc = 0.f;
    for (; i + 1 < end; i += 2) {
        int sA = g_es[i], sB = g_es[i + 1];
        float pA = g_ep[i], pB = g_ep[i + 1];
        float2 vA = __bfloat1622float2(*reinterpret_cast<const __nv_bfloat162*>(g_c2 + (size_t)sA * 32 + 2 * c));
        float2 vB = __bfloat1622float2(*reinterpret_cast<const __nv_bfloat162*>(g_c2 + (size_t)sB * 32 + 2 * c));
        acc += fmaf(pA, vA.y - vA.x, vA.x) + fmaf(pB, vB.y - vB.x, vB.x);
    }
    if (i < end) {
        int s = g_es[i];
        float p = g_ep[i];
        float2 v = __bfloat1622float2(*reinterpret_cast<const __nv_bfloat162*>(g_c2 + (size_t)s * 32 + 2 * c));
        acc += fmaf(p, v.y - v.x, v.x);
    }
    float v = tanhf(fmaf(acc, rd, g_xr2[(size_t)hw * 16 + c]));
    float m = v;
    for (int o = 8; o > 0; o >>= 1) m = fmaxf(m, __shfl_xor_sync(0xffffffffu, m, o, 16));
    float e = expf(v - m);
    float s = e;
    for (int o = 8; o > 0; o >>= 1) s += __shfl_xor_sync(0xffffffffu, s, o, 16);
    out[(size_t)hw * 16 + c] = v - m - logf(s);
}

// ---------------- launch ----------------
extern "C" void kernel_launch(void* const* d_in, const int* in_sizes, int n_in,
                              void* d_out, int out_size) {
    const float* x  = (const float*)d_in[0];
    const float* ea = (const float*)d_in[1];
    const int*   src = (const int*)d_in[2];
    const int*   dst = (const int*)d_in[3];
    const float* W1 = (const float*)d_in[4];
    const float* R1 = (const float*)d_in[5];
    const float* b1 = (const float*)d_in[6];
    const float* Wa = (const float*)d_in[7];
    const float* Ra = (const float*)d_in[8];
    const float* ba = (const float*)d_in[9];
    const float* Wb = (const float*)d_in[10];
    const float* Rb = (const float*)d_in[11];
    const float* bb = (const float*)d_in[12];
    const float* W2 = (const float*)d_in[13];
    const float* R2 = (const float*)d_in[14];
    const float* b2 = (const float*)d_in[15];
    float* out = (float*)d_out;

    float *h, *B1, *B2, *xr1, *xr2;
    __nv_bfloat16 *hb, *midb, *curb, *c1, *c2, *Bh1t, *Bh2t;
    cudaGetSymbolAddress((void**)&h, g_h);
    cudaGetSymbolAddress((void**)&hb, g_hb);
    cudaGetSymbolAddress((void**)&midb, g_midb);
    cudaGetSymbolAddress((void**)&curb, g_curb);
    cudaGetSymbolAddress((void**)&B1, g_B1);
    cudaGetSymbolAddress((void**)&Bh1t, g_Bh1t);
    cudaGetSymbolAddress((void**)&Bh2t, g_Bh2t);
    cudaGetSymbolAddress((void**)&B2, g_B2);
    cudaGetSymbolAddress((void**)&c1, g_c1);
    cudaGetSymbolAddress((void**)&c2, g_c2);
    cudaGetSymbolAddress((void**)&xr1, g_xr1);
    cudaGetSymbolAddress((void**)&xr2, g_xr2);

    static cudaStream_t s2 = nullptr;
    static cudaEvent_t e1 = nullptr, e2 = nullptr;
    if (s2 == nullptr) {
        cudaStreamCreateWithFlags(&s2, cudaStreamNonBlocking);
        cudaEventCreateWithFlags(&e1, cudaEventDisableTiming);
        cudaEventCreateWithFlags(&e2, cudaEventDisableTiming);
    }

    cudaStream_t m = 0;

    // fork: CSR chain on side stream (count -> bsum -> bapply[+scan+reset] -> fill)
    cudaEventRecord(e1, m);
    cudaStreamWaitEvent(s2, e1, 0);
    launch_pdl(N_EDGES / 256, 256, s2, k_count, dst);
    launch_pdl(NB_SCAN, 256, s2, k_bsum);
    launch_pdl(NB_SCAN, 256, s2, k_bapply);
    launch_pdl(N_EDGES / 256, 256, s2, k_fill, src, dst, ea);
    cudaEventRecord(e2, s2);

    // main: weight concat -> conv1 tf32 GEMM (overlaps CSR chain)
    launch_pdl(192, 256, m, k_initW, W1, R1, Wa, Ra, Wb, Rb, W2, R2);
    launch_pdl(dim3(MG, 3), 256, m, k_mm<256, 192, 64, 0>, x, (const float*)B1, b1, c1, xr1);

    // join
    cudaStreamWaitEvent(m, e2, 0);

    const int WG = (N_NODES * 32 + 255) / 256;
    const int HG = (N_NODES * 16 + 255) / 256;

    launch_pdl(WG, 256, m, k_agg1);

    // RK4 stages (PDL-chained, hmm chunk0 pipelined across the wait)
    auto fstep = [&](const __nv_bfloat16* inb, int stage, float curMul) {
        launch_pdl(WG, 256, m, k_preagg, inb);
        launch_pdl(MG, 256, m, k_hmm<1>, inb, Bh1t, ba, midb, 0, 0.f);
        launch_pdl(WG, 256, m, k_preagg, (const __nv_bfloat16*)midb);
        launch_pdl(MG, 256, m, k_hmm<2>, (const __nv_bfloat16*)midb, Bh2t, bb, curb, stage, curMul);
    };
    fstep(hb, 1, 1.5f);
    fstep(curb, 2, 1.5f);
    fstep(curb, 3, 3.0f);
    fstep(curb, 4, 0.f);

    // conv2 + log_softmax
    launch_pdl(dim3(MG, 1), 256, m, k_mm<64, 48, 48, 3>, (const float*)h, (const float*)B2, b2, c2, xr2);
    launch_pdl(HG, 256, m, k_agg2_lsm, out);
}

// round 15
// speedup vs baseline: 1.5357x; 1.0226x over previous
#include <cuda_runtime.h>
#include <cuda_bf16.h>
#include <cstdint>

#define N_NODES 50000
#define N_EDGES 800000
#define F_IN 256
#define HID 64
#define NCLS 16
#define NB_SCAN 196   // ceil(50000/256)
#define MG 391        // ceil(50000/128)

// PDL: allow dependents to launch early; wait gates consumption of predecessor data.
#define PDL_TRIGGER() asm volatile("griddepcontrol.launch_dependents;" ::: "memory")
#define PDL_WAIT()    asm volatile("griddepcontrol.wait;" ::: "memory")

// ---------------- scratch ----------------
__device__ int   g_cnt[N_NODES];       // zero-initialized; re-zeroed by k_bapply each call
__device__ int   g_rowptr[N_NODES + 1];
__device__ int   g_cursor[N_NODES];
__device__ int   g_bsum[256];
__device__ __align__(16) int2 g_edge[N_EDGES];   // packed {src, __float_as_int(p)}
__device__ float g_rdeg[N_NODES];

__device__ __align__(128) float g_h[(size_t)N_NODES * HID];     // fp32 ODE state
__device__ __align__(128) float g_acc[(size_t)N_NODES * HID];   // fp32 RK accumulator
__device__ __align__(128) __nv_bfloat16 g_hb[(size_t)N_NODES * HID];
__device__ __align__(128) __nv_bfloat16 g_midb[(size_t)N_NODES * HID];
__device__ __align__(128) __nv_bfloat16 g_curb[(size_t)N_NODES * HID];
__device__ __align__(128) __nv_bfloat16 g_Ypreb[(size_t)N_NODES * 128]; // [S0n|S1n] bf16
__device__ __align__(128) __nv_bfloat16 g_c1[(size_t)N_NODES * 128];    // interleaved y0/y1, conv1
__device__ __align__(128) float g_xr1[(size_t)N_NODES * HID];
__device__ __align__(128) __nv_bfloat16 g_c2[(size_t)N_NODES * 32];     // interleaved y0/y1, conv2
__device__ __align__(128) float g_xr2[(size_t)N_NODES * NCLS];
// concatenated weights
__device__ __align__(16) float g_B1[256 * 192];            // fp32 cols [W1_0 | W1_1 | R1]
__device__ __align__(16) __nv_bfloat16 g_Bh1t[64 * 192];   // bf16 n-major: [Ra;Wa0;Wa1]^T
__device__ __align__(16) __nv_bfloat16 g_Bh2t[64 * 192];   // bf16 n-major: [Rb;Wb0;Wb1]^T
__device__ __align__(16) float g_B2[64 * 48];              // fp32 cols [W2_0 | W2_1 | R2]

// ---------------- mma helpers ----------------
__device__ __forceinline__ unsigned f2tf(float f) {
    unsigned r; asm("cvt.rna.tf32.f32 %0, %1;" : "=r"(r) : "f"(f)); return r;
}
__device__ __forceinline__ void mma_tf32(float* d, const unsigned* a, const unsigned* b) {
    asm volatile("mma.sync.aligned.m16n8k8.row.col.f32.tf32.tf32.f32 "
        "{%0,%1,%2,%3}, {%4,%5,%6,%7}, {%8,%9}, {%0,%1,%2,%3};"
        : "+f"(d[0]), "+f"(d[1]), "+f"(d[2]), "+f"(d[3])
        : "r"(a[0]), "r"(a[1]), "r"(a[2]), "r"(a[3]), "r"(b[0]), "r"(b[1]));
}
__device__ __forceinline__ void mma_bf16(float* d, const unsigned* a, const unsigned* b) {
    asm volatile("mma.sync.aligned.m16n8k16.row.col.f32.bf16.bf16.f32 "
        "{%0,%1,%2,%3}, {%4,%5,%6,%7}, {%8,%9}, {%0,%1,%2,%3};"
        : "+f"(d[0]), "+f"(d[1]), "+f"(d[2]), "+f"(d[3])
        : "r"(a[0]), "r"(a[1]), "r"(a[2]), "r"(a[3]), "r"(b[0]), "r"(b[1]));
}

// ---------------- PDL launch helper ----------------
template <typename... P, typename... A>
static inline void launch_pdl(dim3 g, dim3 b, cudaStream_t st, void (*k)(P...), A... args) {
    cudaLaunchConfig_t cfg = {};
    cfg.gridDim = g; cfg.blockDim = b; cfg.dynamicSmemBytes = 0; cfg.stream = st;
    cudaLaunchAttribute at[1];
    at[0].id = cudaLaunchAttributeProgrammaticStreamSerialization;
    at[0].val.programmaticStreamSerializationAllowed = 1;
    cfg.attrs = at; cfg.numAttrs = 1;
    cudaLaunchKernelEx(&cfg, k, static_cast<P>(args)...);
}

// ---------------- init: concatenate weights (main stream) ----------------
__global__ void k_initW(const float* __restrict__ W1, const float* __restrict__ R1,
                        const float* __restrict__ Wa, const float* __restrict__ Ra,
                        const float* __restrict__ Wb, const float* __restrict__ Rb,
                        const float* __restrict__ W2, const float* __restrict__ R2) {
    PDL_TRIGGER();
    int i = blockIdx.x * 256 + threadIdx.x;
    if (i < 256 * 192) {   // B1[k][n] fp32
        int k = i / 192, n = i % 192;
        float v;
        if (n < 64)       v = W1[k * 64 + n];
        else if (n < 128) v = W1[256 * 64 + k * 64 + (n - 64)];
        else              v = R1[k * 64 + (n - 128)];
        g_B1[i] = v;
    }
    if (i < 64 * 192) {    // Bh1t/Bh2t[n][k] bf16
        int n = i / 192, k = i % 192;
        float va, vb;
        if (k < 64)       { va = Ra[k * 64 + n];                   vb = Rb[k * 64 + n]; }
        else if (k < 128) { va = Wa[(k - 64) * 64 + n];            vb = Wb[(k - 64) * 64 + n]; }
        else              { va = Wa[64 * 64 + (k - 128) * 64 + n]; vb = Wb[64 * 64 + (k - 128) * 64 + n]; }
        g_Bh1t[i] = __float2bfloat16(va);
        g_Bh2t[i] = __float2bfloat16(vb);
    }
    if (i < 64 * 48) {     // B2[k][n] fp32
        int k = i / 48, n = i % 48;
        float v;
        if (n < 16)      v = W2[k * 16 + n];
        else if (n < 32) v = W2[64 * 16 + k * 16 + (n - 16)];
        else             v = R2[k * 16 + (n - 32)];
        g_B2[i] = v;
    }
}

// ---------------- CSR build (side stream, PDL chained) ----------------
__global__ void k_count(const int* __restrict__ dst) {
    PDL_TRIGGER();
    int e = blockIdx.x * blockDim.x + threadIdx.x;
    int d = (e < N_EDGES) ? dst[e] : -1;
    PDL_WAIT();
    if (e < N_EDGES) atomicAdd(&g_cnt[d], 1);
}
__global__ void k_bsum() {
    PDL_TRIGGER();
    __shared__ int ss[256];
    int t = threadIdx.x;
    int idx = blockIdx.x * 256 + t;
    PDL_WAIT();
    ss[t] = (idx < N_NODES) ? g_cnt[idx] : 0;
    __syncthreads();
    for (int off = 128; off > 0; off >>= 1) {
        if (t < off) ss[t] += ss[t + off];
        __syncthreads();
    }
    if (t == 0) g_bsum[blockIdx.x] = ss[0];
}
// bapply: inline exclusive prefix of block sums + block scan + cnt reset
__global__ void k_bapply() {
    PDL_TRIGGER();
    __shared__ int ss[256];
    __shared__ int s_boff;
    int t = threadIdx.x;
    int idx = blockIdx.x * 256 + t;
    PDL_WAIT();
    int pv = (t < (int)blockIdx.x) ? g_bsum[t] : 0;   // blockIdx.x <= 195 < 256
    ss[t] = pv;
    __syncthreads();
    for (int off = 128; off > 0; off >>= 1) {
        if (t < off) ss[t] += ss[t + off];
        __syncthreads();
    }
    if (t == 0) s_boff = ss[0];
    __syncthreads();
    int v = (idx < N_NODES) ? g_cnt[idx] : 0;
    if (idx < N_NODES) g_cnt[idx] = 0;                // reset for next call (zero-init covers call 1)
    ss[t] = v;
    __syncthreads();
    for (int off = 1; off < 256; off <<= 1) {
        int u = (t >= off) ? ss[t - off] : 0;
        __syncthreads();
        ss[t] += u;
        __syncthreads();
    }
    if (idx < N_NODES) {
        int base = s_boff + ss[t] - v;
        g_rowptr[idx] = base;
        g_cursor[idx] = base;
        g_rdeg[idx] = 1.0f / (float)(v > 0 ? v : 1);
        if (idx == N_NODES - 1) g_rowptr[N_NODES] = base + v;
    }
}
__global__ void k_fill(const int* __restrict__ src, const int* __restrict__ dst,
                       const float* __restrict__ ea) {
    PDL_TRIGGER();
    int e = blockIdx.x * blockDim.x + threadIdx.x;
    int s = 0, d = 0; float p = 0.f;
    if (e < N_EDGES) { s = src[e]; d = dst[e]; p = ea[e]; }
    PDL_WAIT();
    if (e < N_EDGES) {
        int pos = atomicAdd(&g_cursor[d], 1);
        g_edge[pos] = make_int2(s, __float_as_int(p));
    }
}

// ---------------- tf32 GEMM (conv1/conv2), EPI: 0=conv1, 3=conv2 ----------------
template <int K, int NTOT, int BN, int EPI>
__global__ void __launch_bounds__(256) k_mm(const float* __restrict__ A,
                                            const float* __restrict__ B,
                                            const float* __restrict__ bias,
                                            __nv_bfloat16* __restrict__ Cb,
                                            float* __restrict__ aux) {
    PDL_TRIGGER();
    __shared__ unsigned As[128][36];
    __shared__ unsigned Bs[32][BN + 8];

    constexpr int BM = 128, BK = 32;
    constexpr int WN = BN / 2, NF = WN / 8;
    const int tid = threadIdx.x;
    const int lane = tid & 31, warp = tid >> 5;
    const int wm = warp & 3, wn = warp >> 2;
    const int mBase = blockIdx.x * BM;
    const int nBase = blockIdx.y * BN;
    const int g = lane >> 2, t = lane & 3;

    float acc[2][NF][4];
#pragma unroll
    for (int mf = 0; mf < 2; ++mf)
#pragma unroll
        for (int nf = 0; nf < NF; ++nf)
#pragma unroll
            for (int q = 0; q < 4; ++q) acc[mf][nf][q] = 0.f;

    const int ar = tid >> 3, ac = (tid & 7) * 4;
    PDL_WAIT();   // conv1: B1 from k_initW; conv2: g_h from last k_hmm

    for (int k0 = 0; k0 < K; k0 += BK) {
#pragma unroll
        for (int p = 0; p < 4; ++p) {
            int row = p * 32 + ar;
            int gm = mBase + row;
            float4 v = make_float4(0.f, 0.f, 0.f, 0.f);
            if (gm < N_NODES) v = *reinterpret_cast<const float4*>(A + (size_t)gm * K + k0 + ac);
            unsigned* s = &As[row][ac];
            s[0] = f2tf(v.x); s[1] = f2tf(v.y); s[2] = f2tf(v.z); s[3] = f2tf(v.w);
        }
        for (int i = tid; i < BK * BN / 4; i += 256) {
            int bk = i / (BN / 4), bc = (i % (BN / 4)) * 4;
            float4 v = *reinterpret_cast<const float4*>(B + (size_t)(k0 + bk) * NTOT + nBase + bc);
            unsigned* s = &Bs[bk][bc];
            s[0] = f2tf(v.x); s[1] = f2tf(v.y); s[2] = f2tf(v.z); s[3] = f2tf(v.w);
        }
        __syncthreads();
#pragma unroll
        for (int kk = 0; kk < BK / 8; ++kk) {
            const int kb = kk * 8;
            unsigned a[2][4];
#pragma unroll
            for (int mf = 0; mf < 2; ++mf) {
                int r = wm * 32 + mf * 16;
                a[mf][0] = As[r + g][kb + t];
                a[mf][1] = As[r + g + 8][kb + t];
                a[mf][2] = As[r + g][kb + t + 4];
                a[mf][3] = As[r + g + 8][kb + t + 4];
            }
#pragma unroll
            for (int nf = 0; nf < NF; ++nf) {
                int n = wn * WN + nf * 8;
                unsigned b[2] = { Bs[kb + t][n + g], Bs[kb + t + 4][n + g] };
                mma_tf32(acc[0][nf], a[0], b);
                mma_tf32(acc[1][nf], a[1], b);
            }
        }
        __syncthreads();
    }

    const int by = blockIdx.y;
    auto emit = [&](int row, int col, float a0, float a1) {
        if (row >= N_NODES) return;
        if (EPI == 0) {
            int c = col - (by << 6);
            if (by < 2) {
                Cb[(size_t)row * 128 + 2 * c + by]       = __float2bfloat16(a0);
                Cb[(size_t)row * 128 + 2 * (c + 1) + by] = __float2bfloat16(a1);
            } else {
                *reinterpret_cast<float2*>(aux + (size_t)row * 64 + c) =
                    make_float2(a0 + bias[c], a1 + bias[c + 1]);
            }
        } else {  // EPI == 3 (conv2)
            if (col < 32) {
                int sec = col >> 4, c = col & 15;
                Cb[(size_t)row * 32 + 2 * c + sec]       = __float2bfloat16(a0);
                Cb[(size_t)row * 32 + 2 * (c + 1) + sec] = __float2bfloat16(a1);
            } else {
                *reinterpret_cast<float2*>(aux + (size_t)row * 16 + (col - 32)) =
                    make_float2(a0 + bias[col - 32], a1 + bias[col - 31]);
            }
        }
    };

#pragma unroll
    for (int mf = 0; mf < 2; ++mf)
#pragma unroll
        for (int nf = 0; nf < NF; ++nf) {
            int row = mBase + wm * 32 + mf * 16 + g;
            int col = nBase + wn * WN + nf * 8 + 2 * t;
            emit(row, col, acc[mf][nf][0], acc[mf][nf][1]);
            emit(row + 8, col, acc[mf][nf][2], acc[mf][nf][3]);
        }
}

// ---------------- hidden pre-aggregation: warp/node, packed-edge bf16 gather x8 ----------------
// trigger AFTER wait — dependents (k_hmm) may then read inb pre-wait (transitive completion).
__global__ void __launch_bounds__(256) k_preagg(const __nv_bfloat16* __restrict__ inb) {
    PDL_WAIT();
    PDL_TRIGGER();
    int w = (blockIdx.x * 256 + threadIdx.x) >> 5;
    int lane = threadIdx.x & 31;
    if (w >= N_NODES) return;
    int i = g_rowptr[w], end = g_rowptr[w + 1];
    float rd = g_rdeg[w];
    float sa0 = 0.f, sa1 = 0.f, sp0 = 0.f, sp1 = 0.f;
    for (; i + 7 < end; i += 8) {
        int2 ei[8]; float2 xi[8];
#pragma unroll
        for (int q = 0; q < 8; ++q) ei[q] = g_edge[i + q];
#pragma unroll
        for (int q = 0; q < 8; ++q)
            xi[q] = __bfloat1622float2(*reinterpret_cast<const __nv_bfloat162*>(inb + (size_t)ei[q].x * 64 + 2 * lane));
#pragma unroll
        for (int q = 0; q < 8; ++q) {
            float p = __int_as_float(ei[q].y);
            sa0 += xi[q].x;
            sa1 += xi[q].y;
            sp0 = fmaf(p, xi[q].x, sp0);
            sp1 = fmaf(p, xi[q].y, sp1);
        }
    }
    for (; i < end; ++i) {
        int2 e = g_edge[i];
        float p = __int_as_float(e.y);
        float2 xv = __bfloat1622float2(*reinterpret_cast<const __nv_bfloat162*>(inb + (size_t)e.x * 64 + 2 * lane));
        sa0 += xv.x; sa1 += xv.y;
        sp0 = fmaf(p, xv.x, sp0);
        sp1 = fmaf(p, xv.y, sp1);
    }
    __nv_bfloat16* yr = g_Ypreb + (size_t)w * 128;
    *reinterpret_cast<__nv_bfloat162*>(yr + 2 * lane) =
        __float22bfloat162_rn(make_float2((sa0 - sp0) * rd, (sa1 - sp1) * rd));
    *reinterpret_cast<__nv_bfloat162*>(yr + 64 + 2 * lane) =
        __float22bfloat162_rn(make_float2(sp0 * rd, sp1 * rd));
}

// ---------------- hidden GEMM (bf16 mma): A=[inb | Ypreb], Bt n-major bf16, K=192 ----------------
// chunk0 (inb) pipelined pre-wait; Ypreb chunks post-wait.
// EPI: 1 = write midb (bf16), 2 = RK stage epilogue
template <int EPI>
__global__ void __launch_bounds__(256) k_hmm(const __nv_bfloat16* __restrict__ inb,
                                             const __nv_bfloat16* __restrict__ Bt,
                                             const float* __restrict__ bias,
                                             __nv_bfloat16* __restrict__ outb,
                                             int estage, float curMul) {
    PDL_TRIGGER();
    __shared__ __nv_bfloat16 Asm[128][72];
    __shared__ __nv_bfloat16 Bsm[64][200];

    const int tid = threadIdx.x;
    const int lane = tid & 31, warp = tid >> 5;
    const int wm = warp & 3, wn = warp >> 2;
    const int mBase = blockIdx.x * 128;
    const int g = lane >> 2, t = lane & 3;

    for (int i = tid; i < 64 * 192 / 8; i += 256) {
        int n = i / 24, c8 = (i % 24) * 8;
        *reinterpret_cast<uint4*>(&Bsm[n][c8]) = *reinterpret_cast<const uint4*>(Bt + n * 192 + c8);
    }

    float acc[2][4][4];
#pragma unroll
    for (int mf = 0; mf < 2; ++mf)
#pragma unroll
        for (int nf = 0; nf < 4; ++nf)
#pragma unroll
            for (int q = 0; q < 4; ++q) acc[mf][nf][q] = 0.f;

    auto load_A = [&](const __nv_bfloat16* srcbase, size_t rowStride, int off) {
#pragma unroll
        for (int i2 = 0; i2 < 4; ++i2) {
            int i = i2 * 256 + tid;
            int row = i >> 3, c8 = (i & 7) * 8;
            int gm = mBase + row;
            uint4 v = make_uint4(0, 0, 0, 0);
            if (gm < N_NODES)
                v = *reinterpret_cast<const uint4*>(srcbase + (size_t)gm * rowStride + off + c8);
            *reinterpret_cast<uint4*>(&Asm[row][c8]) = v;
        }
    };
    auto mma_chunk = [&](int chunk) {
#pragma unroll
        for (int kk = 0; kk < 4; ++kk) {
            const int kb = kk * 16;
            unsigned a[2][4];
#pragma unroll
            for (int mf = 0; mf < 2; ++mf) {
                int r = wm * 32 + mf * 16;
                a[mf][0] = *reinterpret_cast<const unsigned*>(&Asm[r + g][kb + 2 * t]);
                a[mf][1] = *reinterpret_cast<const unsigned*>(&Asm[r + g + 8][kb + 2 * t]);
                a[mf][2] = *reinterpret_cast<const unsigned*>(&Asm[r + g][kb + 2 * t + 8]);
                a[mf][3] = *reinterpret_cast<const unsigned*>(&Asm[r + g + 8][kb + 2 * t + 8]);
            }
#pragma unroll
            for (int nf = 0; nf < 4; ++nf) {
                int n = wn * 32 + nf * 8;
                unsigned b[2] = {
                    *reinterpret_cast<const unsigned*>(&Bsm[n + g][chunk * 64 + kb + 2 * t]),
                    *reinterpret_cast<const unsigned*>(&Bsm[n + g][chunk * 64 + kb + 2 * t + 8])
                };
                mma_bf16(acc[0][nf], a[0], b);
                mma_bf16(acc[1][nf], a[1], b);
            }
        }
    };

    // chunk 0: inb (R-part) — PRE-WAIT
    load_A(inb, 64, 0);
    __syncthreads();
    mma_chunk(0);
    __syncthreads();

    PDL_WAIT();   // Ypreb from the immediately preceding k_preagg

#pragma unroll
    for (int chunk = 1; chunk < 3; ++chunk) {
        load_A(g_Ypreb, 128, (chunk - 1) * 64);
        __syncthreads();
        mma_chunk(chunk);
        __syncthreads();
    }

    auto emit = [&](int row, int col, float a0, float a1) {
        if (row >= N_NODES) return;
        float2 kv = make_float2(a0 + bias[col], a1 + bias[col + 1]);
        size_t idx = (size_t)row * 64 + col;
        if (EPI == 1) {
            *reinterpret_cast<__nv_bfloat162*>(outb + idx) = __float22bfloat162_rn(kv);
        } else {
            float2 h2 = *reinterpret_cast<const float2*>(g_h + idx);
            if (estage == 4) {
                float2 a2 = *reinterpret_cast<const float2*>(g_acc + idx);
                *reinterpret_cast<float2*>(g_h + idx) =
                    make_float2(h2.x + 0.5f * (a2.x + kv.x), h2.y + 0.5f * (a2.y + kv.y));
            } else {
                float2 a2;
                if (estage == 1) a2 = kv;
                else {
                    a2 = *reinterpret_cast<const float2*>(g_acc + idx);
                    a2.x = fmaf(2.f, kv.x, a2.x); a2.y = fmaf(2.f, kv.y, a2.y);
                }
                *reinterpret_cast<float2*>(g_acc + idx) = a2;
                float2 c2 = make_float2(fmaf(curMul, kv.x, h2.x), fmaf(curMul, kv.y, h2.y));
                *reinterpret_cast<__nv_bfloat162*>(outb + idx) = __float22bfloat162_rn(c2);
            }
        }
    };

#pragma unroll
    for (int mf = 0; mf < 2; ++mf)
#pragma unroll
        for (int nf = 0; nf < 4; ++nf) {
            int row = mBase + wm * 32 + mf * 16 + g;
            int col = wn * 32 + nf * 8 + 2 * t;
            emit(row, col, acc[mf][nf][0], acc[mf][nf][1]);
            emit(row + 8, col, acc[mf][nf][2], acc[mf][nf][3]);
        }
}

// ---------------- conv1 aggregation: warp/node, packed-edge bf16 gather x8, tanh ----------------
__global__ void __launch_bounds__(256) k_agg1() {
    PDL_TRIGGER();
    int w = (blockIdx.x * 256 + threadIdx.x) >> 5;
    int lane = threadIdx.x & 31;
    if (w >= N_NODES) { PDL_WAIT(); return; }
    int i = g_rowptr[w], end = g_rowptr[w + 1];
    float rd = g_rdeg[w];
    PDL_WAIT();   // g_c1 / g_xr1 from conv1 GEMM
    float a0 = 0.f, a1 = 0.f;
    for (; i + 7 < end; i += 8) {
        int2 ei[8]; uint2 ui[8];
#pragma unroll
        for (int q = 0; q < 8; ++q) ei[q] = g_edge[i + q];
#pragma unroll
        for (int q = 0; q < 8; ++q)
            ui[q] = *reinterpret_cast<const uint2*>(g_c1 + (size_t)ei[q].x * 128 + 4 * lane);
#pragma unroll
        for (int q = 0; q < 8; ++q) {
            float p = __int_as_float(ei[q].y);
            float2 v0 = __bfloat1622float2(*reinterpret_cast<__nv_bfloat162*>(&ui[q].x));
            float2 v1 = __bfloat1622float2(*reinterpret_cast<__nv_bfloat162*>(&ui[q].y));
            a0 += fmaf(p, v0.y - v0.x, v0.x);
            a1 += fmaf(p, v1.y - v1.x, v1.x);
        }
    }
    for (; i < end; ++i) {
        int2 e = g_edge[i];
        float p = __int_as_float(e.y);
        uint2 u = *reinterpret_cast<const uint2*>(g_c1 + (size_t)e.x * 128 + 4 * lane);
        float2 v0 = __bfloat1622float2(*reinterpret_cast<__nv_bfloat162*>(&u.x));
        float2 v1 = __bfloat1622float2(*reinterpret_cast<__nv_bfloat162*>(&u.y));
        a0 += fmaf(p, v0.y - v0.x, v0.x);
        a1 += fmaf(p, v1.y - v1.x, v1.x);
    }
    float2 xr = *reinterpret_cast<const float2*>(g_xr1 + (size_t)w * 64 + 2 * lane);
    float2 hv = make_float2(tanhf(fmaf(a0, rd, xr.x)), tanhf(fmaf(a1, rd, xr.y)));
    *reinterpret_cast<float2*>(g_h + (size_t)w * 64 + 2 * lane) = hv;
    *reinterpret_cast<__nv_bfloat162*>(g_hb + (size_t)w * 64 + 2 * lane) = __float22bfloat162_rn(hv);
}

// ---------------- conv2 aggregation + log_softmax (half-warp/node) ----------------
__global__ void __launch_bounds__(256) k_agg2_lsm(float* __restrict__ out) {
    PDL_TRIGGER();
    int hw = (blockIdx.x * 256 + threadIdx.x) >> 4;
    int c = threadIdx.x & 15;
    if (hw >= N_NODES) { PDL_WAIT(); return; }
    int i = g_rowptr[hw], end = g_rowptr[hw + 1];
    float rd = g_rdeg[hw];
    PDL_WAIT();   // g_c2 / g_xr2 from conv2 GEMM
    float acc = 0.f;
    for (; i + 1 < end; i += 2) {
        int2 eA = g_edge[i], eB = g_edge[i + 1];
        float pA = __int_as_float(eA.y), pB = __int_as_float(eB.y);
        float2 vA = __bfloat1622float2(*reinterpret_cast<const __nv_bfloat162*>(g_c2 + (size_t)eA.x * 32 + 2 * c));
        float2 vB = __bfloat1622float2(*reinterpret_cast<const __nv_bfloat162*>(g_c2 + (size_t)eB.x * 32 + 2 * c));
        acc += fmaf(pA, vA.y - vA.x, vA.x) + fmaf(pB, vB.y - vB.x, vB.x);
    }
    if (i < end) {
        int2 e = g_edge[i];
        float p = __int_as_float(e.y);
        float2 v = __bfloat1622float2(*reinterpret_cast<const __nv_bfloat162*>(g_c2 + (size_t)e.x * 32 + 2 * c));
        acc += fmaf(p, v.y - v.x, v.x);
    }
    float v = tanhf(fmaf(acc, rd, g_xr2[(size_t)hw * 16 + c]));
    float m = v;
    for (int o = 8; o > 0; o >>= 1) m = fmaxf(m, __shfl_xor_sync(0xffffffffu, m, o, 16));
    float e = expf(v - m);
    float s = e;
    for (int o = 8; o > 0; o >>= 1) s += __shfl_xor_sync(0xffffffffu, s, o, 16);
    out[(size_t)hw * 16 + c] = v - m - logf(s);
}

// ---------------- launch ----------------
extern "C" void kernel_launch(void* const* d_in, const int* in_sizes, int n_in,
                              void* d_out, int out_size) {
    const float* x  = (const float*)d_in[0];
    const float* ea = (const float*)d_in[1];
    const int*   src = (const int*)d_in[2];
    const int*   dst = (const int*)d_in[3];
    const float* W1 = (const float*)d_in[4];
    const float* R1 = (const float*)d_in[5];
    const float* b1 = (const float*)d_in[6];
    const float* Wa = (const float*)d_in[7];
    const float* Ra = (const float*)d_in[8];
    const float* ba = (const float*)d_in[9];
    const float* Wb = (const float*)d_in[10];
    const float* Rb = (const float*)d_in[11];
    const float* bb = (const float*)d_in[12];
    const float* W2 = (const float*)d_in[13];
    const float* R2 = (const float*)d_in[14];
    const float* b2 = (const float*)d_in[15];
    float* out = (float*)d_out;

    float *h, *B1, *B2, *xr1, *xr2;
    __nv_bfloat16 *hb, *midb, *curb, *c1, *c2, *Bh1t, *Bh2t;
    cudaGetSymbolAddress((void**)&h, g_h);
    cudaGetSymbolAddress((void**)&hb, g_hb);
    cudaGetSymbolAddress((void**)&midb, g_midb);
    cudaGetSymbolAddress((void**)&curb, g_curb);
    cudaGetSymbolAddress((void**)&B1, g_B1);
    cudaGetSymbolAddress((void**)&Bh1t, g_Bh1t);
    cudaGetSymbolAddress((void**)&Bh2t, g_Bh2t);
    cudaGetSymbolAddress((void**)&B2, g_B2);
    cudaGetSymbolAddress((void**)&c1, g_c1);
    cudaGetSymbolAddress((void**)&c2, g_c2);
    cudaGetSymbolAddress((void**)&xr1, g_xr1);
    cudaGetSymbolAddress((void**)&xr2, g_xr2);

    static cudaStream_t s2 = nullptr;
    static cudaEvent_t e1 = nullptr, e2 = nullptr;
    if (s2 == nullptr) {
        cudaStreamCreateWithFlags(&s2, cudaStreamNonBlocking);
        cudaEventCreateWithFlags(&e1, cudaEventDisableTiming);
        cudaEventCreateWithFlags(&e2, cudaEventDisableTiming);
    }

    cudaStream_t m = 0;

    // fork: CSR chain on side stream (count -> bsum -> bapply[+scan+reset] -> fill)
    cudaEventRecord(e1, m);
    cudaStreamWaitEvent(s2, e1, 0);
    launch_pdl(N_EDGES / 256, 256, s2, k_count, dst);
    launch_pdl(NB_SCAN, 256, s2, k_bsum);
    launch_pdl(NB_SCAN, 256, s2, k_bapply);
    launch_pdl(N_EDGES / 256, 256, s2, k_fill, src, dst, ea);
    cudaEventRecord(e2, s2);

    // main: weight concat -> conv1 tf32 GEMM (overlaps CSR chain)
    launch_pdl(192, 256, m, k_initW, W1, R1, Wa, Ra, Wb, Rb, W2, R2);
    launch_pdl(dim3(MG, 3), 256, m, k_mm<256, 192, 64, 0>, x, (const float*)B1, b1, c1, xr1);

    // join
    cudaStreamWaitEvent(m, e2, 0);

    const int WG = (N_NODES * 32 + 255) / 256;
    const int HG = (N_NODES * 16 + 255) / 256;

    launch_pdl(WG, 256, m, k_agg1);

    // RK4 stages (PDL-chained)
    auto fstep = [&](const __nv_bfloat16* inb, int stage, float curMul) {
        launch_pdl(WG, 256, m, k_preagg, inb);
        launch_pdl(MG, 256, m, k_hmm<1>, inb, Bh1t, ba, midb, 0, 0.f);
        launch_pdl(WG, 256, m, k_preagg, (const __nv_bfloat16*)midb);
        launch_pdl(MG, 256, m, k_hmm<2>, (const __nv_bfloat16*)midb, Bh2t, bb, curb, stage, curMul);
    };
    fstep(hb, 1, 1.5f);
    fstep(curb, 2, 1.5f);
    fstep(curb, 3, 3.0f);
    fstep(curb, 4, 0.f);

    // conv2 + log_softmax
    launch_pdl(dim3(MG, 1), 256, m, k_mm<64, 48, 48, 3>, (const float*)h, (const float*)B2, b2, c2, xr2);
    launch_pdl(HG, 256, m, k_agg2_lsm, out);
}

// round 17
// speedup vs baseline: 1.5482x; 1.0082x over previous
#include <cuda_runtime.h>
#include <cuda_bf16.h>
#include <cstdint>

#define N_NODES 50000
#define N_EDGES 800000
#define F_IN 256
#define HID 64
#define NCLS 16
#define NB_SCAN 196   // ceil(50000/256)
#define MG 391        // ceil(50000/128)

// PDL: allow dependents to launch early; wait gates consumption of predecessor data.
#define PDL_TRIGGER() asm volatile("griddepcontrol.launch_dependents;" ::: "memory")
#define PDL_WAIT()    asm volatile("griddepcontrol.wait;" ::: "memory")

// ---------------- scratch ----------------
__device__ int   g_cnt[N_NODES];       // zero-initialized; re-zeroed by k_bapply each call
__device__ int   g_rowptr[N_NODES + 1];
__device__ int   g_cursor[N_NODES];
__device__ int   g_bsum[256];
__device__ __align__(16) int2 g_edge[N_EDGES];   // packed {src, __float_as_int(p)}
__device__ float g_rdeg[N_NODES];

__device__ __align__(128) float g_h[(size_t)N_NODES * HID];     // fp32 ODE state
__device__ __align__(128) float g_acc[(size_t)N_NODES * HID];   // fp32 RK accumulator
__device__ __align__(128) __nv_bfloat16 g_hb[(size_t)N_NODES * HID];
__device__ __align__(128) __nv_bfloat16 g_midb[(size_t)N_NODES * HID];
__device__ __align__(128) __nv_bfloat16 g_curb[(size_t)N_NODES * HID];
__device__ __align__(128) __nv_bfloat16 g_Ypreb[(size_t)N_NODES * 128]; // [S0n|S1n] bf16
__device__ __align__(128) __nv_bfloat16 g_c1[(size_t)N_NODES * 128];    // interleaved y0/y1, conv1
__device__ __align__(128) float g_xr1[(size_t)N_NODES * HID];
__device__ __align__(128) __nv_bfloat16 g_c2[(size_t)N_NODES * 32];     // interleaved y0/y1, conv2
__device__ __align__(128) float g_xr2[(size_t)N_NODES * NCLS];
// concatenated weights
__device__ __align__(16) float g_B1[256 * 192];            // fp32 cols [W1_0 | W1_1 | R1]
__device__ __align__(16) __nv_bfloat16 g_Bh1t[64 * 192];   // bf16 n-major: [Ra;Wa0;Wa1]^T
__device__ __align__(16) __nv_bfloat16 g_Bh2t[64 * 192];   // bf16 n-major: [Rb;Wb0;Wb1]^T
__device__ __align__(16) float g_B2[64 * 48];              // fp32 cols [W2_0 | W2_1 | R2]

// ---------------- mma helpers ----------------
__device__ __forceinline__ unsigned f2tf(float f) {
    unsigned r; asm("cvt.rna.tf32.f32 %0, %1;" : "=r"(r) : "f"(f)); return r;
}
__device__ __forceinline__ void mma_tf32(float* d, const unsigned* a, const unsigned* b) {
    asm volatile("mma.sync.aligned.m16n8k8.row.col.f32.tf32.tf32.f32 "
        "{%0,%1,%2,%3}, {%4,%5,%6,%7}, {%8,%9}, {%0,%1,%2,%3};"
        : "+f"(d[0]), "+f"(d[1]), "+f"(d[2]), "+f"(d[3])
        : "r"(a[0]), "r"(a[1]), "r"(a[2]), "r"(a[3]), "r"(b[0]), "r"(b[1]));
}
__device__ __forceinline__ void mma_bf16(float* d, const unsigned* a, const unsigned* b) {
    asm volatile("mma.sync.aligned.m16n8k16.row.col.f32.bf16.bf16.f32 "
        "{%0,%1,%2,%3}, {%4,%5,%6,%7}, {%8,%9}, {%0,%1,%2,%3};"
        : "+f"(d[0]), "+f"(d[1]), "+f"(d[2]), "+f"(d[3])
        : "r"(a[0]), "r"(a[1]), "r"(a[2]), "r"(a[3]), "r"(b[0]), "r"(b[1]));
}

// ---------------- PDL launch helper ----------------
template <typename... P, typename... A>
static inline void launch_pdl(dim3 g, dim3 b, cudaStream_t st, void (*k)(P...), A... args) {
    cudaLaunchConfig_t cfg = {};
    cfg.gridDim = g; cfg.blockDim = b; cfg.dynamicSmemBytes = 0; cfg.stream = st;
    cudaLaunchAttribute at[1];
    at[0].id = cudaLaunchAttributeProgrammaticStreamSerialization;
    at[0].val.programmaticStreamSerializationAllowed = 1;
    cfg.attrs = at; cfg.numAttrs = 1;
    cudaLaunchKernelEx(&cfg, k, static_cast<P>(args)...);
}

// ---------------- init: concatenate weights (main stream) ----------------
__global__ void k_initW(const float* __restrict__ W1, const float* __restrict__ R1,
                        const float* __restrict__ Wa, const float* __restrict__ Ra,
                        const float* __restrict__ Wb, const float* __restrict__ Rb,
                        const float* __restrict__ W2, const float* __restrict__ R2) {
    PDL_TRIGGER();
    int i = blockIdx.x * 256 + threadIdx.x;
    if (i < 256 * 192) {   // B1[k][n] fp32
        int k = i / 192, n = i % 192;
        float v;
        if (n < 64)       v = W1[k * 64 + n];
        else if (n < 128) v = W1[256 * 64 + k * 64 + (n - 64)];
        else              v = R1[k * 64 + (n - 128)];
        g_B1[i] = v;
    }
    if (i < 64 * 192) {    // Bh1t/Bh2t[n][k] bf16
        int n = i / 192, k = i % 192;
        float va, vb;
        if (k < 64)       { va = Ra[k * 64 + n];                   vb = Rb[k * 64 + n]; }
        else if (k < 128) { va = Wa[(k - 64) * 64 + n];            vb = Wb[(k - 64) * 64 + n]; }
        else              { va = Wa[64 * 64 + (k - 128) * 64 + n]; vb = Wb[64 * 64 + (k - 128) * 64 + n]; }
        g_Bh1t[i] = __float2bfloat16(va);
        g_Bh2t[i] = __float2bfloat16(vb);
    }
    if (i < 64 * 48) {     // B2[k][n] fp32
        int k = i / 48, n = i % 48;
        float v;
        if (n < 16)      v = W2[k * 16 + n];
        else if (n < 32) v = W2[64 * 16 + k * 16 + (n - 16)];
        else             v = R2[k * 16 + (n - 32)];
        g_B2[i] = v;
    }
}

// ---------------- CSR build (side stream, PDL chained) ----------------
__global__ void k_count(const int* __restrict__ dst) {
    PDL_TRIGGER();
    int e = blockIdx.x * blockDim.x + threadIdx.x;
    int d = (e < N_EDGES) ? dst[e] : -1;
    PDL_WAIT();
    if (e < N_EDGES) atomicAdd(&g_cnt[d], 1);
}
__global__ void k_bsum() {
    PDL_TRIGGER();
    __shared__ int ss[256];
    int t = threadIdx.x;
    int idx = blockIdx.x * 256 + t;
    PDL_WAIT();
    ss[t] = (idx < N_NODES) ? g_cnt[idx] : 0;
    __syncthreads();
    for (int off = 128; off > 0; off >>= 1) {
        if (t < off) ss[t] += ss[t + off];
        __syncthreads();
    }
    if (t == 0) g_bsum[blockIdx.x] = ss[0];
}
// bapply: inline exclusive prefix of block sums + block scan + cnt reset
__global__ void k_bapply() {
    PDL_TRIGGER();
    __shared__ int ss[256];
    __shared__ int s_boff;
    int t = threadIdx.x;
    int idx = blockIdx.x * 256 + t;
    PDL_WAIT();
    int pv = (t < (int)blockIdx.x) ? g_bsum[t] : 0;   // blockIdx.x <= 195 < 256
    ss[t] = pv;
    __syncthreads();
    for (int off = 128; off > 0; off >>= 1) {
        if (t < off) ss[t] += ss[t + off];
        __syncthreads();
    }
    if (t == 0) s_boff = ss[0];
    __syncthreads();
    int v = (idx < N_NODES) ? g_cnt[idx] : 0;
    if (idx < N_NODES) g_cnt[idx] = 0;                // reset for next call (zero-init covers call 1)
    ss[t] = v;
    __syncthreads();
    for (int off = 1; off < 256; off <<= 1) {
        int u = (t >= off) ? ss[t - off] : 0;
        __syncthreads();
        ss[t] += u;
        __syncthreads();
    }
    if (idx < N_NODES) {
        int base = s_boff + ss[t] - v;
        g_rowptr[idx] = base;
        g_cursor[idx] = base;
        g_rdeg[idx] = 1.0f / (float)(v > 0 ? v : 1);
        if (idx == N_NODES - 1) g_rowptr[N_NODES] = base + v;
    }
}
__global__ void k_fill(const int* __restrict__ src, const int* __restrict__ dst,
                       const float* __restrict__ ea) {
    PDL_TRIGGER();
    int e = blockIdx.x * blockDim.x + threadIdx.x;
    int s = 0, d = 0; float p = 0.f;
    if (e < N_EDGES) { s = src[e]; d = dst[e]; p = ea[e]; }
    PDL_WAIT();
    if (e < N_EDGES) {
        int pos = atomicAdd(&g_cursor[d], 1);
        g_edge[pos] = make_int2(s, __float_as_int(p));
    }
}

// ---------------- tf32 GEMM (conv1/conv2), EPI: 0=conv1, 3=conv2 ----------------
// Grid: (n_slices, MG) — slices of the SAME row-tile are launch-adjacent so the
// A-tile (x rows) is read once into L2 and hit by the sibling slices.
template <int K, int NTOT, int BN, int EPI>
__global__ void __launch_bounds__(256) k_mm(const float* __restrict__ A,
                                            const float* __restrict__ B,
                                            const float* __restrict__ bias,
                                            __nv_bfloat16* __restrict__ Cb,
                                            float* __restrict__ aux) {
    PDL_TRIGGER();
    __shared__ unsigned As[128][36];
    __shared__ unsigned Bs[32][BN + 8];

    constexpr int BM = 128, BK = 32;
    constexpr int WN = BN / 2, NF = WN / 8;
    const int tid = threadIdx.x;
    const int lane = tid & 31, warp = tid >> 5;
    const int wm = warp & 3, wn = warp >> 2;
    const int mBase = blockIdx.y * BM;
    const int nBase = blockIdx.x * BN;
    const int g = lane >> 2, t = lane & 3;

    float acc[2][NF][4];
#pragma unroll
    for (int mf = 0; mf < 2; ++mf)
#pragma unroll
        for (int nf = 0; nf < NF; ++nf)
#pragma unroll
            for (int q = 0; q < 4; ++q) acc[mf][nf][q] = 0.f;

    const int ar = tid >> 3, ac = (tid & 7) * 4;
    PDL_WAIT();   // conv1: B1 from k_initW; conv2: g_h from last k_hmm

    for (int k0 = 0; k0 < K; k0 += BK) {
#pragma unroll
        for (int p = 0; p < 4; ++p) {
            int row = p * 32 + ar;
            int gm = mBase + row;
            float4 v = make_float4(0.f, 0.f, 0.f, 0.f);
            if (gm < N_NODES) v = *reinterpret_cast<const float4*>(A + (size_t)gm * K + k0 + ac);
            *reinterpret_cast<uint4*>(&As[row][ac]) =
                make_uint4(f2tf(v.x), f2tf(v.y), f2tf(v.z), f2tf(v.w));
        }
        for (int i = tid; i < BK * BN / 4; i += 256) {
            int bk = i / (BN / 4), bc = (i % (BN / 4)) * 4;
            float4 v = *reinterpret_cast<const float4*>(B + (size_t)(k0 + bk) * NTOT + nBase + bc);
            *reinterpret_cast<uint4*>(&Bs[bk][bc]) =
                make_uint4(f2tf(v.x), f2tf(v.y), f2tf(v.z), f2tf(v.w));
        }
        __syncthreads();
#pragma unroll
        for (int kk = 0; kk < BK / 8; ++kk) {
            const int kb = kk * 8;
            unsigned a[2][4];
#pragma unroll
            for (int mf = 0; mf < 2; ++mf) {
                int r = wm * 32 + mf * 16;
                a[mf][0] = As[r + g][kb + t];
                a[mf][1] = As[r + g + 8][kb + t];
                a[mf][2] = As[r + g][kb + t + 4];
                a[mf][3] = As[r + g + 8][kb + t + 4];
            }
#pragma unroll
            for (int nf = 0; nf < NF; ++nf) {
                int n = wn * WN + nf * 8;
                unsigned b[2] = { Bs[kb + t][n + g], Bs[kb + t + 4][n + g] };
                mma_tf32(acc[0][nf], a[0], b);
                mma_tf32(acc[1][nf], a[1], b);
            }
        }
        __syncthreads();
    }

    const int by = blockIdx.x;   // slice index
    auto emit = [&](int row, int col, float a0, float a1) {
        if (row >= N_NODES) return;
        if (EPI == 0) {
            int c = col - (by << 6);
            if (by < 2) {
                Cb[(size_t)row * 128 + 2 * c + by]       = __float2bfloat16(a0);
                Cb[(size_t)row * 128 + 2 * (c + 1) + by] = __float2bfloat16(a1);
            } else {
                *reinterpret_cast<float2*>(aux + (size_t)row * 64 + c) =
                    make_float2(a0 + bias[c], a1 + bias[c + 1]);
            }
        } else {  // EPI == 3 (conv2)
            if (col < 32) {
                int sec = col >> 4, c = col & 15;
                Cb[(size_t)row * 32 + 2 * c + sec]       = __float2bfloat16(a0);
                Cb[(size_t)row * 32 + 2 * (c + 1) + sec] = __float2bfloat16(a1);
            } else {
                *reinterpret_cast<float2*>(aux + (size_t)row * 16 + (col - 32)) =
                    make_float2(a0 + bias[col - 32], a1 + bias[col - 31]);
            }
        }
    };

#pragma unroll
    for (int mf = 0; mf < 2; ++mf)
#pragma unroll
        for (int nf = 0; nf < NF; ++nf) {
            int row = mBase + wm * 32 + mf * 16 + g;
            int col = nBase + wn * WN + nf * 8 + 2 * t;
            emit(row, col, acc[mf][nf][0], acc[mf][nf][1]);
            emit(row + 8, col, acc[mf][nf][2], acc[mf][nf][3]);
        }
}

// ---------------- hidden pre-aggregation: warp/node, packed-edge bf16 gather x8 ----------------
// trigger AFTER wait — dependents (k_hmm) may then read inb pre-wait (transitive completion).
__global__ void __launch_bounds__(256) k_preagg(const __nv_bfloat16* __restrict__ inb) {
    PDL_WAIT();
    PDL_TRIGGER();
    int w = (blockIdx.x * 256 + threadIdx.x) >> 5;
    int lane = threadIdx.x & 31;
    if (w >= N_NODES) return;
    int i = g_rowptr[w], end = g_rowptr[w + 1];
    float rd = g_rdeg[w];
    float sa0 = 0.f, sa1 = 0.f, sp0 = 0.f, sp1 = 0.f;
    for (; i + 7 < end; i += 8) {
        int2 ei[8]; float2 xi[8];
#pragma unroll
        for (int q = 0; q < 8; ++q) ei[q] = g_edge[i + q];
#pragma unroll
        for (int q = 0; q < 8; ++q)
            xi[q] = __bfloat1622float2(*reinterpret_cast<const __nv_bfloat162*>(inb + (size_t)ei[q].x * 64 + 2 * lane));
#pragma unroll
        for (int q = 0; q < 8; ++q) {
            float p = __int_as_float(ei[q].y);
            sa0 += xi[q].x;
            sa1 += xi[q].y;
            sp0 = fmaf(p, xi[q].x, sp0);
            sp1 = fmaf(p, xi[q].y, sp1);
        }
    }
    for (; i < end; ++i) {
        int2 e = g_edge[i];
        float p = __int_as_float(e.y);
        float2 xv = __bfloat1622float2(*reinterpret_cast<const __nv_bfloat162*>(inb + (size_t)e.x * 64 + 2 * lane));
        sa0 += xv.x; sa1 += xv.y;
        sp0 = fmaf(p, xv.x, sp0);
        sp1 = fmaf(p, xv.y, sp1);
    }
    __nv_bfloat16* yr = g_Ypreb + (size_t)w * 128;
    *reinterpret_cast<__nv_bfloat162*>(yr + 2 * lane) =
        __float22bfloat162_rn(make_float2((sa0 - sp0) * rd, (sa1 - sp1) * rd));
    *reinterpret_cast<__nv_bfloat162*>(yr + 64 + 2 * lane) =
        __float22bfloat162_rn(make_float2(sp0 * rd, sp1 * rd));
}

// ---------------- hidden GEMM (bf16 mma): A=[inb | Ypreb], Bt n-major bf16, K=192 ----------------
// chunk0 (inb) pipelined pre-wait; Ypreb chunks post-wait.
// EPI: 1 = write midb (bf16), 2 = RK stage epilogue
template <int EPI>
__global__ void __launch_bounds__(256) k_hmm(const __nv_bfloat16* __restrict__ inb,
                                             const __nv_bfloat16* __restrict__ Bt,
                                             const float* __restrict__ bias,
                                             __nv_bfloat16* __restrict__ outb,
                                             int estage, float curMul) {
    PDL_TRIGGER();
    __shared__ __nv_bfloat16 Asm[128][72];
    __shared__ __nv_bfloat16 Bsm[64][200];

    const int tid = threadIdx.x;
    const int lane = tid & 31, warp = tid >> 5;
    const int wm = warp & 3, wn = warp >> 2;
    const int mBase = blockIdx.x * 128;
    const int g = lane >> 2, t = lane & 3;

    for (int i = tid; i < 64 * 192 / 8; i += 256) {
        int n = i / 24, c8 = (i % 24) * 8;
        *reinterpret_cast<uint4*>(&Bsm[n][c8]) = *reinterpret_cast<const uint4*>(Bt + n * 192 + c8);
    }

    float acc[2][4][4];
#pragma unroll
    for (int mf = 0; mf < 2; ++mf)
#pragma unroll
        for (int nf = 0; nf < 4; ++nf)
#pragma unroll
            for (int q = 0; q < 4; ++q) acc[mf][nf][q] = 0.f;

    auto load_A = [&](const __nv_bfloat16* srcbase, size_t rowStride, int off) {
#pragma unroll
        for (int i2 = 0; i2 < 4; ++i2) {
            int i = i2 * 256 + tid;
            int row = i >> 3, c8 = (i & 7) * 8;
            int gm = mBase + row;
            uint4 v = make_uint4(0, 0, 0, 0);
            if (gm < N_NODES)
                v = *reinterpret_cast<const uint4*>(srcbase + (size_t)gm * rowStride + off + c8);
            *reinterpret_cast<uint4*>(&Asm[row][c8]) = v;
        }
    };
    auto mma_chunk = [&](int chunk) {
#pragma unroll
        for (int kk = 0; kk < 4; ++kk) {
            const int kb = kk * 16;
            unsigned a[2][4];
#pragma unroll
            for (int mf = 0; mf < 2; ++mf) {
                int r = wm * 32 + mf * 16;
                a[mf][0] = *reinterpret_cast<const unsigned*>(&Asm[r + g][kb + 2 * t]);
                a[mf][1] = *reinterpret_cast<const unsigned*>(&Asm[r + g + 8][kb + 2 * t]);
                a[mf][2] = *reinterpret_cast<const unsigned*>(&Asm[r + g][kb + 2 * t + 8]);
                a[mf][3] = *reinterpret_cast<const unsigned*>(&Asm[r + g + 8][kb + 2 * t + 8]);
            }
#pragma unroll
            for (int nf = 0; nf < 4; ++nf) {
                int n = wn * 32 + nf * 8;
                unsigned b[2] = {
                    *reinterpret_cast<const unsigned*>(&Bsm[n + g][chunk * 64 + kb + 2 * t]),
                    *reinterpret_cast<const unsigned*>(&Bsm[n + g][chunk * 64 + kb + 2 * t + 8])
                };
                mma_bf16(acc[0][nf], a[0], b);
                mma_bf16(acc[1][nf], a[1], b);
            }
        }
    };

    // chunk 0: inb (R-part) — PRE-WAIT
    load_A(inb, 64, 0);
    __syncthreads();
    mma_chunk(0);
    __syncthreads();

    PDL_WAIT();   // Ypreb from the immediately preceding k_preagg

#pragma unroll
    for (int chunk = 1; chunk < 3; ++chunk) {
        load_A(g_Ypreb, 128, (chunk - 1) * 64);
        __syncthreads();
        mma_chunk(chunk);
        __syncthreads();
    }

    auto emit = [&](int row, int col, float a0, float a1) {
        if (row >= N_NODES) return;
        float2 kv = make_float2(a0 + bias[col], a1 + bias[col + 1]);
        size_t idx = (size_t)row * 64 + col;
        if (EPI == 1) {
            *reinterpret_cast<__nv_bfloat162*>(outb + idx) = __float22bfloat162_rn(kv);
        } else {
            float2 h2 = *reinterpret_cast<const float2*>(g_h + idx);
            if (estage == 4) {
                float2 a2 = *reinterpret_cast<const float2*>(g_acc + idx);
                *reinterpret_cast<float2*>(g_h + idx) =
                    make_float2(h2.x + 0.5f * (a2.x + kv.x), h2.y + 0.5f * (a2.y + kv.y));
            } else {
                float2 a2;
                if (estage == 1) a2 = kv;
                else {
                    a2 = *reinterpret_cast<const float2*>(g_acc + idx);
                    a2.x = fmaf(2.f, kv.x, a2.x); a2.y = fmaf(2.f, kv.y, a2.y);
                }
                *reinterpret_cast<float2*>(g_acc + idx) = a2;
                float2 c2 = make_float2(fmaf(curMul, kv.x, h2.x), fmaf(curMul, kv.y, h2.y));
                *reinterpret_cast<__nv_bfloat162*>(outb + idx) = __float22bfloat162_rn(c2);
            }
        }
    };

#pragma unroll
    for (int mf = 0; mf < 2; ++mf)
#pragma unroll
        for (int nf = 0; nf < 4; ++nf) {
            int row = mBase + wm * 32 + mf * 16 + g;
            int col = wn * 32 + nf * 8 + 2 * t;
            emit(row, col, acc[mf][nf][0], acc[mf][nf][1]);
            emit(row + 8, col, acc[mf][nf][2], acc[mf][nf][3]);
        }
}

// ---------------- conv1 aggregation: warp/node, packed-edge bf16 gather x8, tanh ----------------
__global__ void __launch_bounds__(256) k_agg1() {
    PDL_TRIGGER();
    int w = (blockIdx.x * 256 + threadIdx.x) >> 5;
    int lane = threadIdx.x & 31;
    if (w >= N_NODES) { PDL_WAIT(); return; }
    int i = g_rowptr[w], end = g_rowptr[w + 1];
    float rd = g_rdeg[w];
    PDL_WAIT();   // g_c1 / g_xr1 from conv1 GEMM
    float a0 = 0.f, a1 = 0.f;
    for (; i + 7 < end; i += 8) {
        int2 ei[8]; uint2 ui[8];
#pragma unroll
        for (int q = 0; q < 8; ++q) ei[q] = g_edge[i + q];
#pragma unroll
        for (int q = 0; q < 8; ++q)
            ui[q] = *reinterpret_cast<const uint2*>(g_c1 + (size_t)ei[q].x * 128 + 4 * lane);
#pragma unroll
        for (int q = 0; q < 8; ++q) {
            float p = __int_as_float(ei[q].y);
            float2 v0 = __bfloat1622float2(*reinterpret_cast<__nv_bfloat162*>(&ui[q].x));
            float2 v1 = __bfloat1622float2(*reinterpret_cast<__nv_bfloat162*>(&ui[q].y));
            a0 += fmaf(p, v0.y - v0.x, v0.x);
            a1 += fmaf(p, v1.y - v1.x, v1.x);
        }
    }
    for (; i < end; ++i) {
        int2 e = g_edge[i];
        float p = __int_as_float(e.y);
        uint2 u = *reinterpret_cast<const uint2*>(g_c1 + (size_t)e.x * 128 + 4 * lane);
        float2 v0 = __bfloat1622float2(*reinterpret_cast<__nv_bfloat162*>(&u.x));
        float2 v1 = __bfloat1622float2(*reinterpret_cast<__nv_bfloat162*>(&u.y));
        a0 += fmaf(p, v0.y - v0.x, v0.x);
        a1 += fmaf(p, v1.y - v1.x, v1.x);
    }
    float2 xr = *reinterpret_cast<const float2*>(g_xr1 + (size_t)w * 64 + 2 * lane);
    float2 hv = make_float2(tanhf(fmaf(a0, rd, xr.x)), tanhf(fmaf(a1, rd, xr.y)));
    *reinterpret_cast<float2*>(g_h + (size_t)w * 64 + 2 * lane) = hv;
    *reinterpret_cast<__nv_bfloat162*>(g_hb + (size_t)w * 64 + 2 * lane) = __float22bfloat162_rn(hv);
}

// ---------------- conv2 aggregation + log_softmax (half-warp/node) ----------------
__global__ void __launch_bounds__(256) k_agg2_lsm(float* __restrict__ out) {
    PDL_TRIGGER();
    int hw = (blockIdx.x * 256 + threadIdx.x) >> 4;
    int c = threadIdx.x & 15;
    if (hw >= N_NODES) { PDL_WAIT(); return; }
    int i = g_rowptr[hw], end = g_rowptr[hw + 1];
    float rd = g_rdeg[hw];
    PDL_WAIT();   // g_c2 / g_xr2 from conv2 GEMM
    float acc = 0.f;
    for (; i + 1 < end; i += 2) {
        int2 eA = g_edge[i], eB = g_edge[i + 1];
        float pA = __int_as_float(eA.y), pB = __int_as_float(eB.y);
        float2 vA = __bfloat1622float2(*reinterpret_cast<const __nv_bfloat162*>(g_c2 + (size_t)eA.x * 32 + 2 * c));
        float2 vB = __bfloat1622float2(*reinterpret_cast<const __nv_bfloat162*>(g_c2 + (size_t)eB.x * 32 + 2 * c));
        acc += fmaf(pA, vA.y - vA.x, vA.x) + fmaf(pB, vB.y - vB.x, vB.x);
    }
    if (i < end) {
        int2 e = g_edge[i];
        float p = __int_as_float(e.y);
        float2 v = __bfloat1622float2(*reinterpret_cast<const __nv_bfloat162*>(g_c2 + (size_t)e.x * 32 + 2 * c));
        acc += fmaf(p, v.y - v.x, v.x);
    }
    float v = tanhf(fmaf(acc, rd, g_xr2[(size_t)hw * 16 + c]));
    float m = v;
    for (int o = 8; o > 0; o >>= 1) m = fmaxf(m, __shfl_xor_sync(0xffffffffu, m, o, 16));
    float e = expf(v - m);
    float s = e;
    for (int o = 8; o > 0; o >>= 1) s += __shfl_xor_sync(0xffffffffu, s, o, 16);
    out[(size_t)hw * 16 + c] = v - m - logf(s);
}

// ---------------- launch ----------------
extern "C" void kernel_launch(void* const* d_in, const int* in_sizes, int n_in,
                              void* d_out, int out_size) {
    const float* x  = (const float*)d_in[0];
    const float* ea = (const float*)d_in[1];
    const int*   src = (const int*)d_in[2];
    const int*   dst = (const int*)d_in[3];
    const float* W1 = (const float*)d_in[4];
    const float* R1 = (const float*)d_in[5];
    const float* b1 = (const float*)d_in[6];
    const float* Wa = (const float*)d_in[7];
    const float* Ra = (const float*)d_in[8];
    const float* ba = (const float*)d_in[9];
    const float* Wb = (const float*)d_in[10];
    const float* Rb = (const float*)d_in[11];
    const float* bb = (const float*)d_in[12];
    const float* W2 = (const float*)d_in[13];
    const float* R2 = (const float*)d_in[14];
    const float* b2 = (const float*)d_in[15];
    float* out = (float*)d_out;

    float *h, *B1, *B2, *xr1, *xr2;
    __nv_bfloat16 *hb, *midb, *curb, *c1, *c2, *Bh1t, *Bh2t;
    cudaGetSymbolAddress((void**)&h, g_h);
    cudaGetSymbolAddress((void**)&hb, g_hb);
    cudaGetSymbolAddress((void**)&midb, g_midb);
    cudaGetSymbolAddress((void**)&curb, g_curb);
    cudaGetSymbolAddress((void**)&B1, g_B1);
    cudaGetSymbolAddress((void**)&Bh1t, g_Bh1t);
    cudaGetSymbolAddress((void**)&Bh2t, g_Bh2t);
    cudaGetSymbolAddress((void**)&B2, g_B2);
    cudaGetSymbolAddress((void**)&c1, g_c1);
    cudaGetSymbolAddress((void**)&c2, g_c2);
    cudaGetSymbolAddress((void**)&xr1, g_xr1);
    cudaGetSymbolAddress((void**)&xr2, g_xr2);

    static cudaStream_t s2 = nullptr;
    static cudaEvent_t e1 = nullptr, e2 = nullptr;
    if (s2 == nullptr) {
        cudaStreamCreateWithFlags(&s2, cudaStreamNonBlocking);
        cudaEventCreateWithFlags(&e1, cudaEventDisableTiming);
        cudaEventCreateWithFlags(&e2, cudaEventDisableTiming);
    }

    cudaStream_t m = 0;

    // fork: CSR chain on side stream (count -> bsum -> bapply[+scan+reset] -> fill)
    cudaEventRecord(e1, m);
    cudaStreamWaitEvent(s2, e1, 0);
    launch_pdl(N_EDGES / 256, 256, s2, k_count, dst);
    launch_pdl(NB_SCAN, 256, s2, k_bsum);
    launch_pdl(NB_SCAN, 256, s2, k_bapply);
    launch_pdl(N_EDGES / 256, 256, s2, k_fill, src, dst, ea);
    cudaEventRecord(e2, s2);

    // main: weight concat -> conv1 tf32 GEMM (overlaps CSR chain)
    launch_pdl(192, 256, m, k_initW, W1, R1, Wa, Ra, Wb, Rb, W2, R2);
    launch_pdl(dim3(3, MG), 256, m, k_mm<256, 192, 64, 0>, x, (const float*)B1, b1, c1, xr1);

    // join
    cudaStreamWaitEvent(m, e2, 0);

    const int WG = (N_NODES * 32 + 255) / 256;
    const int HG = (N_NODES * 16 + 255) / 256;

    launch_pdl(WG, 256, m, k_agg1);

    // RK4 stages (PDL-chained)
    auto fstep = [&](const __nv_bfloat16* inb, int stage, float curMul) {
        launch_pdl(WG, 256, m, k_preagg, inb);
        launch_pdl(MG, 256, m, k_hmm<1>, inb, Bh1t, ba, midb, 0, 0.f);
        launch_pdl(WG, 256, m, k_preagg, (const __nv_bfloat16*)midb);
        launch_pdl(MG, 256, m, k_hmm<2>, (const __nv_bfloat16*)midb, Bh2t, bb, curb, stage, curMul);
    };
    fstep(hb, 1, 1.5f);
    fstep(curb, 2, 1.5f);
    fstep(curb, 3, 3.0f);
    fstep(curb, 4, 0.f);

    // conv2 + log_softmax
    launch_pdl(dim3(1, MG), 256, m, k_mm<64, 48, 48, 3>, (const float*)h, (const float*)B2, b2, c2, xr2);
    launch_pdl(HG, 256, m, k_agg2_lsm, out);
}